// round 13
// baseline (speedup 1.0000x reference)
#include <cuda_runtime.h>
#include <cuda_fp16.h>
#include <math.h>
#include <stdint.h>

// ---------------------------------------------------------------------------
// Problem constants
//  B=32, S=512, F_IN=64, D=512, DFF=2048, MEM=1024, L=3, H=8, dh=64
//  rows = B*S = 16384
// ---------------------------------------------------------------------------

// ------------------------- static scratch buffers --------------------------
__device__ float  g_pe[512 * 512];             // 1 MB
__device__ float  g_h[16384 * 512];            // 32 MB (fp32 residual stream)
__device__ __half g_h16[16384 * 512];          // 16 MB (fp16 mirror of h)
__device__ __half g_h16lo[16384 * 512];        // 16 MB (fp16 low part of h)
__device__ float  g_tmp[16384 * 512];          // 32 MB
__device__ __half g_qkv[16384 * 1536];         // 48 MB (reused as fc1 out)
__device__ __half g_o[16384 * 512];            // 16 MB (reused as upd16)
__device__ __half g_ff[16384 * 2048];          // 64 MB
__device__ __half g_mlo[1024 * 512];           // 1 MB (fp16 low part of memory)
__device__ float  g_fn[32 * 64];
__device__ float  g_An[32 * 64 * 64];
__device__ float  g_gt1[32 * 64 * 512];        // 4 MB
__device__ float  g_gh1[32 * 64 * 512];        // 4 MB
__device__ __half g_wh[10551296];              // 21 MB fp16 weights

// fp16 weight buffer offsets
#define WH_QKV   0                               // 3*1536*512 = 2359296
#define WH_OUT   2359296                         // 3*512*512  = 786432
#define WH_FF1   3145728                         // 3*2048*512 = 3145728
#define WH_FF2   6291456                         // 3*512*2048 = 3145728
#define WH_MEM   9437184                         // 1024*512   = 524288
#define WH_FC1   9961472                         // 512*1024   = 524288
#define WH_FC2   10485760                        // 64*512     = 32768
#define WH_WIN   10518528                        // 512*64     = 32768

// ---------------------------------------------------------------------------
// fp16 / async helpers
// ---------------------------------------------------------------------------
__device__ __forceinline__ uint32_t pack_half2(float a, float b) {
    __half2 h = __floats2half2_rn(a, b);
    return *reinterpret_cast<uint32_t*>(&h);
}

__device__ __forceinline__ void mma_f16(float c[4],
    uint32_t a0, uint32_t a1, uint32_t a2, uint32_t a3,
    uint32_t b0, uint32_t b1)
{
    asm volatile(
        "mma.sync.aligned.m16n8k16.row.col.f32.f16.f16.f32 "
        "{%0,%1,%2,%3}, {%4,%5,%6,%7}, {%8,%9}, {%0,%1,%2,%3};"
        : "+f"(c[0]), "+f"(c[1]), "+f"(c[2]), "+f"(c[3])
        : "r"(a0), "r"(a1), "r"(a2), "r"(a3), "r"(b0), "r"(b1));
}

__device__ __forceinline__ void cp_async16(void* smem_ptr, const void* gptr) {
    uint32_t a = (uint32_t)__cvta_generic_to_shared(smem_ptr);
    asm volatile("cp.async.cg.shared.global [%0], [%1], 16;" :: "r"(a), "l"(gptr));
}
#define CP_COMMIT() asm volatile("cp.async.commit_group;")
#define CP_WAIT0()  asm volatile("cp.async.wait_group 0;")

// ---------------------------------------------------------------------------
// Weight pre-conversion: fp32 -> fp16 (rn)
// ---------------------------------------------------------------------------
__global__ void convert_w_kernel(const float* __restrict__ src,
                                 __half* __restrict__ dst, int n4)
{
    int i = blockIdx.x * 256 + threadIdx.x;
    if (i >= n4) return;
    float4 v = *reinterpret_cast<const float4*>(src + i * 4);
    uint2 u;
    u.x = pack_half2(v.x, v.y);
    u.y = pack_half2(v.z, v.w);
    *reinterpret_cast<uint2*>(dst + i * 4) = u;
}

// lo = fp16(src - fp32(hi))  (hi already = fp16_rn(src))
__global__ void make_lo_kernel(const float* __restrict__ src,
                               const __half* __restrict__ hi,
                               __half* __restrict__ lo, int n4)
{
    int i = blockIdx.x * 256 + threadIdx.x;
    if (i >= n4) return;
    float4 v = *reinterpret_cast<const float4*>(src + i * 4);
    uint2 hu = *reinterpret_cast<const uint2*>(hi + i * 4);
    __half2 h0 = *reinterpret_cast<__half2*>(&hu.x);
    __half2 h1 = *reinterpret_cast<__half2*>(&hu.y);
    uint2 lu;
    lu.x = pack_half2(v.x - __low2float(h0), v.y - __high2float(h0));
    lu.y = pack_half2(v.z - __low2float(h1), v.w - __high2float(h1));
    *reinterpret_cast<uint2*>(lo + i * 4) = lu;
}

// ---------------------------------------------------------------------------
// Positional encoding (match numpy float64 -> float32)
// ---------------------------------------------------------------------------
__global__ void pe_kernel(float* __restrict__ pe) {
    int i = blockIdx.x * 256 + threadIdx.x;
    if (i >= 512 * 512) return;
    int s = i >> 9, d = i & 511;
    int t2 = d & ~1;
    double div = exp((double)t2 * (-9.210340371976184 / 512.0)); // ln(10000)
    double a = (double)s * div;
    pe[i] = (float)((d & 1) ? cos(a) : sin(a));
}

// ---------------------------------------------------------------------------
// Tensor-core GEMM (fp16 mma, fp32 accumulate).
//  C[M,N] = A[M,K] * op(B) + bias (+epilogue)
//   TRANSB : B is (N,K) row-major -> C = A @ B^T ; false: B (K,N)
//   CATAB  : A logical [M,1024] = concat(A[:,:512], A2[:,:512]) (fp16 srcs)
//   AHALF  : A is __half          OHALF : C written as __half
//   BHALF  : B is __half          CPA   : cp.async double-buffered mainloop
//   ODUAL  : write C fp32 AND C2 fp16
// Block tile 128x128, 256 threads (8 warps = 2m x 4n of 64x32 warp tiles).
// EPI: 0 bias, 1 bias+relu, 2 bias+pos-encoding, 3 bias+residual
// ---------------------------------------------------------------------------
template <bool TRANSB, int EPI, bool CATAB, bool AHALF, bool OHALF,
          bool BHALF, bool CPA, bool ODUAL>
__global__ void __launch_bounds__(256) gemm_tc(
    const void* __restrict__ Avoid, const void* __restrict__ A2void,
    const void* __restrict__ Bvoid,
    const float* __restrict__ bias, const float* __restrict__ pe,
    const float* __restrict__ resid,
    void* __restrict__ Cvoid, void* __restrict__ C2void,
    int M, int N, int K)
{
    constexpr int KT    = 32;              // fp16 elems per K-tile
    constexpr int STR2  = 20;              // half2 (uint) stride: 16 + 4
    constexpr int TILE2 = 128 * STR2;
    constexpr int NSEG  = CPA ? 2 : 1;

    __shared__ uint32_t As[NSEG * TILE2];
    __shared__ uint32_t Bs[NSEG * TILE2];

    const float*  Af  = (const float*)Avoid;
    const __half* Ah  = (const __half*)Avoid;
    const __half* A2h = (const __half*)A2void;
    const float*  Bf  = (const float*)Bvoid;
    const __half* Bh  = (const __half*)Bvoid;
    float*  Cf  = (float*)Cvoid;
    __half* Ch  = (__half*)Cvoid;
    __half* Ch2 = (__half*)C2void;

    const int tid  = threadIdx.x;
    const int lane = tid & 31, wid = tid >> 5;
    const int wm = (wid >> 2) * 64, wn = (wid & 3) * 32;
    const int g = lane >> 2, c = lane & 3;
    const int m0 = blockIdx.y * 128, n0 = blockIdx.x * 128;

    float acc[4][4][4];
#pragma unroll
    for (int i = 0; i < 4; i++)
#pragma unroll
        for (int j = 0; j < 4; j++)
#pragma unroll
            for (int t = 0; t < 4; t++) acc[i][j][t] = 0.f;

    // ---- MMA on one buffer ----
    auto mma_tile = [&](int buf) {
        const uint32_t* Asb = As + (CPA ? buf * TILE2 : 0);
        const uint32_t* Bsb = Bs + (CPA ? buf * TILE2 : 0);
#pragma unroll
        for (int ks = 0; ks < 2; ks++) {
            const int kb = ks * 8 + c;
            uint32_t af[4][4], bf[4][2];
#pragma unroll
            for (int mi = 0; mi < 4; mi++) {
                const int mr = wm + mi * 16 + g;
                af[mi][0] = Asb[mr * STR2 + kb];
                af[mi][1] = Asb[(mr + 8) * STR2 + kb];
                af[mi][2] = Asb[mr * STR2 + kb + 4];
                af[mi][3] = Asb[(mr + 8) * STR2 + kb + 4];
            }
#pragma unroll
            for (int ni = 0; ni < 4; ni++) {
                const int nr = wn + ni * 8 + g;
                bf[ni][0] = Bsb[nr * STR2 + kb];
                bf[ni][1] = Bsb[nr * STR2 + kb + 4];
            }
#pragma unroll
            for (int mi = 0; mi < 4; mi++)
#pragma unroll
                for (int ni = 0; ni < 4; ni++)
                    mma_f16(acc[mi][ni], af[mi][0], af[mi][1], af[mi][2], af[mi][3],
                            bf[ni][0], bf[ni][1]);
        }
    };

    if (CPA) {
        // ================= cp.async double-buffered mainloop =================
        auto issue_cp = [&](int k0, int buf) {
            uint32_t* Asb = As + buf * TILE2;
            uint32_t* Bsb = Bs + buf * TILE2;
#pragma unroll
            for (int i = 0; i < 2; i++) {
                int idx = tid + i * 256;
                int u4 = idx & 3, m = idx >> 2;
                const __half* Ap = Ah;
                int lda = K, kcol = k0 + u4 * 8;
                if (CATAB) {
                    lda = 512;
                    if (k0 >= 512) { Ap = A2h; kcol -= 512; }
                }
                cp_async16(&Asb[m * STR2 + u4 * 4],
                           Ap + (size_t)(m0 + m) * lda + kcol);
            }
#pragma unroll
            for (int i = 0; i < 2; i++) {
                int idx = tid + i * 256;
                int u4 = idx & 3, n = idx >> 2;
                if (n0 + n < N)
                    cp_async16(&Bsb[n * STR2 + u4 * 4],
                               Bh + (size_t)(n0 + n) * K + k0 + u4 * 8);
            }
        };

        issue_cp(0, 0);
        CP_COMMIT();
        int pb = 0;
        for (int k0 = 0; k0 < K; k0 += KT) {
            CP_WAIT0();
            __syncthreads();
            if (k0 + KT < K) {
                issue_cp(k0 + KT, pb ^ 1);
                CP_COMMIT();
            }
            mma_tile(pb);
            pb ^= 1;
        }
        __syncthreads();
    } else {
        // ============== register-staged single-buffer mainloop ==============
        float4 rA[4], rB[4];
        uint4  rAh[2], rBh[2];

        auto load_regs = [&](int k0) {
            if (AHALF) {
#pragma unroll
                for (int i = 0; i < 2; i++) {
                    int idx = tid + i * 256;
                    int u4 = idx & 3, m = idx >> 2;
                    rAh[i] = *reinterpret_cast<const uint4*>(
                        Ah + (size_t)(m0 + m) * K + k0 + u4 * 8);
                }
            } else {
#pragma unroll
                for (int i = 0; i < 4; i++) {
                    int idx = tid + i * 256;
                    int kg = idx & 7, m = idx >> 3;
                    rA[i] = *reinterpret_cast<const float4*>(
                        Af + (size_t)(m0 + m) * K + k0 + kg * 4);
                }
            }
            if (BHALF) {
                if (TRANSB) {
#pragma unroll
                    for (int i = 0; i < 2; i++) {
                        int idx = tid + i * 256;
                        int u4 = idx & 3, n = idx >> 2;
                        rBh[i] = make_uint4(0, 0, 0, 0);
                        if (n0 + n < N)
                            rBh[i] = *reinterpret_cast<const uint4*>(
                                Bh + (size_t)(n0 + n) * K + k0 + u4 * 8);
                    }
                } else {
#pragma unroll
                    for (int i = 0; i < 2; i++) {
                        int idx = tid + i * 256;
                        int ng = idx & 15, kk = idx >> 4;
                        rBh[i] = make_uint4(0, 0, 0, 0);
                        if (n0 + ng * 8 < N)
                            rBh[i] = *reinterpret_cast<const uint4*>(
                                Bh + (size_t)(k0 + kk) * N + n0 + ng * 8);
                    }
                }
            } else if (TRANSB) {
#pragma unroll
                for (int i = 0; i < 4; i++) {
                    int idx = tid + i * 256;
                    int kg = idx & 7, n = idx >> 3;
                    rB[i] = make_float4(0.f, 0.f, 0.f, 0.f);
                    if (n0 + n < N)
                        rB[i] = *reinterpret_cast<const float4*>(
                            Bf + (size_t)(n0 + n) * K + k0 + kg * 4);
                }
            } else {
#pragma unroll
                for (int i = 0; i < 4; i++) {
                    int idx = tid + i * 256;
                    int ng = idx & 31, kk = idx >> 5;
                    int n = ng * 4;
                    rB[i] = make_float4(0.f, 0.f, 0.f, 0.f);
                    if (n0 + n < N)
                        rB[i] = *reinterpret_cast<const float4*>(
                            Bf + (size_t)(k0 + kk) * N + n0 + n);
                }
            }
        };

        auto store_smem = [&]() {
            if (AHALF) {
#pragma unroll
                for (int i = 0; i < 2; i++) {
                    int idx = tid + i * 256;
                    int u4 = idx & 3, m = idx >> 2;
                    *reinterpret_cast<uint4*>(&As[m * STR2 + u4 * 4]) = rAh[i];
                }
            } else {
#pragma unroll
                for (int i = 0; i < 4; i++) {
                    int idx = tid + i * 256;
                    int kg = idx & 7, m = idx >> 3;
                    float4 v = rA[i];
                    uint2 hu;
                    hu.x = pack_half2(v.x, v.y);
                    hu.y = pack_half2(v.z, v.w);
                    *reinterpret_cast<uint2*>(&As[m * STR2 + kg * 2]) = hu;
                }
            }
            if (BHALF) {
                if (TRANSB) {
#pragma unroll
                    for (int i = 0; i < 2; i++) {
                        int idx = tid + i * 256;
                        int u4 = idx & 3, n = idx >> 2;
                        *reinterpret_cast<uint4*>(&Bs[n * STR2 + u4 * 4]) = rBh[i];
                    }
                } else {
                    __half* Bsh = reinterpret_cast<__half*>(Bs);
#pragma unroll
                    for (int i = 0; i < 2; i++) {
                        int idx = tid + i * 256;
                        int ng = idx & 15, kk = idx >> 4;
                        const __half* hv = reinterpret_cast<const __half*>(&rBh[i]);
#pragma unroll
                        for (int j = 0; j < 8; j++)
                            Bsh[(ng * 8 + j) * (STR2 * 2) + kk] = hv[j];
                    }
                }
            } else if (TRANSB) {
#pragma unroll
                for (int i = 0; i < 4; i++) {
                    int idx = tid + i * 256;
                    int kg = idx & 7, n = idx >> 3;
                    float4 v = rB[i];
                    uint2 hu;
                    hu.x = pack_half2(v.x, v.y);
                    hu.y = pack_half2(v.z, v.w);
                    *reinterpret_cast<uint2*>(&Bs[n * STR2 + kg * 2]) = hu;
                }
            } else {
                __half* Bsh = reinterpret_cast<__half*>(Bs);
#pragma unroll
                for (int i = 0; i < 4; i++) {
                    int idx = tid + i * 256;
                    int ng = idx & 31, kk = idx >> 5;
                    int n = ng * 4;
                    float4 v = rB[i];
                    float vv[4] = {v.x, v.y, v.z, v.w};
#pragma unroll
                    for (int j = 0; j < 4; j++)
                        Bsh[(n + j) * (STR2 * 2) + kk] = __float2half_rn(vv[j]);
                }
            }
        };

        load_regs(0);
        for (int k0 = 0; k0 < K; k0 += KT) {
            store_smem();
            __syncthreads();
            if (k0 + KT < K) load_regs(k0 + KT);
            mma_tile(0);
            __syncthreads();
        }
    }

    // ---- epilogue ----
#pragma unroll
    for (int mi = 0; mi < 4; mi++) {
#pragma unroll
        for (int ni = 0; ni < 4; ni++) {
            const int row = m0 + wm + mi * 16 + g;
            const int col = n0 + wn + ni * 8 + 2 * c;
#pragma unroll
            for (int hf = 0; hf < 2; hf++) {
                const int rr2 = row + hf * 8;
                if (col < N) {
                    float v0 = acc[mi][ni][hf * 2 + 0];
                    float v1 = acc[mi][ni][hf * 2 + 1];
                    if (bias) { v0 += __ldg(bias + col); v1 += __ldg(bias + col + 1); }
                    if (EPI == 1) { v0 = fmaxf(v0, 0.f); v1 = fmaxf(v1, 0.f); }
                    if (EPI == 2) {
                        v0 += pe[((rr2 & 511) << 9) + col];
                        v1 += pe[((rr2 & 511) << 9) + col + 1];
                    }
                    if (EPI == 3) {
                        v0 += resid[(size_t)rr2 * N + col];
                        v1 += resid[(size_t)rr2 * N + col + 1];
                    }
                    if (OHALF) {
                        *reinterpret_cast<uint32_t*>(Ch + (size_t)rr2 * N + col) =
                            pack_half2(v0, v1);
                    } else {
                        Cf[(size_t)rr2 * N + col]     = v0;
                        Cf[(size_t)rr2 * N + col + 1] = v1;
                        if (ODUAL)
                            *reinterpret_cast<uint32_t*>(Ch2 + (size_t)rr2 * N + col) =
                                pack_half2(v0, v1);
                    }
                }
            }
        }
    }
}

// ---------------------------------------------------------------------------
// Sims split GEMM: C = Ahi@Bhi^T + Ahi@Blo^T + Alo@Bhi^T (fp32 acc).
// All operands pre-split fp16; raw uint4 loads, register-staged single buffer.
// Block tile 128x128, 256 threads. M mult of 128; N mult of 128; K mult of 32.
// ---------------------------------------------------------------------------
__global__ void __launch_bounds__(256) sims_split_tc(
    const __half* __restrict__ Ahi, const __half* __restrict__ Alo,
    const __half* __restrict__ Bhi, const __half* __restrict__ Blo,
    float* __restrict__ C, int M, int N, int K)
{
    constexpr int KT    = 32;
    constexpr int STR2  = 20;
    constexpr int TILE2 = 128 * STR2;

    __shared__ uint32_t As[2 * TILE2];   // [hi | lo]
    __shared__ uint32_t Bs[2 * TILE2];

    const int tid  = threadIdx.x;
    const int lane = tid & 31, wid = tid >> 5;
    const int wm = (wid >> 2) * 64, wn = (wid & 3) * 32;
    const int g = lane >> 2, c = lane & 3;
    const int m0 = blockIdx.y * 128, n0 = blockIdx.x * 128;

    float acc[4][4][4];
#pragma unroll
    for (int i = 0; i < 4; i++)
#pragma unroll
        for (int j = 0; j < 4; j++)
#pragma unroll
            for (int t = 0; t < 4; t++) acc[i][j][t] = 0.f;

    uint4 rAh[2], rAl[2], rBh[2], rBl[2];

    auto load_regs = [&](int k0) {
#pragma unroll
        for (int i = 0; i < 2; i++) {
            int idx = tid + i * 256;
            int u4 = idx & 3, m = idx >> 2;
            size_t aoff = (size_t)(m0 + m) * K + k0 + u4 * 8;
            size_t boff = (size_t)(n0 + m) * K + k0 + u4 * 8;
            rAh[i] = *reinterpret_cast<const uint4*>(Ahi + aoff);
            rAl[i] = *reinterpret_cast<const uint4*>(Alo + aoff);
            rBh[i] = *reinterpret_cast<const uint4*>(Bhi + boff);
            rBl[i] = *reinterpret_cast<const uint4*>(Blo + boff);
        }
    };

    auto store_smem = [&]() {
#pragma unroll
        for (int i = 0; i < 2; i++) {
            int idx = tid + i * 256;
            int u4 = idx & 3, m = idx >> 2;
            *reinterpret_cast<uint4*>(&As[m * STR2 + u4 * 4]) = rAh[i];
            *reinterpret_cast<uint4*>(&As[TILE2 + m * STR2 + u4 * 4]) = rAl[i];
            *reinterpret_cast<uint4*>(&Bs[m * STR2 + u4 * 4]) = rBh[i];
            *reinterpret_cast<uint4*>(&Bs[TILE2 + m * STR2 + u4 * 4]) = rBl[i];
        }
    };

    load_regs(0);
    for (int k0 = 0; k0 < K; k0 += KT) {
        store_smem();
        __syncthreads();
        if (k0 + KT < K) load_regs(k0 + KT);

#pragma unroll
        for (int ks = 0; ks < 2; ks++) {
            const int kb = ks * 8 + c;
            uint32_t af[4][4], bf[4][2];
#pragma unroll
            for (int mi = 0; mi < 4; mi++) {
                const int mr = wm + mi * 16 + g;
                af[mi][0] = As[mr * STR2 + kb];
                af[mi][1] = As[(mr + 8) * STR2 + kb];
                af[mi][2] = As[mr * STR2 + kb + 4];
                af[mi][3] = As[(mr + 8) * STR2 + kb + 4];
            }
#pragma unroll
            for (int ni = 0; ni < 4; ni++) {
                const int nr = wn + ni * 8 + g;
                bf[ni][0] = Bs[nr * STR2 + kb];
                bf[ni][1] = Bs[nr * STR2 + kb + 4];
            }
#pragma unroll
            for (int mi = 0; mi < 4; mi++)
#pragma unroll
                for (int ni = 0; ni < 4; ni++)
                    mma_f16(acc[mi][ni], af[mi][0], af[mi][1], af[mi][2], af[mi][3],
                            bf[ni][0], bf[ni][1]);
            uint32_t afl[4][4], bfl[4][2];
#pragma unroll
            for (int mi = 0; mi < 4; mi++) {
                const int mr = wm + mi * 16 + g;
                afl[mi][0] = As[TILE2 + mr * STR2 + kb];
                afl[mi][1] = As[TILE2 + (mr + 8) * STR2 + kb];
                afl[mi][2] = As[TILE2 + mr * STR2 + kb + 4];
                afl[mi][3] = As[TILE2 + (mr + 8) * STR2 + kb + 4];
            }
#pragma unroll
            for (int ni = 0; ni < 4; ni++) {
                const int nr = wn + ni * 8 + g;
                bfl[ni][0] = Bs[TILE2 + nr * STR2 + kb];
                bfl[ni][1] = Bs[TILE2 + nr * STR2 + kb + 4];
            }
#pragma unroll
            for (int mi = 0; mi < 4; mi++)
#pragma unroll
                for (int ni = 0; ni < 4; ni++) {
                    mma_f16(acc[mi][ni], af[mi][0], af[mi][1], af[mi][2], af[mi][3],
                            bfl[ni][0], bfl[ni][1]);
                    mma_f16(acc[mi][ni], afl[mi][0], afl[mi][1], afl[mi][2], afl[mi][3],
                            bf[ni][0], bf[ni][1]);
                }
        }
        __syncthreads();
    }

#pragma unroll
    for (int mi = 0; mi < 4; mi++)
#pragma unroll
        for (int ni = 0; ni < 4; ni++) {
            const int row = m0 + wm + mi * 16 + g;
            const int col = n0 + wn + ni * 8 + 2 * c;
#pragma unroll
            for (int hf = 0; hf < 2; hf++) {
                const int rr2 = row + hf * 8;
                C[(size_t)rr2 * N + col]     = acc[mi][ni][hf * 2 + 0];
                C[(size_t)rr2 * N + col + 1] = acc[mi][ni][hf * 2 + 1];
            }
        }
}

// ---------------------------------------------------------------------------
// Fused flash attention (fp16 in/out): o = softmax(QK^T/8) @ V per (b,h).
// K double-buffered via cp.async; V transposed-scatter synchronously.
// ---------------------------------------------------------------------------
__global__ void __launch_bounds__(128) flash_attn_tc(
    const __half* __restrict__ qkv, __half* __restrict__ o)
{
    constexpr int QSTR = 36;
    constexpr int VSTR = 38;
    constexpr int KSEG = 64 * QSTR;
    __shared__ uint32_t Qs[64 * QSTR];
    __shared__ uint32_t Ks[2 * KSEG];
    __shared__ uint32_t Ps[64 * QSTR];
    __shared__ uint32_t Vs[64 * VSTR];

    const int qt = blockIdx.x, bh = blockIdx.y;
    const int b = bh >> 3, h = bh & 7;
    const int tid = threadIdx.x, lane = tid & 31, wid = tid >> 5;
    const int wm = wid * 16;
    const int g = lane >> 2, c = lane & 3;

#pragma unroll
    for (int i = 0; i < 4; i++) {
        int idx = tid + i * 128;
        int u4 = idx & 7, m = idx >> 3;
        uint4 u = *reinterpret_cast<const uint4*>(
            qkv + (size_t)(b * 512 + qt * 64 + m) * 1536 + h * 64 + u4 * 8);
        *reinterpret_cast<uint4*>(&Qs[m * QSTR + u4 * 4]) = u;
    }

    // issue K(0) via cp.async
    auto issue_k = [&](int kc, int buf) {
#pragma unroll
        for (int i = 0; i < 4; i++) {
            int idx = tid + i * 128;
            int u4 = idx & 7, m = idx >> 3;
            cp_async16(&Ks[buf * KSEG + m * QSTR + u4 * 4],
                       qkv + (size_t)(b * 512 + kc * 64 + m) * 1536 + 512 +
                           h * 64 + u4 * 8);
        }
    };
    issue_k(0, 0);
    CP_COMMIT();

    float m_r[2] = {-3.402823466e38f, -3.402823466e38f};
    float l_r[2] = {0.f, 0.f};
    float oacc[8][4];
#pragma unroll
    for (int nf = 0; nf < 8; nf++)
#pragma unroll
        for (int t = 0; t < 4; t++) oacc[nf][t] = 0.f;

    __half* Vsh = reinterpret_cast<__half*>(Vs);
    int pb = 0;

    for (int kc = 0; kc < 8; kc++) {
        // ---- V transposed scatter (sync) ----
#pragma unroll
        for (int i = 0; i < 4; i++) {
            int idx = tid + i * 128;
            int u4 = idx & 7, m = idx >> 3;
            uint4 vu = *reinterpret_cast<const uint4*>(
                qkv + (size_t)(b * 512 + kc * 64 + m) * 1536 + 1024 +
                    h * 64 + u4 * 8);
            const __half2* vh = reinterpret_cast<const __half2*>(&vu);
#pragma unroll
            for (int j = 0; j < 4; j++) {
                __half2 p = vh[j];
                Vsh[(u4 * 8 + 2 * j + 0) * 76 + m] = __low2half(p);
                Vsh[(u4 * 8 + 2 * j + 1) * 76 + m] = __high2half(p);
            }
        }
        CP_WAIT0();
        __syncthreads();
        if (kc + 1 < 8) {
            issue_k(kc + 1, pb ^ 1);
            CP_COMMIT();
        }
        const uint32_t* Ksb = Ks + pb * KSEG;

        // ---- S = Q K^T, contraction over d=64 ----
        float sacc[8][4];
#pragma unroll
        for (int nf = 0; nf < 8; nf++)
#pragma unroll
            for (int t = 0; t < 4; t++) sacc[nf][t] = 0.f;

#pragma unroll
        for (int ks = 0; ks < 4; ks++) {
            const int kb = ks * 8 + c;
            uint32_t a0 = Qs[(wm + g) * QSTR + kb];
            uint32_t a1 = Qs[(wm + g + 8) * QSTR + kb];
            uint32_t a2 = Qs[(wm + g) * QSTR + kb + 4];
            uint32_t a3 = Qs[(wm + g + 8) * QSTR + kb + 4];
#pragma unroll
            for (int nf = 0; nf < 8; nf++) {
                const int nr = nf * 8 + g;
                mma_f16(sacc[nf], a0, a1, a2, a3,
                        Ksb[nr * QSTR + kb], Ksb[nr * QSTR + kb + 4]);
            }
        }

        float mx0 = -3.402823466e38f, mx1 = -3.402823466e38f;
#pragma unroll
        for (int nf = 0; nf < 8; nf++) {
#pragma unroll
            for (int t = 0; t < 4; t++) sacc[nf][t] *= 0.125f;
            mx0 = fmaxf(mx0, fmaxf(sacc[nf][0], sacc[nf][1]));
            mx1 = fmaxf(mx1, fmaxf(sacc[nf][2], sacc[nf][3]));
        }
        mx0 = fmaxf(mx0, __shfl_xor_sync(0xffffffffu, mx0, 1));
        mx0 = fmaxf(mx0, __shfl_xor_sync(0xffffffffu, mx0, 2));
        mx1 = fmaxf(mx1, __shfl_xor_sync(0xffffffffu, mx1, 1));
        mx1 = fmaxf(mx1, __shfl_xor_sync(0xffffffffu, mx1, 2));

        const float mn0 = fmaxf(m_r[0], mx0);
        const float mn1 = fmaxf(m_r[1], mx1);
        const float f0 = expf(m_r[0] - mn0);
        const float f1 = expf(m_r[1] - mn1);

        float s0 = 0.f, s1 = 0.f;
#pragma unroll
        for (int nf = 0; nf < 8; nf++) {
            float p0 = expf(sacc[nf][0] - mn0);
            float p1 = expf(sacc[nf][1] - mn0);
            float p2 = expf(sacc[nf][2] - mn1);
            float p3 = expf(sacc[nf][3] - mn1);
            s0 += p0 + p1;
            s1 += p2 + p3;
            Ps[(wm + g) * QSTR + nf * 4 + c]     = pack_half2(p0, p1);
            Ps[(wm + g + 8) * QSTR + nf * 4 + c] = pack_half2(p2, p3);
            oacc[nf][0] *= f0; oacc[nf][1] *= f0;
            oacc[nf][2] *= f1; oacc[nf][3] *= f1;
        }
        s0 += __shfl_xor_sync(0xffffffffu, s0, 1);
        s0 += __shfl_xor_sync(0xffffffffu, s0, 2);
        s1 += __shfl_xor_sync(0xffffffffu, s1, 1);
        s1 += __shfl_xor_sync(0xffffffffu, s1, 2);
        l_r[0] = l_r[0] * f0 + s0;
        l_r[1] = l_r[1] * f1 + s1;
        m_r[0] = mn0; m_r[1] = mn1;
        __syncwarp();

#pragma unroll
        for (int ks = 0; ks < 4; ks++) {
            const int kb = ks * 8 + c;
            uint32_t a0 = Ps[(wm + g) * QSTR + kb];
            uint32_t a1 = Ps[(wm + g + 8) * QSTR + kb];
            uint32_t a2 = Ps[(wm + g) * QSTR + kb + 4];
            uint32_t a3 = Ps[(wm + g + 8) * QSTR + kb + 4];
#pragma unroll
            for (int nf = 0; nf < 8; nf++) {
                const int nr = nf * 8 + g;
                mma_f16(oacc[nf], a0, a1, a2, a3,
                        Vs[nr * VSTR + kb], Vs[nr * VSTR + kb + 4]);
            }
        }
        __syncthreads();
        pb ^= 1;
    }

    const float inv0 = 1.f / l_r[0];
    const float inv1 = 1.f / l_r[1];
#pragma unroll
    for (int nf = 0; nf < 8; nf++) {
        const int row = qt * 64 + wm + g;
        const int col = nf * 8 + 2 * c;
        __half* ob = o + (size_t)(b * 512 + row) * 512 + h * 64 + col;
        *reinterpret_cast<uint32_t*>(ob) =
            pack_half2(oacc[nf][0] * inv0, oacc[nf][1] * inv0);
        *reinterpret_cast<uint32_t*>(ob + 8 * 512) =
            pack_half2(oacc[nf][2] * inv1, oacc[nf][3] * inv1);
    }
}

// ---------------------------------------------------------------------------
// Row softmax, row length = CPT*256
// ---------------------------------------------------------------------------
template <int CPT>
__global__ void __launch_bounds__(256) softmax_kernel(float* __restrict__ data)
{
    float* row = data + (size_t)blockIdx.x * (CPT * 256);
    const int tid = threadIdx.x;
    float x[CPT];
    float mx = -3.402823466e38f;
#pragma unroll
    for (int c = 0; c < CPT; c++) {
        x[c] = row[tid + 256 * c];
        mx = fmaxf(mx, x[c]);
    }
    __shared__ float sh[8];
#pragma unroll
    for (int o = 16; o; o >>= 1) mx = fmaxf(mx, __shfl_xor_sync(0xffffffffu, mx, o));
    if ((tid & 31) == 0) sh[tid >> 5] = mx;
    __syncthreads();
    mx = sh[0];
#pragma unroll
    for (int w = 1; w < 8; w++) mx = fmaxf(mx, sh[w]);

    float s = 0.f;
#pragma unroll
    for (int c = 0; c < CPT; c++) { x[c] = expf(x[c] - mx); s += x[c]; }
    __syncthreads();
#pragma unroll
    for (int o = 16; o; o >>= 1) s += __shfl_xor_sync(0xffffffffu, s, o);
    if ((tid & 31) == 0) sh[tid >> 5] = s;
    __syncthreads();
    float tot = sh[0];
#pragma unroll
    for (int w = 1; w < 8; w++) tot += sh[w];
    float inv = 1.f / tot;
#pragma unroll
    for (int c = 0; c < CPT; c++) row[tid + 256 * c] = x[c] * inv;
}

// ---------------------------------------------------------------------------
// out = LayerNorm(X) * g + b ; dual fp32 + fp16 outputs
// ---------------------------------------------------------------------------
__global__ void __launch_bounds__(256) ln_kernel(
    const float* __restrict__ X,
    const float* __restrict__ gam, const float* __restrict__ bet,
    float* __restrict__ out, __half* __restrict__ out16)
{
    const size_t row = blockIdx.x;
    const float* xr = X + row * 512;
    const int tid = threadIdx.x;
    float t0 = xr[tid];
    float t1 = xr[tid + 256];

    __shared__ float sh[8];
    float s = t0 + t1;
#pragma unroll
    for (int o = 16; o; o >>= 1) s += __shfl_xor_sync(0xffffffffu, s, o);
    if ((tid & 31) == 0) sh[tid >> 5] = s;
    __syncthreads();
    float tot = sh[0];
#pragma unroll
    for (int w = 1; w < 8; w++) tot += sh[w];
    float mean = tot * (1.f / 512.f);
    float d0 = t0 - mean, d1 = t1 - mean;
    float q = d0 * d0 + d1 * d1;
    __syncthreads();
#pragma unroll
    for (int o = 16; o; o >>= 1) q += __shfl_xor_sync(0xffffffffu, q, o);
    if ((tid & 31) == 0) sh[tid >> 5] = q;
    __syncthreads();
    float vtot = sh[0];
#pragma unroll
    for (int w = 1; w < 8; w++) vtot += sh[w];
    float inv = rsqrtf(vtot * (1.f / 512.f) + 1e-5f);
    float r0 = d0 * inv * gam[tid] + bet[tid];
    float r1 = d1 * inv * gam[tid + 256] + bet[tid + 256];
    float* orow = out + row * 512;
    orow[tid] = r0;
    orow[tid + 256] = r1;
    __half* hrow = out16 + row * 512;
    hrow[tid] = __float2half_rn(r0);
    hrow[tid + 256] = __float2half_rn(r1);
}

// ---------------------------------------------------------------------------
// Graph branch (exact fp32, tiny cost)
// ---------------------------------------------------------------------------
__global__ void feat_fn_kernel(const float* __restrict__ x, float* __restrict__ fn)
{
    const int b = blockIdx.x, i = threadIdx.x;
    const float* xp = x + (size_t)b * 32768 + i;
    float s = 0.f;
    for (int t = 0; t < 512; t++) s += xp[(size_t)t * 64];
    float f = s * (1.f / 512.f);
    __shared__ float sh[64];
    sh[i] = f * f;
    __syncthreads();
    for (int o = 32; o; o >>= 1) {
        if (i < o) sh[i] += sh[i + o];
        __syncthreads();
    }
    float norm = sqrtf(sh[0]);
    fn[b * 64 + i] = f / fmaxf(norm, 1e-12f);
}

__global__ void graph_adj_kernel(const float* __restrict__ fn, float* __restrict__ An)
{
    const int b = blockIdx.x, i = threadIdx.x;
    __shared__ float f[64];
    __shared__ unsigned char A[64][64];
    f[i] = fn[b * 64 + i];
    for (int j = 0; j < 64; j++) A[i][j] = 0;
    __syncthreads();
    const float fi = f[i];
    float bv0 = -3.402823466e38f, bv1 = bv0, bv2 = bv0, bv3 = bv0;
    int i0 = 0, i1 = 0, i2 = 0, i3 = 0;
    for (int j = 0; j < 64; j++) {
        float v = fi * f[j];
        if (v > bv3) {
            if (v > bv0)      { bv3 = bv2; i3 = i2; bv2 = bv1; i2 = i1; bv1 = bv0; i1 = i0; bv0 = v; i0 = j; }
            else if (v > bv1) { bv3 = bv2; i3 = i2; bv2 = bv1; i2 = i1; bv1 = v; i1 = j; }
            else if (v > bv2) { bv3 = bv2; i3 = i2; bv2 = v; i2 = j; }
            else              { bv3 = v; i3 = j; }
        }
    }
    A[i][i1] = 1; A[i][i2] = 1; A[i][i3] = 1;
    __syncthreads();
    float deg = 0.f;
    for (int j = 0; j < 64; j++) {
        bool a = (j == i) || A[i][j] || A[j][i];
        deg += a ? 1.f : 0.f;
    }
    float inv = 1.f / deg;
    float* row = An + (size_t)b * 4096 + i * 64;
    for (int j = 0; j < 64; j++) {
        bool a = (j == i) || A[i][j] || A[j][i];
        row[j] = a ? inv : 0.f;
    }
}

__global__ void __launch_bounds__(256) gcn_gemm1_kernel(
    const float* __restrict__ x, const float* __restrict__ w,
    const float* __restrict__ bias, float* __restrict__ out)
{
    const int dt = blockIdx.x, b = blockIdx.y;
    __shared__ float Xs[16][64];
    __shared__ float Ws[64][17];
    const int tid = threadIdx.x, tx = tid & 15, ty = tid >> 4;
    float acc[4][4];
#pragma unroll
    for (int i = 0; i < 4; i++)
#pragma unroll
        for (int j = 0; j < 4; j++) acc[i][j] = 0.f;

    for (int k0 = 0; k0 < 512; k0 += 16) {
        {
            int kk = tid >> 4, f4 = (tid & 15) << 2;
            float4 v = *reinterpret_cast<const float4*>(
                x + (size_t)b * 32768 + (size_t)(k0 + kk) * 64 + f4);
            *reinterpret_cast<float4*>(&Xs[kk][f4]) = v;
            int dd = tid >> 2, k4 = (tid & 3) << 2;
            float4 w4 = *reinterpret_cast<const float4*>(
                w + (size_t)(dt * 64 + dd) * 512 + k0 + k4);
            Ws[dd][k4 + 0] = w4.x; Ws[dd][k4 + 1] = w4.y;
            Ws[dd][k4 + 2] = w4.z; Ws[dd][k4 + 3] = w4.w;
        }
        __syncthreads();
#pragma unroll
        for (int kk = 0; kk < 16; kk++) {
            float a[4], bb[4];
#pragma unroll
            for (int i = 0; i < 4; i++) a[i] = Xs[kk][ty + 16 * i];
#pragma unroll
            for (int j = 0; j < 4; j++) bb[j] = Ws[tx + 16 * j][kk];
#pragma unroll
            for (int i = 0; i < 4; i++)
#pragma unroll
                for (int j = 0; j < 4; j++)
                    acc[i][j] = fmaf(a[i], bb[j], acc[i][j]);
        }
        __syncthreads();
    }
#pragma unroll
    for (int i = 0; i < 4; i++)
#pragma unroll
        for (int j = 0; j < 4; j++) {
            int dd = dt * 64 + tx + 16 * j;
            out[(size_t)b * 32768 + (size_t)(ty + 16 * i) * 512 + dd] =
                acc[i][j] + bias[dd];
        }
}

__global__ void __launch_bounds__(256) gcn_gemm2_kernel(
    const float* __restrict__ Ain, const float* __restrict__ w,
    const float* __restrict__ bias, float* __restrict__ out)
{
    const int st = blockIdx.x, b = blockIdx.y;
    __shared__ float As[64][17];
    __shared__ float Ws[64][17];
    const int tid = threadIdx.x, tx = tid & 15, ty = tid >> 4;
    const int rr = tid >> 2, k4 = (tid & 3) << 2;
    float acc[4][4];
#pragma unroll
    for (int i = 0; i < 4; i++)
#pragma unroll
        for (int j = 0; j < 4; j++) acc[i][j] = 0.f;

    for (int k0 = 0; k0 < 512; k0 += 16) {
        float4 a4 = *reinterpret_cast<const float4*>(
            Ain + (size_t)b * 32768 + (size_t)rr * 512 + k0 + k4);
        As[rr][k4 + 0] = a4.x; As[rr][k4 + 1] = a4.y;
        As[rr][k4 + 2] = a4.z; As[rr][k4 + 3] = a4.w;
        float4 w4 = *reinterpret_cast<const float4*>(
            w + (size_t)(st * 64 + rr) * 512 + k0 + k4);
        Ws[rr][k4 + 0] = w4.x; Ws[rr][k4 + 1] = w4.y;
        Ws[rr][k4 + 2] = w4.z; Ws[rr][k4 + 3] = w4.w;
        __syncthreads();
#pragma unroll
        for (int kk = 0; kk < 16; kk++) {
            float a[4], bb[4];
#pragma unroll
            for (int i = 0; i < 4; i++) a[i] = As[ty + 16 * i][kk];
#pragma unroll
            for (int j = 0; j < 4; j++) bb[j] = Ws[tx + 16 * j][kk];
#pragma unroll
            for (int i = 0; i < 4; i++)
#pragma unroll
                for (int j = 0; j < 4; j++)
                    acc[i][j] = fmaf(a[i], bb[j], acc[i][j]);
        }
        __syncthreads();
    }
#pragma unroll
    for (int i = 0; i < 4; i++)
#pragma unroll
        for (int j = 0; j < 4; j++) {
            int ss = st * 64 + tx + 16 * j;
            out[(size_t)b * 32768 + (size_t)(ty + 16 * i) * 512 + ss] =
                acc[i][j] + bias[ss];
        }
}

template <bool RELU, bool TRANSOUT>
__global__ void __launch_bounds__(256) an_mult_kernel(
    const float* __restrict__ An, const float* __restrict__ in,
    float* __restrict__ out)
{
    const int dt = blockIdx.x, b = blockIdx.y;
    __shared__ float As[64][65];
    __shared__ float Ins[64][64];
    const int tid = threadIdx.x, tx = tid & 15, ty = tid >> 4;

    for (int t = tid; t < 4096; t += 256)
        As[t >> 6][t & 63] = An[(size_t)b * 4096 + t];
#pragma unroll
    for (int hh = 0; hh < 4; hh++) {
        int idx4 = tid + hh * 256;
        int gg = idx4 >> 4, c4 = (idx4 & 15) << 2;
        float4 v = *reinterpret_cast<const float4*>(
            in + (size_t)b * 32768 + (size_t)gg * 512 + dt * 64 + c4);
        *reinterpret_cast<float4*>(&Ins[gg][c4]) = v;
    }
    __syncthreads();

    float acc[4][4];
#pragma unroll
    for (int i = 0; i < 4; i++)
#pragma unroll
        for (int j = 0; j < 4; j++) acc[i][j] = 0.f;

#pragma unroll 8
    for (int kk = 0; kk < 64; kk++) {
        float a[4], bb[4];
#pragma unroll
        for (int i = 0; i < 4; i++) a[i] = As[ty + 16 * i][kk];
#pragma unroll
        for (int j = 0; j < 4; j++) bb[j] = Ins[kk][tx + 16 * j];
#pragma unroll
        for (int i = 0; i < 4; i++)
#pragma unroll
            for (int j = 0; j < 4; j++)
                acc[i][j] = fmaf(a[i], bb[j], acc[i][j]);
    }

#pragma unroll
    for (int i = 0; i < 4; i++)
#pragma unroll
        for (int j = 0; j < 4; j++) {
            int ff = ty + 16 * i;
            int dd = dt * 64 + tx + 16 * j;
            float v = acc[i][j];
            if (RELU) v = fmaxf(v, 0.f);
            if (!TRANSOUT)
                out[(size_t)b * 32768 + (size_t)ff * 512 + dd] = v;
            else
                out[(size_t)b * 32768 + (size_t)dd * 64 + ff] = v;
        }
}

// ---------------------------------------------------------------------------
// Host orchestration
// ---------------------------------------------------------------------------
extern "C" void kernel_launch(void* const* d_in, const int* in_sizes, int n_in,
                              void* d_out, int out_size)
{
    const float* x      = (const float*)d_in[0];
    const float* W_in   = (const float*)d_in[1];
    const float* b_in   = (const float*)d_in[2];
    const float* qkv_w  = (const float*)d_in[3];
    const float* qkv_b  = (const float*)d_in[4];
    const float* out_w  = (const float*)d_in[5];
    const float* out_b  = (const float*)d_in[6];
    const float* ln1_g  = (const float*)d_in[7];
    const float* ln1_b  = (const float*)d_in[8];
    const float* ln2_g  = (const float*)d_in[9];
    const float* ln2_b  = (const float*)d_in[10];
    const float* ff1_w  = (const float*)d_in[11];
    const float* ff1_b  = (const float*)d_in[12];
    const float* ff2_w  = (const float*)d_in[13];
    const float* ff2_b  = (const float*)d_in[14];
    const float* memory = (const float*)d_in[15];
    const float* fc1_w  = (const float*)d_in[16];
    const float* fc1_b  = (const float*)d_in[17];
    const float* fc2_w  = (const float*)d_in[18];
    const float* fc2_b  = (const float*)d_in[19];
    const float* gc1_w  = (const float*)d_in[20];
    const float* gc1_b  = (const float*)d_in[21];
    const float* gc2_w  = (const float*)d_in[22];
    const float* gc2_b  = (const float*)d_in[23];

    float* out    = (float*)d_out;
    float* t_out  = out;                       // (32,512,64)
    float* gout_p = out + 1048576;             // (32,512,64)
    float* attn_p = out + 2097152;             // (32,512,1024)

    static float *p_pe = nullptr, *p_h, *p_tmp, *p_fn, *p_An, *p_gt1, *p_gh1;
    static __half *p_h16, *p_h16lo, *p_qkv, *p_o, *p_ff, *p_mlo, *p_wh;
    if (!p_pe) {
        cudaGetSymbolAddress((void**)&p_pe,    g_pe);
        cudaGetSymbolAddress((void**)&p_h,     g_h);
        cudaGetSymbolAddress((void**)&p_h16,   g_h16);
        cudaGetSymbolAddress((void**)&p_h16lo, g_h16lo);
        cudaGetSymbolAddress((void**)&p_tmp,   g_tmp);
        cudaGetSymbolAddress((void**)&p_qkv,   g_qkv);
        cudaGetSymbolAddress((void**)&p_o,     g_o);
        cudaGetSymbolAddress((void**)&p_ff,    g_ff);
        cudaGetSymbolAddress((void**)&p_mlo,   g_mlo);
        cudaGetSymbolAddress((void**)&p_fn,    g_fn);
        cudaGetSymbolAddress((void**)&p_An,    g_An);
        cudaGetSymbolAddress((void**)&p_gt1,   g_gt1);
        cudaGetSymbolAddress((void**)&p_gh1,   g_gh1);
        cudaGetSymbolAddress((void**)&p_wh,    g_wh);
    }

    const int M = 16384;

    // ---- pre-convert weights to fp16 (graph-captured) ----
    auto conv = [&](const float* src, __half* dst, int n) {
        convert_w_kernel<<<(n / 4 + 255) / 256, 256>>>(src, dst, n / 4);
    };
    conv(qkv_w,  p_wh + WH_QKV, 3 * 1536 * 512);
    conv(out_w,  p_wh + WH_OUT, 3 * 512 * 512);
    conv(ff1_w,  p_wh + WH_FF1, 3 * 2048 * 512);
    conv(ff2_w,  p_wh + WH_FF2, 3 * 512 * 2048);
    conv(memory, p_wh + WH_MEM, 1024 * 512);
    conv(fc1_w,  p_wh + WH_FC1, 512 * 1024);
    conv(fc2_w,  p_wh + WH_FC2, 64 * 512);
    conv(W_in,   p_wh + WH_WIN, 512 * 64);
    // memory low part for split sims
    make_lo_kernel<<<(1024 * 512 / 4 + 255) / 256, 256>>>(
        memory, p_wh + WH_MEM, p_mlo, 1024 * 512 / 4);

    pe_kernel<<<(512 * 512 + 255) / 256, 256>>>(p_pe);

    // h = x @ W_in^T + b_in + pe (dual fp32+fp16 out, fp16 B register-staged)
    gemm_tc<true, 2, false, false, false, true, false, true>
        <<<dim3(4, 128), 256>>>(
        x, nullptr, p_wh + WH_WIN, b_in, p_pe, nullptr, p_h, p_h16, M, 512, 64);

    for (int l = 0; l < 3; l++) {
        // qkv (pure fp16, cp.async)
        gemm_tc<true, 0, false, true, true, true, true, false>
            <<<dim3(12, 128), 256>>>(
            p_h16, nullptr, p_wh + WH_QKV + (size_t)l * 1536 * 512,
            qkv_b + l * 1536, nullptr, nullptr, p_qkv, nullptr, M, 1536, 512);
        // fused attention
        flash_attn_tc<<<dim3(8, 256), 128>>>(p_qkv, p_o);
        // out projection + residual (pure fp16 in, cp.async, fp32 out)
        gemm_tc<true, 3, false, true, false, true, true, false>
            <<<dim3(4, 128), 256>>>(
            p_o, nullptr, p_wh + WH_OUT + (size_t)l * 512 * 512,
            out_b + l * 512, nullptr, p_h, p_tmp, nullptr, M, 512, 512);
        ln_kernel<<<16384, 256>>>(p_tmp, ln1_g + l * 512, ln1_b + l * 512,
                                  p_h, p_h16);
        // feed-forward (pure fp16, cp.async)
        gemm_tc<true, 1, false, true, true, true, true, false>
            <<<dim3(16, 128), 256>>>(
            p_h16, nullptr, p_wh + WH_FF1 + (size_t)l * 2048 * 512,
            ff1_b + l * 2048, nullptr, nullptr, p_ff, nullptr, M, 2048, 512);
        gemm_tc<true, 3, false, true, false, true, true, false>
            <<<dim3(4, 128), 256>>>(
            p_ff, nullptr, p_wh + WH_FF2 + (size_t)l * 512 * 2048,
            ff2_b + l * 512, nullptr, p_h, p_tmp, nullptr, M, 512, 2048);
        ln_kernel<<<16384, 256>>>(p_tmp, ln2_g + l * 512, ln2_b + l * 512,
                                  p_h, p_h16);
    }

    // sims: split fp16 operands (h16/h16lo x memhi/memlo), 3-pass exact-order
    make_lo_kernel<<<(16384 * 512 / 4 + 255) / 256, 256>>>(
        p_h, p_h16, p_h16lo, 16384 * 512 / 4);
    sims_split_tc<<<dim3(8, 128), 256>>>(
        p_h16, p_h16lo, p_wh + WH_MEM, p_mlo, attn_p, M, 1024, 512);
    softmax_kernel<4><<<16384, 256>>>(attn_p);
    // upd = attn @ memory (fp32 A converted, fp16 B, fp16 out)
    gemm_tc<false, 0, false, false, true, true, false, false>
        <<<dim3(4, 128), 256>>>(
        attn_p, nullptr, p_wh + WH_MEM, nullptr, nullptr, nullptr,
        p_o, nullptr, M, 512, 1024);
    // fc1 over fp16 concat [h16 | upd16] (cp.async), fp16 out into qkv buffer
    gemm_tc<true, 1, true, true, true, true, true, false>
        <<<dim3(4, 128), 256>>>(
        p_h16, p_o, p_wh + WH_FC1, fc1_b, nullptr, nullptr,
        p_qkv, nullptr, M, 512, 1024);
    // fc2 (pure fp16 in, cp.async, fp32 out to t_out)
    gemm_tc<true, 0, false, true, false, true, true, false>
        <<<dim3(1, 128), 256>>>(
        p_qkv, nullptr, p_wh + WH_FC2, fc2_b, nullptr, nullptr,
        t_out, nullptr, M, 64, 512);

    // graph branch (exact fp32)
    feat_fn_kernel<<<32, 64>>>(x, p_fn);
    graph_adj_kernel<<<32, 64>>>(p_fn, p_An);
    gcn_gemm1_kernel<<<dim3(8, 32), 256>>>(x, gc1_w, gc1_b, p_gt1);
    an_mult_kernel<true, false><<<dim3(8, 32), 256>>>(p_An, p_gt1, p_gh1);
    gcn_gemm2_kernel<<<dim3(8, 32), 256>>>(p_gh1, gc2_w, gc2_b, p_gt1);
    an_mult_kernel<false, true><<<dim3(8, 32), 256>>>(p_An, p_gt1, gout_p);

    (void)in_sizes; (void)n_in; (void)out_size;
}

// round 14
// speedup vs baseline: 1.0447x; 1.0447x over previous
#include <cuda_runtime.h>
#include <cuda_fp16.h>
#include <math.h>
#include <stdint.h>

// ---------------------------------------------------------------------------
// Problem constants
//  B=32, S=512, F_IN=64, D=512, DFF=2048, MEM=1024, L=3, H=8, dh=64
//  rows = B*S = 16384
// ---------------------------------------------------------------------------

// ------------------------- static scratch buffers --------------------------
__device__ float  g_pe[512 * 512];             // 1 MB
__device__ float  g_h[16384 * 512];            // 32 MB (fp32 residual stream)
__device__ __half g_h16[16384 * 512];          // 16 MB (fp16 mirror of h)
__device__ __half g_h16lo[16384 * 512];        // 16 MB (fp16 low part of h)
__device__ float  g_tmp[16384 * 512];          // 32 MB
__device__ __half g_qkv[16384 * 1536];         // 48 MB (reused as fc1 out)
__device__ __half g_o[16384 * 512];            // 16 MB (reused as upd16)
__device__ __half g_ff[16384 * 2048];          // 64 MB (reused as attn16)
__device__ __half g_mlo[1024 * 512];           // 1 MB (fp16 low part of memory)
__device__ __half g_memT[512 * 1024];          // 1 MB (fp16 memory transposed)
__device__ float  g_fn[32 * 64];
__device__ float  g_An[32 * 64 * 64];
__device__ float  g_gt1[32 * 64 * 512];        // 4 MB
__device__ float  g_gh1[32 * 64 * 512];        // 4 MB
__device__ __half g_wh[10551296];              // 21 MB fp16 weights

// fp16 weight buffer offsets
#define WH_QKV   0                               // 3*1536*512 = 2359296
#define WH_OUT   2359296                         // 3*512*512  = 786432
#define WH_FF1   3145728                         // 3*2048*512 = 3145728
#define WH_FF2   6291456                         // 3*512*2048 = 3145728
#define WH_MEM   9437184                         // 1024*512   = 524288
#define WH_FC1   9961472                         // 512*1024   = 524288
#define WH_FC2   10485760                        // 64*512     = 32768
#define WH_WIN   10518528                        // 512*64     = 32768

// ---------------------------------------------------------------------------
// fp16 / async helpers
// ---------------------------------------------------------------------------
__device__ __forceinline__ uint32_t pack_half2(float a, float b) {
    __half2 h = __floats2half2_rn(a, b);
    return *reinterpret_cast<uint32_t*>(&h);
}

__device__ __forceinline__ void mma_f16(float c[4],
    uint32_t a0, uint32_t a1, uint32_t a2, uint32_t a3,
    uint32_t b0, uint32_t b1)
{
    asm volatile(
        "mma.sync.aligned.m16n8k16.row.col.f32.f16.f16.f32 "
        "{%0,%1,%2,%3}, {%4,%5,%6,%7}, {%8,%9}, {%0,%1,%2,%3};"
        : "+f"(c[0]), "+f"(c[1]), "+f"(c[2]), "+f"(c[3])
        : "r"(a0), "r"(a1), "r"(a2), "r"(a3), "r"(b0), "r"(b1));
}

__device__ __forceinline__ void cp_async16(void* smem_ptr, const void* gptr) {
    uint32_t a = (uint32_t)__cvta_generic_to_shared(smem_ptr);
    asm volatile("cp.async.cg.shared.global [%0], [%1], 16;" :: "r"(a), "l"(gptr));
}
#define CP_COMMIT() asm volatile("cp.async.commit_group;")
#define CP_WAIT0()  asm volatile("cp.async.wait_group 0;")

// ---------------------------------------------------------------------------
// Weight pre-conversion: fp32 -> fp16 (rn)
// ---------------------------------------------------------------------------
__global__ void convert_w_kernel(const float* __restrict__ src,
                                 __half* __restrict__ dst, int n4)
{
    int i = blockIdx.x * 256 + threadIdx.x;
    if (i >= n4) return;
    float4 v = *reinterpret_cast<const float4*>(src + i * 4);
    uint2 u;
    u.x = pack_half2(v.x, v.y);
    u.y = pack_half2(v.z, v.w);
    *reinterpret_cast<uint2*>(dst + i * 4) = u;
}

// lo = fp16(src - fp32(hi))  (hi already = fp16_rn(src))
__global__ void make_lo_kernel(const float* __restrict__ src,
                               const __half* __restrict__ hi,
                               __half* __restrict__ lo, int n4)
{
    int i = blockIdx.x * 256 + threadIdx.x;
    if (i >= n4) return;
    float4 v = *reinterpret_cast<const float4*>(src + i * 4);
    uint2 hu = *reinterpret_cast<const uint2*>(hi + i * 4);
    __half2 h0 = *reinterpret_cast<__half2*>(&hu.x);
    __half2 h1 = *reinterpret_cast<__half2*>(&hu.y);
    uint2 lu;
    lu.x = pack_half2(v.x - __low2float(h0), v.y - __high2float(h0));
    lu.y = pack_half2(v.z - __low2float(h1), v.w - __high2float(h1));
    *reinterpret_cast<uint2*>(lo + i * 4) = lu;
}

// memT[d][m] = wh_mem[m][d]  (fp16 -> fp16 transpose, 1024x512 -> 512x1024)
__global__ void transpose_mem_kernel(const __half* __restrict__ src,
                                     __half* __restrict__ dst)
{
    __shared__ __half s[32][33];
    const int m0 = blockIdx.x * 32, d0 = blockIdx.y * 32;
    const int tx = threadIdx.x, ty = threadIdx.y;
    s[ty][tx] = src[(size_t)(m0 + ty) * 512 + d0 + tx];
    __syncthreads();
    dst[(size_t)(d0 + ty) * 1024 + m0 + tx] = s[tx][ty];
}

// ---------------------------------------------------------------------------
// Positional encoding (match numpy float64 -> float32)
// ---------------------------------------------------------------------------
__global__ void pe_kernel(float* __restrict__ pe) {
    int i = blockIdx.x * 256 + threadIdx.x;
    if (i >= 512 * 512) return;
    int s = i >> 9, d = i & 511;
    int t2 = d & ~1;
    double div = exp((double)t2 * (-9.210340371976184 / 512.0)); // ln(10000)
    double a = (double)s * div;
    pe[i] = (float)((d & 1) ? cos(a) : sin(a));
}

// ---------------------------------------------------------------------------
// Tensor-core GEMM (fp16 mma, fp32 accumulate).
//  C[M,N] = A[M,K] * op(B) + bias (+epilogue)
//   TRANSB : B is (N,K) row-major -> C = A @ B^T ; false: B (K,N)
//   CATAB  : A logical [M,1024] = concat(A[:,:512], A2[:,:512]) (fp16 srcs)
//   AHALF  : A is __half          OHALF : C written as __half
//   BHALF  : B is __half          CPA   : cp.async double-buffered mainloop
//   ODUAL  : write C fp32 AND C2 fp16
// Block tile 128x128, 256 threads (8 warps = 2m x 4n of 64x32 warp tiles).
// EPI: 0 bias, 1 bias+relu, 2 bias+pos-encoding, 3 bias+residual
// ---------------------------------------------------------------------------
template <bool TRANSB, int EPI, bool CATAB, bool AHALF, bool OHALF,
          bool BHALF, bool CPA, bool ODUAL>
__global__ void __launch_bounds__(256) gemm_tc(
    const void* __restrict__ Avoid, const void* __restrict__ A2void,
    const void* __restrict__ Bvoid,
    const float* __restrict__ bias, const float* __restrict__ pe,
    const float* __restrict__ resid,
    void* __restrict__ Cvoid, void* __restrict__ C2void,
    int M, int N, int K)
{
    constexpr int KT    = 32;              // fp16 elems per K-tile
    constexpr int STR2  = 20;              // half2 (uint) stride: 16 + 4
    constexpr int TILE2 = 128 * STR2;
    constexpr int NSEG  = CPA ? 2 : 1;

    __shared__ uint32_t As[NSEG * TILE2];
    __shared__ uint32_t Bs[NSEG * TILE2];

    const float*  Af  = (const float*)Avoid;
    const __half* Ah  = (const __half*)Avoid;
    const __half* A2h = (const __half*)A2void;
    const float*  Bf  = (const float*)Bvoid;
    const __half* Bh  = (const __half*)Bvoid;
    float*  Cf  = (float*)Cvoid;
    __half* Ch  = (__half*)Cvoid;
    __half* Ch2 = (__half*)C2void;

    const int tid  = threadIdx.x;
    const int lane = tid & 31, wid = tid >> 5;
    const int wm = (wid >> 2) * 64, wn = (wid & 3) * 32;
    const int g = lane >> 2, c = lane & 3;
    const int m0 = blockIdx.y * 128, n0 = blockIdx.x * 128;

    float acc[4][4][4];
#pragma unroll
    for (int i = 0; i < 4; i++)
#pragma unroll
        for (int j = 0; j < 4; j++)
#pragma unroll
            for (int t = 0; t < 4; t++) acc[i][j][t] = 0.f;

    // ---- MMA on one buffer ----
    auto mma_tile = [&](int buf) {
        const uint32_t* Asb = As + (CPA ? buf * TILE2 : 0);
        const uint32_t* Bsb = Bs + (CPA ? buf * TILE2 : 0);
#pragma unroll
        for (int ks = 0; ks < 2; ks++) {
            const int kb = ks * 8 + c;
            uint32_t af[4][4], bf[4][2];
#pragma unroll
            for (int mi = 0; mi < 4; mi++) {
                const int mr = wm + mi * 16 + g;
                af[mi][0] = Asb[mr * STR2 + kb];
                af[mi][1] = Asb[(mr + 8) * STR2 + kb];
                af[mi][2] = Asb[mr * STR2 + kb + 4];
                af[mi][3] = Asb[(mr + 8) * STR2 + kb + 4];
            }
#pragma unroll
            for (int ni = 0; ni < 4; ni++) {
                const int nr = wn + ni * 8 + g;
                bf[ni][0] = Bsb[nr * STR2 + kb];
                bf[ni][1] = Bsb[nr * STR2 + kb + 4];
            }
#pragma unroll
            for (int mi = 0; mi < 4; mi++)
#pragma unroll
                for (int ni = 0; ni < 4; ni++)
                    mma_f16(acc[mi][ni], af[mi][0], af[mi][1], af[mi][2], af[mi][3],
                            bf[ni][0], bf[ni][1]);
        }
    };

    if (CPA) {
        // ================= cp.async double-buffered mainloop =================
        auto issue_cp = [&](int k0, int buf) {
            uint32_t* Asb = As + buf * TILE2;
            uint32_t* Bsb = Bs + buf * TILE2;
#pragma unroll
            for (int i = 0; i < 2; i++) {
                int idx = tid + i * 256;
                int u4 = idx & 3, m = idx >> 2;
                const __half* Ap = Ah;
                int lda = K, kcol = k0 + u4 * 8;
                if (CATAB) {
                    lda = 512;
                    if (k0 >= 512) { Ap = A2h; kcol -= 512; }
                }
                cp_async16(&Asb[m * STR2 + u4 * 4],
                           Ap + (size_t)(m0 + m) * lda + kcol);
            }
#pragma unroll
            for (int i = 0; i < 2; i++) {
                int idx = tid + i * 256;
                int u4 = idx & 3, n = idx >> 2;
                if (n0 + n < N)
                    cp_async16(&Bsb[n * STR2 + u4 * 4],
                               Bh + (size_t)(n0 + n) * K + k0 + u4 * 8);
            }
        };

        issue_cp(0, 0);
        CP_COMMIT();
        int pb = 0;
        for (int k0 = 0; k0 < K; k0 += KT) {
            CP_WAIT0();
            __syncthreads();
            if (k0 + KT < K) {
                issue_cp(k0 + KT, pb ^ 1);
                CP_COMMIT();
            }
            mma_tile(pb);
            pb ^= 1;
        }
        __syncthreads();
    } else {
        // ============== register-staged single-buffer mainloop ==============
        float4 rA[4], rB[4];
        uint4  rAh[2], rBh[2];

        auto load_regs = [&](int k0) {
            if (AHALF) {
#pragma unroll
                for (int i = 0; i < 2; i++) {
                    int idx = tid + i * 256;
                    int u4 = idx & 3, m = idx >> 2;
                    rAh[i] = *reinterpret_cast<const uint4*>(
                        Ah + (size_t)(m0 + m) * K + k0 + u4 * 8);
                }
            } else {
#pragma unroll
                for (int i = 0; i < 4; i++) {
                    int idx = tid + i * 256;
                    int kg = idx & 7, m = idx >> 3;
                    rA[i] = *reinterpret_cast<const float4*>(
                        Af + (size_t)(m0 + m) * K + k0 + kg * 4);
                }
            }
            if (BHALF) {
                if (TRANSB) {
#pragma unroll
                    for (int i = 0; i < 2; i++) {
                        int idx = tid + i * 256;
                        int u4 = idx & 3, n = idx >> 2;
                        rBh[i] = make_uint4(0, 0, 0, 0);
                        if (n0 + n < N)
                            rBh[i] = *reinterpret_cast<const uint4*>(
                                Bh + (size_t)(n0 + n) * K + k0 + u4 * 8);
                    }
                } else {
#pragma unroll
                    for (int i = 0; i < 2; i++) {
                        int idx = tid + i * 256;
                        int ng = idx & 15, kk = idx >> 4;
                        rBh[i] = make_uint4(0, 0, 0, 0);
                        if (n0 + ng * 8 < N)
                            rBh[i] = *reinterpret_cast<const uint4*>(
                                Bh + (size_t)(k0 + kk) * N + n0 + ng * 8);
                    }
                }
            } else if (TRANSB) {
#pragma unroll
                for (int i = 0; i < 4; i++) {
                    int idx = tid + i * 256;
                    int kg = idx & 7, n = idx >> 3;
                    rB[i] = make_float4(0.f, 0.f, 0.f, 0.f);
                    if (n0 + n < N)
                        rB[i] = *reinterpret_cast<const float4*>(
                            Bf + (size_t)(n0 + n) * K + k0 + kg * 4);
                }
            } else {
#pragma unroll
                for (int i = 0; i < 4; i++) {
                    int idx = tid + i * 256;
                    int ng = idx & 31, kk = idx >> 5;
                    int n = ng * 4;
                    rB[i] = make_float4(0.f, 0.f, 0.f, 0.f);
                    if (n0 + n < N)
                        rB[i] = *reinterpret_cast<const float4*>(
                            Bf + (size_t)(k0 + kk) * N + n0 + n);
                }
            }
        };

        auto store_smem = [&]() {
            if (AHALF) {
#pragma unroll
                for (int i = 0; i < 2; i++) {
                    int idx = tid + i * 256;
                    int u4 = idx & 3, m = idx >> 2;
                    *reinterpret_cast<uint4*>(&As[m * STR2 + u4 * 4]) = rAh[i];
                }
            } else {
#pragma unroll
                for (int i = 0; i < 4; i++) {
                    int idx = tid + i * 256;
                    int kg = idx & 7, m = idx >> 3;
                    float4 v = rA[i];
                    uint2 hu;
                    hu.x = pack_half2(v.x, v.y);
                    hu.y = pack_half2(v.z, v.w);
                    *reinterpret_cast<uint2*>(&As[m * STR2 + kg * 2]) = hu;
                }
            }
            if (BHALF) {
                if (TRANSB) {
#pragma unroll
                    for (int i = 0; i < 2; i++) {
                        int idx = tid + i * 256;
                        int u4 = idx & 3, n = idx >> 2;
                        *reinterpret_cast<uint4*>(&Bs[n * STR2 + u4 * 4]) = rBh[i];
                    }
                } else {
                    __half* Bsh = reinterpret_cast<__half*>(Bs);
#pragma unroll
                    for (int i = 0; i < 2; i++) {
                        int idx = tid + i * 256;
                        int ng = idx & 15, kk = idx >> 4;
                        const __half* hv = reinterpret_cast<const __half*>(&rBh[i]);
#pragma unroll
                        for (int j = 0; j < 8; j++)
                            Bsh[(ng * 8 + j) * (STR2 * 2) + kk] = hv[j];
                    }
                }
            } else if (TRANSB) {
#pragma unroll
                for (int i = 0; i < 4; i++) {
                    int idx = tid + i * 256;
                    int kg = idx & 7, n = idx >> 3;
                    float4 v = rB[i];
                    uint2 hu;
                    hu.x = pack_half2(v.x, v.y);
                    hu.y = pack_half2(v.z, v.w);
                    *reinterpret_cast<uint2*>(&Bs[n * STR2 + kg * 2]) = hu;
                }
            } else {
                __half* Bsh = reinterpret_cast<__half*>(Bs);
#pragma unroll
                for (int i = 0; i < 4; i++) {
                    int idx = tid + i * 256;
                    int ng = idx & 31, kk = idx >> 5;
                    int n = ng * 4;
                    float4 v = rB[i];
                    float vv[4] = {v.x, v.y, v.z, v.w};
#pragma unroll
                    for (int j = 0; j < 4; j++)
                        Bsh[(n + j) * (STR2 * 2) + kk] = __float2half_rn(vv[j]);
                }
            }
        };

        load_regs(0);
        for (int k0 = 0; k0 < K; k0 += KT) {
            store_smem();
            __syncthreads();
            if (k0 + KT < K) load_regs(k0 + KT);
            mma_tile(0);
            __syncthreads();
        }
    }

    // ---- epilogue ----
#pragma unroll
    for (int mi = 0; mi < 4; mi++) {
#pragma unroll
        for (int ni = 0; ni < 4; ni++) {
            const int row = m0 + wm + mi * 16 + g;
            const int col = n0 + wn + ni * 8 + 2 * c;
#pragma unroll
            for (int hf = 0; hf < 2; hf++) {
                const int rr2 = row + hf * 8;
                if (col < N) {
                    float v0 = acc[mi][ni][hf * 2 + 0];
                    float v1 = acc[mi][ni][hf * 2 + 1];
                    if (bias) { v0 += __ldg(bias + col); v1 += __ldg(bias + col + 1); }
                    if (EPI == 1) { v0 = fmaxf(v0, 0.f); v1 = fmaxf(v1, 0.f); }
                    if (EPI == 2) {
                        v0 += pe[((rr2 & 511) << 9) + col];
                        v1 += pe[((rr2 & 511) << 9) + col + 1];
                    }
                    if (EPI == 3) {
                        v0 += resid[(size_t)rr2 * N + col];
                        v1 += resid[(size_t)rr2 * N + col + 1];
                    }
                    if (OHALF) {
                        *reinterpret_cast<uint32_t*>(Ch + (size_t)rr2 * N + col) =
                            pack_half2(v0, v1);
                    } else {
                        Cf[(size_t)rr2 * N + col]     = v0;
                        Cf[(size_t)rr2 * N + col + 1] = v1;
                        if (ODUAL)
                            *reinterpret_cast<uint32_t*>(Ch2 + (size_t)rr2 * N + col) =
                                pack_half2(v0, v1);
                    }
                }
            }
        }
    }
}

// ---------------------------------------------------------------------------
// Sims split GEMM: C = Ahi@Bhi^T + Ahi@Blo^T + Alo@Bhi^T (fp32 acc).
// All operands pre-split fp16; raw uint4 loads, register-staged single buffer.
// ---------------------------------------------------------------------------
__global__ void __launch_bounds__(256) sims_split_tc(
    const __half* __restrict__ Ahi, const __half* __restrict__ Alo,
    const __half* __restrict__ Bhi, const __half* __restrict__ Blo,
    float* __restrict__ C, int M, int N, int K)
{
    constexpr int KT    = 32;
    constexpr int STR2  = 20;
    constexpr int TILE2 = 128 * STR2;

    __shared__ uint32_t As[2 * TILE2];   // [hi | lo]
    __shared__ uint32_t Bs[2 * TILE2];

    const int tid  = threadIdx.x;
    const int lane = tid & 31, wid = tid >> 5;
    const int wm = (wid >> 2) * 64, wn = (wid & 3) * 32;
    const int g = lane >> 2, c = lane & 3;
    const int m0 = blockIdx.y * 128, n0 = blockIdx.x * 128;

    float acc[4][4][4];
#pragma unroll
    for (int i = 0; i < 4; i++)
#pragma unroll
        for (int j = 0; j < 4; j++)
#pragma unroll
            for (int t = 0; t < 4; t++) acc[i][j][t] = 0.f;

    uint4 rAh[2], rAl[2], rBh[2], rBl[2];

    auto load_regs = [&](int k0) {
#pragma unroll
        for (int i = 0; i < 2; i++) {
            int idx = tid + i * 256;
            int u4 = idx & 3, m = idx >> 2;
            size_t aoff = (size_t)(m0 + m) * K + k0 + u4 * 8;
            size_t boff = (size_t)(n0 + m) * K + k0 + u4 * 8;
            rAh[i] = *reinterpret_cast<const uint4*>(Ahi + aoff);
            rAl[i] = *reinterpret_cast<const uint4*>(Alo + aoff);
            rBh[i] = *reinterpret_cast<const uint4*>(Bhi + boff);
            rBl[i] = *reinterpret_cast<const uint4*>(Blo + boff);
        }
    };

    auto store_smem = [&]() {
#pragma unroll
        for (int i = 0; i < 2; i++) {
            int idx = tid + i * 256;
            int u4 = idx & 3, m = idx >> 2;
            *reinterpret_cast<uint4*>(&As[m * STR2 + u4 * 4]) = rAh[i];
            *reinterpret_cast<uint4*>(&As[TILE2 + m * STR2 + u4 * 4]) = rAl[i];
            *reinterpret_cast<uint4*>(&Bs[m * STR2 + u4 * 4]) = rBh[i];
            *reinterpret_cast<uint4*>(&Bs[TILE2 + m * STR2 + u4 * 4]) = rBl[i];
        }
    };

    load_regs(0);
    for (int k0 = 0; k0 < K; k0 += KT) {
        store_smem();
        __syncthreads();
        if (k0 + KT < K) load_regs(k0 + KT);

#pragma unroll
        for (int ks = 0; ks < 2; ks++) {
            const int kb = ks * 8 + c;
            uint32_t af[4][4], bf[4][2];
#pragma unroll
            for (int mi = 0; mi < 4; mi++) {
                const int mr = wm + mi * 16 + g;
                af[mi][0] = As[mr * STR2 + kb];
                af[mi][1] = As[(mr + 8) * STR2 + kb];
                af[mi][2] = As[mr * STR2 + kb + 4];
                af[mi][3] = As[(mr + 8) * STR2 + kb + 4];
            }
#pragma unroll
            for (int ni = 0; ni < 4; ni++) {
                const int nr = wn + ni * 8 + g;
                bf[ni][0] = Bs[nr * STR2 + kb];
                bf[ni][1] = Bs[nr * STR2 + kb + 4];
            }
#pragma unroll
            for (int mi = 0; mi < 4; mi++)
#pragma unroll
                for (int ni = 0; ni < 4; ni++)
                    mma_f16(acc[mi][ni], af[mi][0], af[mi][1], af[mi][2], af[mi][3],
                            bf[ni][0], bf[ni][1]);
            uint32_t afl[4][4], bfl[4][2];
#pragma unroll
            for (int mi = 0; mi < 4; mi++) {
                const int mr = wm + mi * 16 + g;
                afl[mi][0] = As[TILE2 + mr * STR2 + kb];
                afl[mi][1] = As[TILE2 + (mr + 8) * STR2 + kb];
                afl[mi][2] = As[TILE2 + mr * STR2 + kb + 4];
                afl[mi][3] = As[TILE2 + (mr + 8) * STR2 + kb + 4];
            }
#pragma unroll
            for (int ni = 0; ni < 4; ni++) {
                const int nr = wn + ni * 8 + g;
                bfl[ni][0] = Bs[TILE2 + nr * STR2 + kb];
                bfl[ni][1] = Bs[TILE2 + nr * STR2 + kb + 4];
            }
#pragma unroll
            for (int mi = 0; mi < 4; mi++)
#pragma unroll
                for (int ni = 0; ni < 4; ni++) {
                    mma_f16(acc[mi][ni], af[mi][0], af[mi][1], af[mi][2], af[mi][3],
                            bfl[ni][0], bfl[ni][1]);
                    mma_f16(acc[mi][ni], afl[mi][0], afl[mi][1], afl[mi][2], afl[mi][3],
                            bf[ni][0], bf[ni][1]);
                }
        }
        __syncthreads();
    }

#pragma unroll
    for (int mi = 0; mi < 4; mi++)
#pragma unroll
        for (int ni = 0; ni < 4; ni++) {
            const int row = m0 + wm + mi * 16 + g;
            const int col = n0 + wn + ni * 8 + 2 * c;
#pragma unroll
            for (int hf = 0; hf < 2; hf++) {
                const int rr2 = row + hf * 8;
                C[(size_t)rr2 * N + col]     = acc[mi][ni][hf * 2 + 0];
                C[(size_t)rr2 * N + col + 1] = acc[mi][ni][hf * 2 + 1];
            }
        }
}

// ---------------------------------------------------------------------------
// Fused flash attention (fp16 in/out): o = softmax(QK^T/8) @ V per (b,h).
// (R11-proven version: single K buffer, sync loads, 37 KB smem.)
// ---------------------------------------------------------------------------
__global__ void __launch_bounds__(128) flash_attn_tc(
    const __half* __restrict__ qkv, __half* __restrict__ o)
{
    constexpr int QSTR = 36;
    constexpr int VSTR = 38;
    __shared__ uint32_t Qs[64 * QSTR];
    __shared__ uint32_t Ks[64 * QSTR];
    __shared__ uint32_t Ps[64 * QSTR];
    __shared__ uint32_t Vs[64 * VSTR];

    const int qt = blockIdx.x, bh = blockIdx.y;
    const int b = bh >> 3, h = bh & 7;
    const int tid = threadIdx.x, lane = tid & 31, wid = tid >> 5;
    const int wm = wid * 16;
    const int g = lane >> 2, c = lane & 3;

#pragma unroll
    for (int i = 0; i < 4; i++) {
        int idx = tid + i * 128;
        int u4 = idx & 7, m = idx >> 3;
        uint4 u = *reinterpret_cast<const uint4*>(
            qkv + (size_t)(b * 512 + qt * 64 + m) * 1536 + h * 64 + u4 * 8);
        *reinterpret_cast<uint4*>(&Qs[m * QSTR + u4 * 4]) = u;
    }

    float m_r[2] = {-3.402823466e38f, -3.402823466e38f};
    float l_r[2] = {0.f, 0.f};
    float oacc[8][4];
#pragma unroll
    for (int nf = 0; nf < 8; nf++)
#pragma unroll
        for (int t = 0; t < 4; t++) oacc[nf][t] = 0.f;

    __half* Vsh = reinterpret_cast<__half*>(Vs);

    for (int kc = 0; kc < 8; kc++) {
#pragma unroll
        for (int i = 0; i < 4; i++) {
            int idx = tid + i * 128;
            int u4 = idx & 7, m = idx >> 3;
            const __half* base = qkv + (size_t)(b * 512 + kc * 64 + m) * 1536 + h * 64;
            uint4 ku = *reinterpret_cast<const uint4*>(base + 512 + u4 * 8);
            *reinterpret_cast<uint4*>(&Ks[m * QSTR + u4 * 4]) = ku;
            uint4 vu = *reinterpret_cast<const uint4*>(base + 1024 + u4 * 8);
            const __half2* vh = reinterpret_cast<const __half2*>(&vu);
#pragma unroll
            for (int j = 0; j < 4; j++) {
                __half2 p = vh[j];
                Vsh[(u4 * 8 + 2 * j + 0) * 76 + m] = __low2half(p);
                Vsh[(u4 * 8 + 2 * j + 1) * 76 + m] = __high2half(p);
            }
        }
        __syncthreads();

        float sacc[8][4];
#pragma unroll
        for (int nf = 0; nf < 8; nf++)
#pragma unroll
            for (int t = 0; t < 4; t++) sacc[nf][t] = 0.f;

#pragma unroll
        for (int ks = 0; ks < 4; ks++) {
            const int kb = ks * 8 + c;
            uint32_t a0 = Qs[(wm + g) * QSTR + kb];
            uint32_t a1 = Qs[(wm + g + 8) * QSTR + kb];
            uint32_t a2 = Qs[(wm + g) * QSTR + kb + 4];
            uint32_t a3 = Qs[(wm + g + 8) * QSTR + kb + 4];
#pragma unroll
            for (int nf = 0; nf < 8; nf++) {
                const int nr = nf * 8 + g;
                mma_f16(sacc[nf], a0, a1, a2, a3,
                        Ks[nr * QSTR + kb], Ks[nr * QSTR + kb + 4]);
            }
        }

        float mx0 = -3.402823466e38f, mx1 = -3.402823466e38f;
#pragma unroll
        for (int nf = 0; nf < 8; nf++) {
#pragma unroll
            for (int t = 0; t < 4; t++) sacc[nf][t] *= 0.125f;
            mx0 = fmaxf(mx0, fmaxf(sacc[nf][0], sacc[nf][1]));
            mx1 = fmaxf(mx1, fmaxf(sacc[nf][2], sacc[nf][3]));
        }
        mx0 = fmaxf(mx0, __shfl_xor_sync(0xffffffffu, mx0, 1));
        mx0 = fmaxf(mx0, __shfl_xor_sync(0xffffffffu, mx0, 2));
        mx1 = fmaxf(mx1, __shfl_xor_sync(0xffffffffu, mx1, 1));
        mx1 = fmaxf(mx1, __shfl_xor_sync(0xffffffffu, mx1, 2));

        const float mn0 = fmaxf(m_r[0], mx0);
        const float mn1 = fmaxf(m_r[1], mx1);
        const float f0 = expf(m_r[0] - mn0);
        const float f1 = expf(m_r[1] - mn1);

        float s0 = 0.f, s1 = 0.f;
#pragma unroll
        for (int nf = 0; nf < 8; nf++) {
            float p0 = expf(sacc[nf][0] - mn0);
            float p1 = expf(sacc[nf][1] - mn0);
            float p2 = expf(sacc[nf][2] - mn1);
            float p3 = expf(sacc[nf][3] - mn1);
            s0 += p0 + p1;
            s1 += p2 + p3;
            Ps[(wm + g) * QSTR + nf * 4 + c]     = pack_half2(p0, p1);
            Ps[(wm + g + 8) * QSTR + nf * 4 + c] = pack_half2(p2, p3);
            oacc[nf][0] *= f0; oacc[nf][1] *= f0;
            oacc[nf][2] *= f1; oacc[nf][3] *= f1;
        }
        s0 += __shfl_xor_sync(0xffffffffu, s0, 1);
        s0 += __shfl_xor_sync(0xffffffffu, s0, 2);
        s1 += __shfl_xor_sync(0xffffffffu, s1, 1);
        s1 += __shfl_xor_sync(0xffffffffu, s1, 2);
        l_r[0] = l_r[0] * f0 + s0;
        l_r[1] = l_r[1] * f1 + s1;
        m_r[0] = mn0; m_r[1] = mn1;
        __syncwarp();

#pragma unroll
        for (int ks = 0; ks < 4; ks++) {
            const int kb = ks * 8 + c;
            uint32_t a0 = Ps[(wm + g) * QSTR + kb];
            uint32_t a1 = Ps[(wm + g + 8) * QSTR + kb];
            uint32_t a2 = Ps[(wm + g) * QSTR + kb + 4];
            uint32_t a3 = Ps[(wm + g + 8) * QSTR + kb + 4];
#pragma unroll
            for (int nf = 0; nf < 8; nf++) {
                const int nr = nf * 8 + g;
                mma_f16(oacc[nf], a0, a1, a2, a3,
                        Vs[nr * VSTR + kb], Vs[nr * VSTR + kb + 4]);
            }
        }
        __syncthreads();
    }

    const float inv0 = 1.f / l_r[0];
    const float inv1 = 1.f / l_r[1];
#pragma unroll
    for (int nf = 0; nf < 8; nf++) {
        const int row = qt * 64 + wm + g;
        const int col = nf * 8 + 2 * c;
        __half* ob = o + (size_t)(b * 512 + row) * 512 + h * 64 + col;
        *reinterpret_cast<uint32_t*>(ob) =
            pack_half2(oacc[nf][0] * inv0, oacc[nf][1] * inv0);
        *reinterpret_cast<uint32_t*>(ob + 8 * 512) =
            pack_half2(oacc[nf][2] * inv1, oacc[nf][3] * inv1);
    }
}

// ---------------------------------------------------------------------------
// Row softmax (row length 1024) with dual fp32 + fp16 output
// ---------------------------------------------------------------------------
__global__ void __launch_bounds__(256) softmax_dual_kernel(
    float* __restrict__ data, __half* __restrict__ out16)
{
    float* row = data + (size_t)blockIdx.x * 1024;
    __half* hrow = out16 + (size_t)blockIdx.x * 1024;
    const int tid = threadIdx.x;
    float x[4];
    float mx = -3.402823466e38f;
#pragma unroll
    for (int c = 0; c < 4; c++) {
        x[c] = row[tid + 256 * c];
        mx = fmaxf(mx, x[c]);
    }
    __shared__ float sh[8];
#pragma unroll
    for (int o = 16; o; o >>= 1) mx = fmaxf(mx, __shfl_xor_sync(0xffffffffu, mx, o));
    if ((tid & 31) == 0) sh[tid >> 5] = mx;
    __syncthreads();
    mx = sh[0];
#pragma unroll
    for (int w = 1; w < 8; w++) mx = fmaxf(mx, sh[w]);

    float s = 0.f;
#pragma unroll
    for (int c = 0; c < 4; c++) { x[c] = expf(x[c] - mx); s += x[c]; }
    __syncthreads();
#pragma unroll
    for (int o = 16; o; o >>= 1) s += __shfl_xor_sync(0xffffffffu, s, o);
    if ((tid & 31) == 0) sh[tid >> 5] = s;
    __syncthreads();
    float tot = sh[0];
#pragma unroll
    for (int w = 1; w < 8; w++) tot += sh[w];
    float inv = 1.f / tot;
#pragma unroll
    for (int c = 0; c < 4; c++) {
        float r = x[c] * inv;
        row[tid + 256 * c] = r;
        hrow[tid + 256 * c] = __float2half_rn(r);
    }
}

// ---------------------------------------------------------------------------
// out = LayerNorm(X) * g + b ; fp32 + fp16 (+optional fp16 low part)
// ---------------------------------------------------------------------------
template <bool LO>
__global__ void __launch_bounds__(256) ln_kernel(
    const float* __restrict__ X,
    const float* __restrict__ gam, const float* __restrict__ bet,
    float* __restrict__ out, __half* __restrict__ out16,
    __half* __restrict__ out16lo)
{
    const size_t row = blockIdx.x;
    const float* xr = X + row * 512;
    const int tid = threadIdx.x;
    float t0 = xr[tid];
    float t1 = xr[tid + 256];

    __shared__ float sh[8];
    float s = t0 + t1;
#pragma unroll
    for (int o = 16; o; o >>= 1) s += __shfl_xor_sync(0xffffffffu, s, o);
    if ((tid & 31) == 0) sh[tid >> 5] = s;
    __syncthreads();
    float tot = sh[0];
#pragma unroll
    for (int w = 1; w < 8; w++) tot += sh[w];
    float mean = tot * (1.f / 512.f);
    float d0 = t0 - mean, d1 = t1 - mean;
    float q = d0 * d0 + d1 * d1;
    __syncthreads();
#pragma unroll
    for (int o = 16; o; o >>= 1) q += __shfl_xor_sync(0xffffffffu, q, o);
    if ((tid & 31) == 0) sh[tid >> 5] = q;
    __syncthreads();
    float vtot = sh[0];
#pragma unroll
    for (int w = 1; w < 8; w++) vtot += sh[w];
    float inv = rsqrtf(vtot * (1.f / 512.f) + 1e-5f);
    float r0 = d0 * inv * gam[tid] + bet[tid];
    float r1 = d1 * inv * gam[tid + 256] + bet[tid + 256];
    float* orow = out + row * 512;
    orow[tid] = r0;
    orow[tid + 256] = r1;
    __half* hrow = out16 + row * 512;
    __half h0 = __float2half_rn(r0);
    __half h1 = __float2half_rn(r1);
    hrow[tid] = h0;
    hrow[tid + 256] = h1;
    if (LO) {
        __half* lrow = out16lo + row * 512;
        lrow[tid]       = __float2half_rn(r0 - __half2float(h0));
        lrow[tid + 256] = __float2half_rn(r1 - __half2float(h1));
    }
}

// ---------------------------------------------------------------------------
// Graph branch (exact fp32, tiny cost)
// ---------------------------------------------------------------------------
__global__ void feat_fn_kernel(const float* __restrict__ x, float* __restrict__ fn)
{
    const int b = blockIdx.x, i = threadIdx.x;
    const float* xp = x + (size_t)b * 32768 + i;
    float s = 0.f;
    for (int t = 0; t < 512; t++) s += xp[(size_t)t * 64];
    float f = s * (1.f / 512.f);
    __shared__ float sh[64];
    sh[i] = f * f;
    __syncthreads();
    for (int o = 32; o; o >>= 1) {
        if (i < o) sh[i] += sh[i + o];
        __syncthreads();
    }
    float norm = sqrtf(sh[0]);
    fn[b * 64 + i] = f / fmaxf(norm, 1e-12f);
}

__global__ void graph_adj_kernel(const float* __restrict__ fn, float* __restrict__ An)
{
    const int b = blockIdx.x, i = threadIdx.x;
    __shared__ float f[64];
    __shared__ unsigned char A[64][64];
    f[i] = fn[b * 64 + i];
    for (int j = 0; j < 64; j++) A[i][j] = 0;
    __syncthreads();
    const float fi = f[i];
    float bv0 = -3.402823466e38f, bv1 = bv0, bv2 = bv0, bv3 = bv0;
    int i0 = 0, i1 = 0, i2 = 0, i3 = 0;
    for (int j = 0; j < 64; j++) {
        float v = fi * f[j];
        if (v > bv3) {
            if (v > bv0)      { bv3 = bv2; i3 = i2; bv2 = bv1; i2 = i1; bv1 = bv0; i1 = i0; bv0 = v; i0 = j; }
            else if (v > bv1) { bv3 = bv2; i3 = i2; bv2 = bv1; i2 = i1; bv1 = v; i1 = j; }
            else if (v > bv2) { bv3 = bv2; i3 = i2; bv2 = v; i2 = j; }
            else              { bv3 = v; i3 = j; }
        }
    }
    A[i][i1] = 1; A[i][i2] = 1; A[i][i3] = 1;
    __syncthreads();
    float deg = 0.f;
    for (int j = 0; j < 64; j++) {
        bool a = (j == i) || A[i][j] || A[j][i];
        deg += a ? 1.f : 0.f;
    }
    float inv = 1.f / deg;
    float* row = An + (size_t)b * 4096 + i * 64;
    for (int j = 0; j < 64; j++) {
        bool a = (j == i) || A[i][j] || A[j][i];
        row[j] = a ? inv : 0.f;
    }
}

__global__ void __launch_bounds__(256) gcn_gemm1_kernel(
    const float* __restrict__ x, const float* __restrict__ w,
    const float* __restrict__ bias, float* __restrict__ out)
{
    const int dt = blockIdx.x, b = blockIdx.y;
    __shared__ float Xs[16][64];
    __shared__ float Ws[64][17];
    const int tid = threadIdx.x, tx = tid & 15, ty = tid >> 4;
    float acc[4][4];
#pragma unroll
    for (int i = 0; i < 4; i++)
#pragma unroll
        for (int j = 0; j < 4; j++) acc[i][j] = 0.f;

    for (int k0 = 0; k0 < 512; k0 += 16) {
        {
            int kk = tid >> 4, f4 = (tid & 15) << 2;
            float4 v = *reinterpret_cast<const float4*>(
                x + (size_t)b * 32768 + (size_t)(k0 + kk) * 64 + f4);
            *reinterpret_cast<float4*>(&Xs[kk][f4]) = v;
            int dd = tid >> 2, k4 = (tid & 3) << 2;
            float4 w4 = *reinterpret_cast<const float4*>(
                w + (size_t)(dt * 64 + dd) * 512 + k0 + k4);
            Ws[dd][k4 + 0] = w4.x; Ws[dd][k4 + 1] = w4.y;
            Ws[dd][k4 + 2] = w4.z; Ws[dd][k4 + 3] = w4.w;
        }
        __syncthreads();
#pragma unroll
        for (int kk = 0; kk < 16; kk++) {
            float a[4], bb[4];
#pragma unroll
            for (int i = 0; i < 4; i++) a[i] = Xs[kk][ty + 16 * i];
#pragma unroll
            for (int j = 0; j < 4; j++) bb[j] = Ws[tx + 16 * j][kk];
#pragma unroll
            for (int i = 0; i < 4; i++)
#pragma unroll
                for (int j = 0; j < 4; j++)
                    acc[i][j] = fmaf(a[i], bb[j], acc[i][j]);
        }
        __syncthreads();
    }
#pragma unroll
    for (int i = 0; i < 4; i++)
#pragma unroll
        for (int j = 0; j < 4; j++) {
            int dd = dt * 64 + tx + 16 * j;
            out[(size_t)b * 32768 + (size_t)(ty + 16 * i) * 512 + dd] =
                acc[i][j] + bias[dd];
        }
}

__global__ void __launch_bounds__(256) gcn_gemm2_kernel(
    const float* __restrict__ Ain, const float* __restrict__ w,
    const float* __restrict__ bias, float* __restrict__ out)
{
    const int st = blockIdx.x, b = blockIdx.y;
    __shared__ float As[64][17];
    __shared__ float Ws[64][17];
    const int tid = threadIdx.x, tx = tid & 15, ty = tid >> 4;
    const int rr = tid >> 2, k4 = (tid & 3) << 2;
    float acc[4][4];
#pragma unroll
    for (int i = 0; i < 4; i++)
#pragma unroll
        for (int j = 0; j < 4; j++) acc[i][j] = 0.f;

    for (int k0 = 0; k0 < 512; k0 += 16) {
        float4 a4 = *reinterpret_cast<const float4*>(
            Ain + (size_t)b * 32768 + (size_t)rr * 512 + k0 + k4);
        As[rr][k4 + 0] = a4.x; As[rr][k4 + 1] = a4.y;
        As[rr][k4 + 2] = a4.z; As[rr][k4 + 3] = a4.w;
        float4 w4 = *reinterpret_cast<const float4*>(
            w + (size_t)(st * 64 + rr) * 512 + k0 + k4);
        Ws[rr][k4 + 0] = w4.x; Ws[rr][k4 + 1] = w4.y;
        Ws[rr][k4 + 2] = w4.z; Ws[rr][k4 + 3] = w4.w;
        __syncthreads();
#pragma unroll
        for (int kk = 0; kk < 16; kk++) {
            float a[4], bb[4];
#pragma unroll
            for (int i = 0; i < 4; i++) a[i] = As[ty + 16 * i][kk];
#pragma unroll
            for (int j = 0; j < 4; j++) bb[j] = Ws[tx + 16 * j][kk];
#pragma unroll
            for (int i = 0; i < 4; i++)
#pragma unroll
                for (int j = 0; j < 4; j++)
                    acc[i][j] = fmaf(a[i], bb[j], acc[i][j]);
        }
        __syncthreads();
    }
#pragma unroll
    for (int i = 0; i < 4; i++)
#pragma unroll
        for (int j = 0; j < 4; j++) {
            int ss = st * 64 + tx + 16 * j;
            out[(size_t)b * 32768 + (size_t)(ty + 16 * i) * 512 + ss] =
                acc[i][j] + bias[ss];
        }
}

template <bool RELU, bool TRANSOUT>
__global__ void __launch_bounds__(256) an_mult_kernel(
    const float* __restrict__ An, const float* __restrict__ in,
    float* __restrict__ out)
{
    const int dt = blockIdx.x, b = blockIdx.y;
    __shared__ float As[64][65];
    __shared__ float Ins[64][64];
    const int tid = threadIdx.x, tx = tid & 15, ty = tid >> 4;

    for (int t = tid; t < 4096; t += 256)
        As[t >> 6][t & 63] = An[(size_t)b * 4096 + t];
#pragma unroll
    for (int hh = 0; hh < 4; hh++) {
        int idx4 = tid + hh * 256;
        int gg = idx4 >> 4, c4 = (idx4 & 15) << 2;
        float4 v = *reinterpret_cast<const float4*>(
            in + (size_t)b * 32768 + (size_t)gg * 512 + dt * 64 + c4);
        *reinterpret_cast<float4*>(&Ins[gg][c4]) = v;
    }
    __syncthreads();

    float acc[4][4];
#pragma unroll
    for (int i = 0; i < 4; i++)
#pragma unroll
        for (int j = 0; j < 4; j++) acc[i][j] = 0.f;

#pragma unroll 8
    for (int kk = 0; kk < 64; kk++) {
        float a[4], bb[4];
#pragma unroll
        for (int i = 0; i < 4; i++) a[i] = As[ty + 16 * i][kk];
#pragma unroll
        for (int j = 0; j < 4; j++) bb[j] = Ins[kk][tx + 16 * j];
#pragma unroll
        for (int i = 0; i < 4; i++)
#pragma unroll
            for (int j = 0; j < 4; j++)
                acc[i][j] = fmaf(a[i], bb[j], acc[i][j]);
    }

#pragma unroll
    for (int i = 0; i < 4; i++)
#pragma unroll
        for (int j = 0; j < 4; j++) {
            int ff = ty + 16 * i;
            int dd = dt * 64 + tx + 16 * j;
            float v = acc[i][j];
            if (RELU) v = fmaxf(v, 0.f);
            if (!TRANSOUT)
                out[(size_t)b * 32768 + (size_t)ff * 512 + dd] = v;
            else
                out[(size_t)b * 32768 + (size_t)dd * 64 + ff] = v;
        }
}

// ---------------------------------------------------------------------------
// Host orchestration
// ---------------------------------------------------------------------------
extern "C" void kernel_launch(void* const* d_in, const int* in_sizes, int n_in,
                              void* d_out, int out_size)
{
    const float* x      = (const float*)d_in[0];
    const float* W_in   = (const float*)d_in[1];
    const float* b_in   = (const float*)d_in[2];
    const float* qkv_w  = (const float*)d_in[3];
    const float* qkv_b  = (const float*)d_in[4];
    const float* out_w  = (const float*)d_in[5];
    const float* out_b  = (const float*)d_in[6];
    const float* ln1_g  = (const float*)d_in[7];
    const float* ln1_b  = (const float*)d_in[8];
    const float* ln2_g  = (const float*)d_in[9];
    const float* ln2_b  = (const float*)d_in[10];
    const float* ff1_w  = (const float*)d_in[11];
    const float* ff1_b  = (const float*)d_in[12];
    const float* ff2_w  = (const float*)d_in[13];
    const float* ff2_b  = (const float*)d_in[14];
    const float* memory = (const float*)d_in[15];
    const float* fc1_w  = (const float*)d_in[16];
    const float* fc1_b  = (const float*)d_in[17];
    const float* fc2_w  = (const float*)d_in[18];
    const float* fc2_b  = (const float*)d_in[19];
    const float* gc1_w  = (const float*)d_in[20];
    const float* gc1_b  = (const float*)d_in[21];
    const float* gc2_w  = (const float*)d_in[22];
    const float* gc2_b  = (const float*)d_in[23];

    float* out    = (float*)d_out;
    float* t_out  = out;                       // (32,512,64)
    float* gout_p = out + 1048576;             // (32,512,64)
    float* attn_p = out + 2097152;             // (32,512,1024)

    static float *p_pe = nullptr, *p_h, *p_tmp, *p_fn, *p_An, *p_gt1, *p_gh1;
    static __half *p_h16, *p_h16lo, *p_qkv, *p_o, *p_ff, *p_mlo, *p_memT, *p_wh;
    if (!p_pe) {
        cudaGetSymbolAddress((void**)&p_pe,    g_pe);
        cudaGetSymbolAddress((void**)&p_h,     g_h);
        cudaGetSymbolAddress((void**)&p_h16,   g_h16);
        cudaGetSymbolAddress((void**)&p_h16lo, g_h16lo);
        cudaGetSymbolAddress((void**)&p_tmp,   g_tmp);
        cudaGetSymbolAddress((void**)&p_qkv,   g_qkv);
        cudaGetSymbolAddress((void**)&p_o,     g_o);
        cudaGetSymbolAddress((void**)&p_ff,    g_ff);
        cudaGetSymbolAddress((void**)&p_mlo,   g_mlo);
        cudaGetSymbolAddress((void**)&p_memT,  g_memT);
        cudaGetSymbolAddress((void**)&p_fn,    g_fn);
        cudaGetSymbolAddress((void**)&p_An,    g_An);
        cudaGetSymbolAddress((void**)&p_gt1,   g_gt1);
        cudaGetSymbolAddress((void**)&p_gh1,   g_gh1);
        cudaGetSymbolAddress((void**)&p_wh,    g_wh);
    }

    const int M = 16384;

    // ---- pre-convert weights to fp16 (graph-captured) ----
    auto conv = [&](const float* src, __half* dst, int n) {
        convert_w_kernel<<<(n / 4 + 255) / 256, 256>>>(src, dst, n / 4);
    };
    conv(qkv_w,  p_wh + WH_QKV, 3 * 1536 * 512);
    conv(out_w,  p_wh + WH_OUT, 3 * 512 * 512);
    conv(ff1_w,  p_wh + WH_FF1, 3 * 2048 * 512);
    conv(ff2_w,  p_wh + WH_FF2, 3 * 512 * 2048);
    conv(memory, p_wh + WH_MEM, 1024 * 512);
    conv(fc1_w,  p_wh + WH_FC1, 512 * 1024);
    conv(fc2_w,  p_wh + WH_FC2, 64 * 512);
    conv(W_in,   p_wh + WH_WIN, 512 * 64);
    make_lo_kernel<<<(1024 * 512 / 4 + 255) / 256, 256>>>(
        memory, p_wh + WH_MEM, p_mlo, 1024 * 512 / 4);
    transpose_mem_kernel<<<dim3(32, 16), dim3(32, 32)>>>(p_wh + WH_MEM, p_memT);

    pe_kernel<<<(512 * 512 + 255) / 256, 256>>>(p_pe);

    // h = x @ W_in^T + b_in + pe (dual fp32+fp16 out, fp16 B register-staged)
    gemm_tc<true, 2, false, false, false, true, false, true>
        <<<dim3(4, 128), 256>>>(
        x, nullptr, p_wh + WH_WIN, b_in, p_pe, nullptr, p_h, p_h16, M, 512, 64);

    for (int l = 0; l < 3; l++) {
        // qkv (pure fp16, cp.async)
        gemm_tc<true, 0, false, true, true, true, true, false>
            <<<dim3(12, 128), 256>>>(
            p_h16, nullptr, p_wh + WH_QKV + (size_t)l * 1536 * 512,
            qkv_b + l * 1536, nullptr, nullptr, p_qkv, nullptr, M, 1536, 512);
        // fused attention
        flash_attn_tc<<<dim3(8, 256), 128>>>(p_qkv, p_o);
        // out projection + residual (pure fp16 in, cp.async, fp32 out)
        gemm_tc<true, 3, false, true, false, true, true, false>
            <<<dim3(4, 128), 256>>>(
            p_o, nullptr, p_wh + WH_OUT + (size_t)l * 512 * 512,
            out_b + l * 512, nullptr, p_h, p_tmp, nullptr, M, 512, 512);
        ln_kernel<false><<<16384, 256>>>(p_tmp, ln1_g + l * 512, ln1_b + l * 512,
                                         p_h, p_h16, nullptr);
        // feed-forward (pure fp16, cp.async)
        gemm_tc<true, 1, false, true, true, true, true, false>
            <<<dim3(16, 128), 256>>>(
            p_h16, nullptr, p_wh + WH_FF1 + (size_t)l * 2048 * 512,
            ff1_b + l * 2048, nullptr, nullptr, p_ff, nullptr, M, 2048, 512);
        gemm_tc<true, 3, false, true, false, true, true, false>
            <<<dim3(4, 128), 256>>>(
            p_ff, nullptr, p_wh + WH_FF2 + (size_t)l * 512 * 2048,
            ff2_b + l * 512, nullptr, p_h, p_tmp, nullptr, M, 512, 2048);
        if (l == 2)
            ln_kernel<true><<<16384, 256>>>(p_tmp, ln2_g + l * 512,
                                            ln2_b + l * 512, p_h, p_h16, p_h16lo);
        else
            ln_kernel<false><<<16384, 256>>>(p_tmp, ln2_g + l * 512,
                                             ln2_b + l * 512, p_h, p_h16, nullptr);
    }

    // sims: pre-split fp16 operands, 3-pass exact-order split GEMM
    sims_split_tc<<<dim3(8, 128), 256>>>(
        p_h16, p_h16lo, p_wh + WH_MEM, p_mlo, attn_p, M, 1024, 512);
    // softmax with dual fp32 + fp16 output (attn16 in g_ff scratch)
    softmax_dual_kernel<<<16384, 256>>>(attn_p, p_ff);
    // upd = attn16 @ memT^T (pure fp16, cp.async), fp16 out
    gemm_tc<true, 0, false, true, true, true, true, false>
        <<<dim3(4, 128), 256>>>(
        p_ff, nullptr, p_memT, nullptr, nullptr, nullptr,
        p_o, nullptr, M, 512, 1024);
    // fc1 over fp16 concat [h16 | upd16] (cp.async), fp16 out into qkv buffer
    gemm_tc<true, 1, true, true, true, true, true, false>
        <<<dim3(4, 128), 256>>>(
        p_h16, p_o, p_wh + WH_FC1, fc1_b, nullptr, nullptr,
        p_qkv, nullptr, M, 512, 1024);
    // fc2 (pure fp16 in, cp.async, fp32 out to t_out)
    gemm_tc<true, 0, false, true, false, true, true, false>
        <<<dim3(1, 128), 256>>>(
        p_qkv, nullptr, p_wh + WH_FC2, fc2_b, nullptr, nullptr,
        t_out, nullptr, M, 64, 512);

    // graph branch (exact fp32)
    feat_fn_kernel<<<32, 64>>>(x, p_fn);
    graph_adj_kernel<<<32, 64>>>(p_fn, p_An);
    gcn_gemm1_kernel<<<dim3(8, 32), 256>>>(x, gc1_w, gc1_b, p_gt1);
    an_mult_kernel<true, false><<<dim3(8, 32), 256>>>(p_An, p_gt1, p_gh1);
    gcn_gemm2_kernel<<<dim3(8, 32), 256>>>(p_gh1, gc2_w, gc2_b, p_gt1);
    an_mult_kernel<false, true><<<dim3(8, 32), 256>>>(p_An, p_gt1, gout_p);

    (void)in_sizes; (void)n_in; (void)out_size;
}

// round 15
// speedup vs baseline: 1.0780x; 1.0319x over previous
#include <cuda_runtime.h>
#include <cuda_fp16.h>
#include <math.h>
#include <stdint.h>

// ---------------------------------------------------------------------------
// Problem constants
//  B=32, S=512, F_IN=64, D=512, DFF=2048, MEM=1024, L=3, H=8, dh=64
//  rows = B*S = 16384
// ---------------------------------------------------------------------------

// ------------------------- static scratch buffers --------------------------
__device__ float  g_pe[512 * 512];             // 1 MB
__device__ float  g_h[16384 * 512];            // 32 MB (fp32 residual stream)
__device__ __half g_h16[16384 * 512];          // 16 MB (fp16 mirror of h)
__device__ float  g_tmp[16384 * 512];          // 32 MB
__device__ __half g_qkv[16384 * 1536];         // 48 MB (reused as fc1 out)
__device__ __half g_o[16384 * 512];            // 16 MB (reused as upd16)
__device__ __half g_ff[16384 * 2048];          // 64 MB (reused as attn16)
__device__ __half g_mlo[1024 * 512];           // 1 MB (fp16 low part of memory)
__device__ __half g_memT[512 * 1024];          // 1 MB (fp16 memory transposed)
__device__ float  g_fn[32 * 64];
__device__ float  g_An[32 * 64 * 64];
__device__ float  g_gt1[32 * 64 * 512];        // 4 MB
__device__ float  g_gh1[32 * 64 * 512];        // 4 MB
__device__ __half g_wh[10551296];              // 21 MB fp16 weights

// fp16 weight buffer offsets
#define WH_QKV   0                               // 3*1536*512 = 2359296
#define WH_OUT   2359296                         // 3*512*512  = 786432
#define WH_FF1   3145728                         // 3*2048*512 = 3145728
#define WH_FF2   6291456                         // 3*512*2048 = 3145728
#define WH_MEM   9437184                         // 1024*512   = 524288
#define WH_FC1   9961472                         // 512*1024   = 524288
#define WH_FC2   10485760                        // 64*512     = 32768
#define WH_WIN   10518528                        // 512*64     = 32768

// ---------------------------------------------------------------------------
// fp16 / async helpers
// ---------------------------------------------------------------------------
__device__ __forceinline__ uint32_t pack_half2(float a, float b) {
    __half2 h = __floats2half2_rn(a, b);
    return *reinterpret_cast<uint32_t*>(&h);
}

__device__ __forceinline__ void mma_f16(float c[4],
    uint32_t a0, uint32_t a1, uint32_t a2, uint32_t a3,
    uint32_t b0, uint32_t b1)
{
    asm volatile(
        "mma.sync.aligned.m16n8k16.row.col.f32.f16.f16.f32 "
        "{%0,%1,%2,%3}, {%4,%5,%6,%7}, {%8,%9}, {%0,%1,%2,%3};"
        : "+f"(c[0]), "+f"(c[1]), "+f"(c[2]), "+f"(c[3])
        : "r"(a0), "r"(a1), "r"(a2), "r"(a3), "r"(b0), "r"(b1));
}

__device__ __forceinline__ void cp_async16(void* smem_ptr, const void* gptr) {
    uint32_t a = (uint32_t)__cvta_generic_to_shared(smem_ptr);
    asm volatile("cp.async.cg.shared.global [%0], [%1], 16;" :: "r"(a), "l"(gptr));
}
#define CP_COMMIT() asm volatile("cp.async.commit_group;")
#define CP_WAIT0()  asm volatile("cp.async.wait_group 0;")

// ---------------------------------------------------------------------------
// Weight pre-conversion: fp32 -> fp16 (rn)
// ---------------------------------------------------------------------------
__global__ void convert_w_kernel(const float* __restrict__ src,
                                 __half* __restrict__ dst, int n4)
{
    int i = blockIdx.x * 256 + threadIdx.x;
    if (i >= n4) return;
    float4 v = *reinterpret_cast<const float4*>(src + i * 4);
    uint2 u;
    u.x = pack_half2(v.x, v.y);
    u.y = pack_half2(v.z, v.w);
    *reinterpret_cast<uint2*>(dst + i * 4) = u;
}

// lo = fp16(src - fp32(hi))  (hi already = fp16_rn(src))
__global__ void make_lo_kernel(const float* __restrict__ src,
                               const __half* __restrict__ hi,
                               __half* __restrict__ lo, int n4)
{
    int i = blockIdx.x * 256 + threadIdx.x;
    if (i >= n4) return;
    float4 v = *reinterpret_cast<const float4*>(src + i * 4);
    uint2 hu = *reinterpret_cast<const uint2*>(hi + i * 4);
    __half2 h0 = *reinterpret_cast<__half2*>(&hu.x);
    __half2 h1 = *reinterpret_cast<__half2*>(&hu.y);
    uint2 lu;
    lu.x = pack_half2(v.x - __low2float(h0), v.y - __high2float(h0));
    lu.y = pack_half2(v.z - __low2float(h1), v.w - __high2float(h1));
    *reinterpret_cast<uint2*>(lo + i * 4) = lu;
}

// memT[d][m] = wh_mem[m][d]  (fp16 -> fp16 transpose, 1024x512 -> 512x1024)
__global__ void transpose_mem_kernel(const __half* __restrict__ src,
                                     __half* __restrict__ dst)
{
    __shared__ __half s[32][33];
    const int m0 = blockIdx.x * 32, d0 = blockIdx.y * 32;
    const int tx = threadIdx.x, ty = threadIdx.y;
    s[ty][tx] = src[(size_t)(m0 + ty) * 512 + d0 + tx];
    __syncthreads();
    dst[(size_t)(d0 + ty) * 1024 + m0 + tx] = s[tx][ty];
}

// ---------------------------------------------------------------------------
// Positional encoding (match numpy float64 -> float32)
// ---------------------------------------------------------------------------
__global__ void pe_kernel(float* __restrict__ pe) {
    int i = blockIdx.x * 256 + threadIdx.x;
    if (i >= 512 * 512) return;
    int s = i >> 9, d = i & 511;
    int t2 = d & ~1;
    double div = exp((double)t2 * (-9.210340371976184 / 512.0)); // ln(10000)
    double a = (double)s * div;
    pe[i] = (float)((d & 1) ? cos(a) : sin(a));
}

// ---------------------------------------------------------------------------
// Tensor-core GEMM (fp16 mma, fp32 accumulate).
//  C[M,N] = A[M,K] * op(B) + bias (+epilogue)
//   TRANSB : B is (N,K) row-major -> C = A @ B^T ; false: B (K,N)
//   CATAB  : A logical [M,1024] = concat(A[:,:512], A2[:,:512]) (fp16 srcs)
//   AHALF  : A is __half          OHALF : C written as __half
//   BHALF  : B is __half          CPA   : cp.async double-buffered mainloop
//   ODUAL  : write C fp32 AND C2 fp16
// Block tile 128x128, 256 threads (8 warps = 2m x 4n of 64x32 warp tiles).
// EPI: 0 bias, 1 bias+relu, 2 bias+pos-encoding, 3 bias+residual
// ---------------------------------------------------------------------------
template <bool TRANSB, int EPI, bool CATAB, bool AHALF, bool OHALF,
          bool BHALF, bool CPA, bool ODUAL>
__global__ void __launch_bounds__(256) gemm_tc(
    const void* __restrict__ Avoid, const void* __restrict__ A2void,
    const void* __restrict__ Bvoid,
    const float* __restrict__ bias, const float* __restrict__ pe,
    const float* __restrict__ resid,
    void* __restrict__ Cvoid, void* __restrict__ C2void,
    int M, int N, int K)
{
    constexpr int KT    = 32;              // fp16 elems per K-tile
    constexpr int STR2  = 20;              // half2 (uint) stride: 16 + 4
    constexpr int TILE2 = 128 * STR2;
    constexpr int NSEG  = CPA ? 2 : 1;

    __shared__ uint32_t As[NSEG * TILE2];
    __shared__ uint32_t Bs[NSEG * TILE2];

    const float*  Af  = (const float*)Avoid;
    const __half* Ah  = (const __half*)Avoid;
    const __half* A2h = (const __half*)A2void;
    const float*  Bf  = (const float*)Bvoid;
    const __half* Bh  = (const __half*)Bvoid;
    float*  Cf  = (float*)Cvoid;
    __half* Ch  = (__half*)Cvoid;
    __half* Ch2 = (__half*)C2void;

    const int tid  = threadIdx.x;
    const int lane = tid & 31, wid = tid >> 5;
    const int wm = (wid >> 2) * 64, wn = (wid & 3) * 32;
    const int g = lane >> 2, c = lane & 3;
    const int m0 = blockIdx.y * 128, n0 = blockIdx.x * 128;

    float acc[4][4][4];
#pragma unroll
    for (int i = 0; i < 4; i++)
#pragma unroll
        for (int j = 0; j < 4; j++)
#pragma unroll
            for (int t = 0; t < 4; t++) acc[i][j][t] = 0.f;

    // ---- MMA on one buffer ----
    auto mma_tile = [&](int buf) {
        const uint32_t* Asb = As + (CPA ? buf * TILE2 : 0);
        const uint32_t* Bsb = Bs + (CPA ? buf * TILE2 : 0);
#pragma unroll
        for (int ks = 0; ks < 2; ks++) {
            const int kb = ks * 8 + c;
            uint32_t af[4][4], bf[4][2];
#pragma unroll
            for (int mi = 0; mi < 4; mi++) {
                const int mr = wm + mi * 16 + g;
                af[mi][0] = Asb[mr * STR2 + kb];
                af[mi][1] = Asb[(mr + 8) * STR2 + kb];
                af[mi][2] = Asb[mr * STR2 + kb + 4];
                af[mi][3] = Asb[(mr + 8) * STR2 + kb + 4];
            }
#pragma unroll
            for (int ni = 0; ni < 4; ni++) {
                const int nr = wn + ni * 8 + g;
                bf[ni][0] = Bsb[nr * STR2 + kb];
                bf[ni][1] = Bsb[nr * STR2 + kb + 4];
            }
#pragma unroll
            for (int mi = 0; mi < 4; mi++)
#pragma unroll
                for (int ni = 0; ni < 4; ni++)
                    mma_f16(acc[mi][ni], af[mi][0], af[mi][1], af[mi][2], af[mi][3],
                            bf[ni][0], bf[ni][1]);
        }
    };

    if (CPA) {
        // ================= cp.async double-buffered mainloop =================
        auto issue_cp = [&](int k0, int buf) {
            uint32_t* Asb = As + buf * TILE2;
            uint32_t* Bsb = Bs + buf * TILE2;
#pragma unroll
            for (int i = 0; i < 2; i++) {
                int idx = tid + i * 256;
                int u4 = idx & 3, m = idx >> 2;
                const __half* Ap = Ah;
                int lda = K, kcol = k0 + u4 * 8;
                if (CATAB) {
                    lda = 512;
                    if (k0 >= 512) { Ap = A2h; kcol -= 512; }
                }
                cp_async16(&Asb[m * STR2 + u4 * 4],
                           Ap + (size_t)(m0 + m) * lda + kcol);
            }
#pragma unroll
            for (int i = 0; i < 2; i++) {
                int idx = tid + i * 256;
                int u4 = idx & 3, n = idx >> 2;
                if (n0 + n < N)
                    cp_async16(&Bsb[n * STR2 + u4 * 4],
                               Bh + (size_t)(n0 + n) * K + k0 + u4 * 8);
            }
        };

        issue_cp(0, 0);
        CP_COMMIT();
        int pb = 0;
        for (int k0 = 0; k0 < K; k0 += KT) {
            CP_WAIT0();
            __syncthreads();
            if (k0 + KT < K) {
                issue_cp(k0 + KT, pb ^ 1);
                CP_COMMIT();
            }
            mma_tile(pb);
            pb ^= 1;
        }
        __syncthreads();
    } else {
        // ============== register-staged single-buffer mainloop ==============
        float4 rA[4], rB[4];
        uint4  rAh[2], rBh[2];

        auto load_regs = [&](int k0) {
            if (AHALF) {
#pragma unroll
                for (int i = 0; i < 2; i++) {
                    int idx = tid + i * 256;
                    int u4 = idx & 3, m = idx >> 2;
                    rAh[i] = *reinterpret_cast<const uint4*>(
                        Ah + (size_t)(m0 + m) * K + k0 + u4 * 8);
                }
            } else {
#pragma unroll
                for (int i = 0; i < 4; i++) {
                    int idx = tid + i * 256;
                    int kg = idx & 7, m = idx >> 3;
                    rA[i] = *reinterpret_cast<const float4*>(
                        Af + (size_t)(m0 + m) * K + k0 + kg * 4);
                }
            }
            if (BHALF) {
                if (TRANSB) {
#pragma unroll
                    for (int i = 0; i < 2; i++) {
                        int idx = tid + i * 256;
                        int u4 = idx & 3, n = idx >> 2;
                        rBh[i] = make_uint4(0, 0, 0, 0);
                        if (n0 + n < N)
                            rBh[i] = *reinterpret_cast<const uint4*>(
                                Bh + (size_t)(n0 + n) * K + k0 + u4 * 8);
                    }
                } else {
#pragma unroll
                    for (int i = 0; i < 2; i++) {
                        int idx = tid + i * 256;
                        int ng = idx & 15, kk = idx >> 4;
                        rBh[i] = make_uint4(0, 0, 0, 0);
                        if (n0 + ng * 8 < N)
                            rBh[i] = *reinterpret_cast<const uint4*>(
                                Bh + (size_t)(k0 + kk) * N + n0 + ng * 8);
                    }
                }
            } else if (TRANSB) {
#pragma unroll
                for (int i = 0; i < 4; i++) {
                    int idx = tid + i * 256;
                    int kg = idx & 7, n = idx >> 3;
                    rB[i] = make_float4(0.f, 0.f, 0.f, 0.f);
                    if (n0 + n < N)
                        rB[i] = *reinterpret_cast<const float4*>(
                            Bf + (size_t)(n0 + n) * K + k0 + kg * 4);
                }
            } else {
#pragma unroll
                for (int i = 0; i < 4; i++) {
                    int idx = tid + i * 256;
                    int ng = idx & 31, kk = idx >> 5;
                    int n = ng * 4;
                    rB[i] = make_float4(0.f, 0.f, 0.f, 0.f);
                    if (n0 + n < N)
                        rB[i] = *reinterpret_cast<const float4*>(
                            Bf + (size_t)(k0 + kk) * N + n0 + n);
                }
            }
        };

        auto store_smem = [&]() {
            if (AHALF) {
#pragma unroll
                for (int i = 0; i < 2; i++) {
                    int idx = tid + i * 256;
                    int u4 = idx & 3, m = idx >> 2;
                    *reinterpret_cast<uint4*>(&As[m * STR2 + u4 * 4]) = rAh[i];
                }
            } else {
#pragma unroll
                for (int i = 0; i < 4; i++) {
                    int idx = tid + i * 256;
                    int kg = idx & 7, m = idx >> 3;
                    float4 v = rA[i];
                    uint2 hu;
                    hu.x = pack_half2(v.x, v.y);
                    hu.y = pack_half2(v.z, v.w);
                    *reinterpret_cast<uint2*>(&As[m * STR2 + kg * 2]) = hu;
                }
            }
            if (BHALF) {
                if (TRANSB) {
#pragma unroll
                    for (int i = 0; i < 2; i++) {
                        int idx = tid + i * 256;
                        int u4 = idx & 3, n = idx >> 2;
                        *reinterpret_cast<uint4*>(&Bs[n * STR2 + u4 * 4]) = rBh[i];
                    }
                } else {
                    __half* Bsh = reinterpret_cast<__half*>(Bs);
#pragma unroll
                    for (int i = 0; i < 2; i++) {
                        int idx = tid + i * 256;
                        int ng = idx & 15, kk = idx >> 4;
                        const __half* hv = reinterpret_cast<const __half*>(&rBh[i]);
#pragma unroll
                        for (int j = 0; j < 8; j++)
                            Bsh[(ng * 8 + j) * (STR2 * 2) + kk] = hv[j];
                    }
                }
            } else if (TRANSB) {
#pragma unroll
                for (int i = 0; i < 4; i++) {
                    int idx = tid + i * 256;
                    int kg = idx & 7, n = idx >> 3;
                    float4 v = rB[i];
                    uint2 hu;
                    hu.x = pack_half2(v.x, v.y);
                    hu.y = pack_half2(v.z, v.w);
                    *reinterpret_cast<uint2*>(&Bs[n * STR2 + kg * 2]) = hu;
                }
            } else {
                __half* Bsh = reinterpret_cast<__half*>(Bs);
#pragma unroll
                for (int i = 0; i < 4; i++) {
                    int idx = tid + i * 256;
                    int ng = idx & 31, kk = idx >> 5;
                    int n = ng * 4;
                    float4 v = rB[i];
                    float vv[4] = {v.x, v.y, v.z, v.w};
#pragma unroll
                    for (int j = 0; j < 4; j++)
                        Bsh[(n + j) * (STR2 * 2) + kk] = __float2half_rn(vv[j]);
                }
            }
        };

        load_regs(0);
        for (int k0 = 0; k0 < K; k0 += KT) {
            store_smem();
            __syncthreads();
            if (k0 + KT < K) load_regs(k0 + KT);
            mma_tile(0);
            __syncthreads();
        }
    }

    // ---- epilogue ----
#pragma unroll
    for (int mi = 0; mi < 4; mi++) {
#pragma unroll
        for (int ni = 0; ni < 4; ni++) {
            const int row = m0 + wm + mi * 16 + g;
            const int col = n0 + wn + ni * 8 + 2 * c;
#pragma unroll
            for (int hf = 0; hf < 2; hf++) {
                const int rr2 = row + hf * 8;
                if (col < N) {
                    float v0 = acc[mi][ni][hf * 2 + 0];
                    float v1 = acc[mi][ni][hf * 2 + 1];
                    if (bias) { v0 += __ldg(bias + col); v1 += __ldg(bias + col + 1); }
                    if (EPI == 1) { v0 = fmaxf(v0, 0.f); v1 = fmaxf(v1, 0.f); }
                    if (EPI == 2) {
                        v0 += pe[((rr2 & 511) << 9) + col];
                        v1 += pe[((rr2 & 511) << 9) + col + 1];
                    }
                    if (EPI == 3) {
                        v0 += resid[(size_t)rr2 * N + col];
                        v1 += resid[(size_t)rr2 * N + col + 1];
                    }
                    if (OHALF) {
                        *reinterpret_cast<uint32_t*>(Ch + (size_t)rr2 * N + col) =
                            pack_half2(v0, v1);
                    } else {
                        Cf[(size_t)rr2 * N + col]     = v0;
                        Cf[(size_t)rr2 * N + col + 1] = v1;
                        if (ODUAL)
                            *reinterpret_cast<uint32_t*>(Ch2 + (size_t)rr2 * N + col) =
                                pack_half2(v0, v1);
                    }
                }
            }
        }
    }
}

// ---------------------------------------------------------------------------
// Sims split GEMM (2-pass): C = Ahi@Bhi^T + Ahi@Blo^T (fp32 acc).
// Operands pre-split fp16; raw uint4 loads, register-staged single buffer.
// ---------------------------------------------------------------------------
__global__ void __launch_bounds__(256) sims_split_tc(
    const __half* __restrict__ Ahi,
    const __half* __restrict__ Bhi, const __half* __restrict__ Blo,
    float* __restrict__ C, int M, int N, int K)
{
    constexpr int KT    = 32;
    constexpr int STR2  = 20;
    constexpr int TILE2 = 128 * STR2;

    __shared__ uint32_t As[TILE2];
    __shared__ uint32_t Bs[2 * TILE2];   // [hi | lo]

    const int tid  = threadIdx.x;
    const int lane = tid & 31, wid = tid >> 5;
    const int wm = (wid >> 2) * 64, wn = (wid & 3) * 32;
    const int g = lane >> 2, c = lane & 3;
    const int m0 = blockIdx.y * 128, n0 = blockIdx.x * 128;

    float acc[4][4][4];
#pragma unroll
    for (int i = 0; i < 4; i++)
#pragma unroll
        for (int j = 0; j < 4; j++)
#pragma unroll
            for (int t = 0; t < 4; t++) acc[i][j][t] = 0.f;

    uint4 rAh[2], rBh[2], rBl[2];

    auto load_regs = [&](int k0) {
#pragma unroll
        for (int i = 0; i < 2; i++) {
            int idx = tid + i * 256;
            int u4 = idx & 3, m = idx >> 2;
            size_t aoff = (size_t)(m0 + m) * K + k0 + u4 * 8;
            size_t boff = (size_t)(n0 + m) * K + k0 + u4 * 8;
            rAh[i] = *reinterpret_cast<const uint4*>(Ahi + aoff);
            rBh[i] = *reinterpret_cast<const uint4*>(Bhi + boff);
            rBl[i] = *reinterpret_cast<const uint4*>(Blo + boff);
        }
    };

    auto store_smem = [&]() {
#pragma unroll
        for (int i = 0; i < 2; i++) {
            int idx = tid + i * 256;
            int u4 = idx & 3, m = idx >> 2;
            *reinterpret_cast<uint4*>(&As[m * STR2 + u4 * 4]) = rAh[i];
            *reinterpret_cast<uint4*>(&Bs[m * STR2 + u4 * 4]) = rBh[i];
            *reinterpret_cast<uint4*>(&Bs[TILE2 + m * STR2 + u4 * 4]) = rBl[i];
        }
    };

    load_regs(0);
    for (int k0 = 0; k0 < K; k0 += KT) {
        store_smem();
        __syncthreads();
        if (k0 + KT < K) load_regs(k0 + KT);

#pragma unroll
        for (int ks = 0; ks < 2; ks++) {
            const int kb = ks * 8 + c;
            uint32_t af[4][4], bf[4][2], bfl[4][2];
#pragma unroll
            for (int mi = 0; mi < 4; mi++) {
                const int mr = wm + mi * 16 + g;
                af[mi][0] = As[mr * STR2 + kb];
                af[mi][1] = As[(mr + 8) * STR2 + kb];
                af[mi][2] = As[mr * STR2 + kb + 4];
                af[mi][3] = As[(mr + 8) * STR2 + kb + 4];
            }
#pragma unroll
            for (int ni = 0; ni < 4; ni++) {
                const int nr = wn + ni * 8 + g;
                bf[ni][0]  = Bs[nr * STR2 + kb];
                bf[ni][1]  = Bs[nr * STR2 + kb + 4];
                bfl[ni][0] = Bs[TILE2 + nr * STR2 + kb];
                bfl[ni][1] = Bs[TILE2 + nr * STR2 + kb + 4];
            }
#pragma unroll
            for (int mi = 0; mi < 4; mi++)
#pragma unroll
                for (int ni = 0; ni < 4; ni++) {
                    mma_f16(acc[mi][ni], af[mi][0], af[mi][1], af[mi][2], af[mi][3],
                            bf[ni][0], bf[ni][1]);
                    mma_f16(acc[mi][ni], af[mi][0], af[mi][1], af[mi][2], af[mi][3],
                            bfl[ni][0], bfl[ni][1]);
                }
        }
        __syncthreads();
    }

#pragma unroll
    for (int mi = 0; mi < 4; mi++)
#pragma unroll
        for (int ni = 0; ni < 4; ni++) {
            const int row = m0 + wm + mi * 16 + g;
            const int col = n0 + wn + ni * 8 + 2 * c;
#pragma unroll
            for (int hf = 0; hf < 2; hf++) {
                const int rr2 = row + hf * 8;
                C[(size_t)rr2 * N + col]     = acc[mi][ni][hf * 2 + 0];
                C[(size_t)rr2 * N + col + 1] = acc[mi][ni][hf * 2 + 1];
            }
        }
}

// ---------------------------------------------------------------------------
// Fused flash attention (fp16 in/out): o = softmax(QK^T/8) @ V per (b,h).
// (R11-proven version: single K buffer, sync loads, 37 KB smem.)
// ---------------------------------------------------------------------------
__global__ void __launch_bounds__(128) flash_attn_tc(
    const __half* __restrict__ qkv, __half* __restrict__ o)
{
    constexpr int QSTR = 36;
    constexpr int VSTR = 38;
    __shared__ uint32_t Qs[64 * QSTR];
    __shared__ uint32_t Ks[64 * QSTR];
    __shared__ uint32_t Ps[64 * QSTR];
    __shared__ uint32_t Vs[64 * VSTR];

    const int qt = blockIdx.x, bh = blockIdx.y;
    const int b = bh >> 3, h = bh & 7;
    const int tid = threadIdx.x, lane = tid & 31, wid = tid >> 5;
    const int wm = wid * 16;
    const int g = lane >> 2, c = lane & 3;

#pragma unroll
    for (int i = 0; i < 4; i++) {
        int idx = tid + i * 128;
        int u4 = idx & 7, m = idx >> 3;
        uint4 u = *reinterpret_cast<const uint4*>(
            qkv + (size_t)(b * 512 + qt * 64 + m) * 1536 + h * 64 + u4 * 8);
        *reinterpret_cast<uint4*>(&Qs[m * QSTR + u4 * 4]) = u;
    }

    float m_r[2] = {-3.402823466e38f, -3.402823466e38f};
    float l_r[2] = {0.f, 0.f};
    float oacc[8][4];
#pragma unroll
    for (int nf = 0; nf < 8; nf++)
#pragma unroll
        for (int t = 0; t < 4; t++) oacc[nf][t] = 0.f;

    __half* Vsh = reinterpret_cast<__half*>(Vs);

    for (int kc = 0; kc < 8; kc++) {
#pragma unroll
        for (int i = 0; i < 4; i++) {
            int idx = tid + i * 128;
            int u4 = idx & 7, m = idx >> 3;
            const __half* base = qkv + (size_t)(b * 512 + kc * 64 + m) * 1536 + h * 64;
            uint4 ku = *reinterpret_cast<const uint4*>(base + 512 + u4 * 8);
            *reinterpret_cast<uint4*>(&Ks[m * QSTR + u4 * 4]) = ku;
            uint4 vu = *reinterpret_cast<const uint4*>(base + 1024 + u4 * 8);
            const __half2* vh = reinterpret_cast<const __half2*>(&vu);
#pragma unroll
            for (int j = 0; j < 4; j++) {
                __half2 p = vh[j];
                Vsh[(u4 * 8 + 2 * j + 0) * 76 + m] = __low2half(p);
                Vsh[(u4 * 8 + 2 * j + 1) * 76 + m] = __high2half(p);
            }
        }
        __syncthreads();

        float sacc[8][4];
#pragma unroll
        for (int nf = 0; nf < 8; nf++)
#pragma unroll
            for (int t = 0; t < 4; t++) sacc[nf][t] = 0.f;

#pragma unroll
        for (int ks = 0; ks < 4; ks++) {
            const int kb = ks * 8 + c;
            uint32_t a0 = Qs[(wm + g) * QSTR + kb];
            uint32_t a1 = Qs[(wm + g + 8) * QSTR + kb];
            uint32_t a2 = Qs[(wm + g) * QSTR + kb + 4];
            uint32_t a3 = Qs[(wm + g + 8) * QSTR + kb + 4];
#pragma unroll
            for (int nf = 0; nf < 8; nf++) {
                const int nr = nf * 8 + g;
                mma_f16(sacc[nf], a0, a1, a2, a3,
                        Ks[nr * QSTR + kb], Ks[nr * QSTR + kb + 4]);
            }
        }

        float mx0 = -3.402823466e38f, mx1 = -3.402823466e38f;
#pragma unroll
        for (int nf = 0; nf < 8; nf++) {
#pragma unroll
            for (int t = 0; t < 4; t++) sacc[nf][t] *= 0.125f;
            mx0 = fmaxf(mx0, fmaxf(sacc[nf][0], sacc[nf][1]));
            mx1 = fmaxf(mx1, fmaxf(sacc[nf][2], sacc[nf][3]));
        }
        mx0 = fmaxf(mx0, __shfl_xor_sync(0xffffffffu, mx0, 1));
        mx0 = fmaxf(mx0, __shfl_xor_sync(0xffffffffu, mx0, 2));
        mx1 = fmaxf(mx1, __shfl_xor_sync(0xffffffffu, mx1, 1));
        mx1 = fmaxf(mx1, __shfl_xor_sync(0xffffffffu, mx1, 2));

        const float mn0 = fmaxf(m_r[0], mx0);
        const float mn1 = fmaxf(m_r[1], mx1);
        const float f0 = expf(m_r[0] - mn0);
        const float f1 = expf(m_r[1] - mn1);

        float s0 = 0.f, s1 = 0.f;
#pragma unroll
        for (int nf = 0; nf < 8; nf++) {
            float p0 = expf(sacc[nf][0] - mn0);
            float p1 = expf(sacc[nf][1] - mn0);
            float p2 = expf(sacc[nf][2] - mn1);
            float p3 = expf(sacc[nf][3] - mn1);
            s0 += p0 + p1;
            s1 += p2 + p3;
            Ps[(wm + g) * QSTR + nf * 4 + c]     = pack_half2(p0, p1);
            Ps[(wm + g + 8) * QSTR + nf * 4 + c] = pack_half2(p2, p3);
            oacc[nf][0] *= f0; oacc[nf][1] *= f0;
            oacc[nf][2] *= f1; oacc[nf][3] *= f1;
        }
        s0 += __shfl_xor_sync(0xffffffffu, s0, 1);
        s0 += __shfl_xor_sync(0xffffffffu, s0, 2);
        s1 += __shfl_xor_sync(0xffffffffu, s1, 1);
        s1 += __shfl_xor_sync(0xffffffffu, s1, 2);
        l_r[0] = l_r[0] * f0 + s0;
        l_r[1] = l_r[1] * f1 + s1;
        m_r[0] = mn0; m_r[1] = mn1;
        __syncwarp();

#pragma unroll
        for (int ks = 0; ks < 4; ks++) {
            const int kb = ks * 8 + c;
            uint32_t a0 = Ps[(wm + g) * QSTR + kb];
            uint32_t a1 = Ps[(wm + g + 8) * QSTR + kb];
            uint32_t a2 = Ps[(wm + g) * QSTR + kb + 4];
            uint32_t a3 = Ps[(wm + g + 8) * QSTR + kb + 4];
#pragma unroll
            for (int nf = 0; nf < 8; nf++) {
                const int nr = nf * 8 + g;
                mma_f16(oacc[nf], a0, a1, a2, a3,
                        Vs[nr * VSTR + kb], Vs[nr * VSTR + kb + 4]);
            }
        }
        __syncthreads();
    }

    const float inv0 = 1.f / l_r[0];
    const float inv1 = 1.f / l_r[1];
#pragma unroll
    for (int nf = 0; nf < 8; nf++) {
        const int row = qt * 64 + wm + g;
        const int col = nf * 8 + 2 * c;
        __half* ob = o + (size_t)(b * 512 + row) * 512 + h * 64 + col;
        *reinterpret_cast<uint32_t*>(ob) =
            pack_half2(oacc[nf][0] * inv0, oacc[nf][1] * inv0);
        *reinterpret_cast<uint32_t*>(ob + 8 * 512) =
            pack_half2(oacc[nf][2] * inv1, oacc[nf][3] * inv1);
    }
}

// ---------------------------------------------------------------------------
// Row softmax (row length 1024) with dual fp32 + fp16 output
// ---------------------------------------------------------------------------
__global__ void __launch_bounds__(256) softmax_dual_kernel(
    float* __restrict__ data, __half* __restrict__ out16)
{
    float* row = data + (size_t)blockIdx.x * 1024;
    __half* hrow = out16 + (size_t)blockIdx.x * 1024;
    const int tid = threadIdx.x;
    float x[4];
    float mx = -3.402823466e38f;
#pragma unroll
    for (int c = 0; c < 4; c++) {
        x[c] = row[tid + 256 * c];
        mx = fmaxf(mx, x[c]);
    }
    __shared__ float sh[8];
#pragma unroll
    for (int o = 16; o; o >>= 1) mx = fmaxf(mx, __shfl_xor_sync(0xffffffffu, mx, o));
    if ((tid & 31) == 0) sh[tid >> 5] = mx;
    __syncthreads();
    mx = sh[0];
#pragma unroll
    for (int w = 1; w < 8; w++) mx = fmaxf(mx, sh[w]);

    float s = 0.f;
#pragma unroll
    for (int c = 0; c < 4; c++) { x[c] = expf(x[c] - mx); s += x[c]; }
    __syncthreads();
#pragma unroll
    for (int o = 16; o; o >>= 1) s += __shfl_xor_sync(0xffffffffu, s, o);
    if ((tid & 31) == 0) sh[tid >> 5] = s;
    __syncthreads();
    float tot = sh[0];
#pragma unroll
    for (int w = 1; w < 8; w++) tot += sh[w];
    float inv = 1.f / tot;
#pragma unroll
    for (int c = 0; c < 4; c++) {
        float r = x[c] * inv;
        row[tid + 256 * c] = r;
        hrow[tid + 256 * c] = __float2half_rn(r);
    }
}

// ---------------------------------------------------------------------------
// out = LayerNorm(X) * g + b ; dual fp32 + fp16 outputs
// ---------------------------------------------------------------------------
__global__ void __launch_bounds__(256) ln_kernel(
    const float* __restrict__ X,
    const float* __restrict__ gam, const float* __restrict__ bet,
    float* __restrict__ out, __half* __restrict__ out16)
{
    const size_t row = blockIdx.x;
    const float* xr = X + row * 512;
    const int tid = threadIdx.x;
    float t0 = xr[tid];
    float t1 = xr[tid + 256];

    __shared__ float sh[8];
    float s = t0 + t1;
#pragma unroll
    for (int o = 16; o; o >>= 1) s += __shfl_xor_sync(0xffffffffu, s, o);
    if ((tid & 31) == 0) sh[tid >> 5] = s;
    __syncthreads();
    float tot = sh[0];
#pragma unroll
    for (int w = 1; w < 8; w++) tot += sh[w];
    float mean = tot * (1.f / 512.f);
    float d0 = t0 - mean, d1 = t1 - mean;
    float q = d0 * d0 + d1 * d1;
    __syncthreads();
#pragma unroll
    for (int o = 16; o; o >>= 1) q += __shfl_xor_sync(0xffffffffu, q, o);
    if ((tid & 31) == 0) sh[tid >> 5] = q;
    __syncthreads();
    float vtot = sh[0];
#pragma unroll
    for (int w = 1; w < 8; w++) vtot += sh[w];
    float inv = rsqrtf(vtot * (1.f / 512.f) + 1e-5f);
    float r0 = d0 * inv * gam[tid] + bet[tid];
    float r1 = d1 * inv * gam[tid + 256] + bet[tid + 256];
    float* orow = out + row * 512;
    orow[tid] = r0;
    orow[tid + 256] = r1;
    __half* hrow = out16 + row * 512;
    hrow[tid] = __float2half_rn(r0);
    hrow[tid + 256] = __float2half_rn(r1);
}

// ---------------------------------------------------------------------------
// Graph branch (exact fp32, tiny cost)
// ---------------------------------------------------------------------------
__global__ void feat_fn_kernel(const float* __restrict__ x, float* __restrict__ fn)
{
    const int b = blockIdx.x, i = threadIdx.x;
    const float* xp = x + (size_t)b * 32768 + i;
    float s = 0.f;
    for (int t = 0; t < 512; t++) s += xp[(size_t)t * 64];
    float f = s * (1.f / 512.f);
    __shared__ float sh[64];
    sh[i] = f * f;
    __syncthreads();
    for (int o = 32; o; o >>= 1) {
        if (i < o) sh[i] += sh[i + o];
        __syncthreads();
    }
    float norm = sqrtf(sh[0]);
    fn[b * 64 + i] = f / fmaxf(norm, 1e-12f);
}

__global__ void graph_adj_kernel(const float* __restrict__ fn, float* __restrict__ An)
{
    const int b = blockIdx.x, i = threadIdx.x;
    __shared__ float f[64];
    __shared__ unsigned char A[64][64];
    f[i] = fn[b * 64 + i];
    for (int j = 0; j < 64; j++) A[i][j] = 0;
    __syncthreads();
    const float fi = f[i];
    float bv0 = -3.402823466e38f, bv1 = bv0, bv2 = bv0, bv3 = bv0;
    int i0 = 0, i1 = 0, i2 = 0, i3 = 0;
    for (int j = 0; j < 64; j++) {
        float v = fi * f[j];
        if (v > bv3) {
            if (v > bv0)      { bv3 = bv2; i3 = i2; bv2 = bv1; i2 = i1; bv1 = bv0; i1 = i0; bv0 = v; i0 = j; }
            else if (v > bv1) { bv3 = bv2; i3 = i2; bv2 = bv1; i2 = i1; bv1 = v; i1 = j; }
            else if (v > bv2) { bv3 = bv2; i3 = i2; bv2 = v; i2 = j; }
            else              { bv3 = v; i3 = j; }
        }
    }
    A[i][i1] = 1; A[i][i2] = 1; A[i][i3] = 1;
    __syncthreads();
    float deg = 0.f;
    for (int j = 0; j < 64; j++) {
        bool a = (j == i) || A[i][j] || A[j][i];
        deg += a ? 1.f : 0.f;
    }
    float inv = 1.f / deg;
    float* row = An + (size_t)b * 4096 + i * 64;
    for (int j = 0; j < 64; j++) {
        bool a = (j == i) || A[i][j] || A[j][i];
        row[j] = a ? inv : 0.f;
    }
}

__global__ void __launch_bounds__(256) gcn_gemm1_kernel(
    const float* __restrict__ x, const float* __restrict__ w,
    const float* __restrict__ bias, float* __restrict__ out)
{
    const int dt = blockIdx.x, b = blockIdx.y;
    __shared__ float Xs[16][64];
    __shared__ float Ws[64][17];
    const int tid = threadIdx.x, tx = tid & 15, ty = tid >> 4;
    float acc[4][4];
#pragma unroll
    for (int i = 0; i < 4; i++)
#pragma unroll
        for (int j = 0; j < 4; j++) acc[i][j] = 0.f;

    for (int k0 = 0; k0 < 512; k0 += 16) {
        {
            int kk = tid >> 4, f4 = (tid & 15) << 2;
            float4 v = *reinterpret_cast<const float4*>(
                x + (size_t)b * 32768 + (size_t)(k0 + kk) * 64 + f4);
            *reinterpret_cast<float4*>(&Xs[kk][f4]) = v;
            int dd = tid >> 2, k4 = (tid & 3) << 2;
            float4 w4 = *reinterpret_cast<const float4*>(
                w + (size_t)(dt * 64 + dd) * 512 + k0 + k4);
            Ws[dd][k4 + 0] = w4.x; Ws[dd][k4 + 1] = w4.y;
            Ws[dd][k4 + 2] = w4.z; Ws[dd][k4 + 3] = w4.w;
        }
        __syncthreads();
#pragma unroll
        for (int kk = 0; kk < 16; kk++) {
            float a[4], bb[4];
#pragma unroll
            for (int i = 0; i < 4; i++) a[i] = Xs[kk][ty + 16 * i];
#pragma unroll
            for (int j = 0; j < 4; j++) bb[j] = Ws[tx + 16 * j][kk];
#pragma unroll
            for (int i = 0; i < 4; i++)
#pragma unroll
                for (int j = 0; j < 4; j++)
                    acc[i][j] = fmaf(a[i], bb[j], acc[i][j]);
        }
        __syncthreads();
    }
#pragma unroll
    for (int i = 0; i < 4; i++)
#pragma unroll
        for (int j = 0; j < 4; j++) {
            int dd = dt * 64 + tx + 16 * j;
            out[(size_t)b * 32768 + (size_t)(ty + 16 * i) * 512 + dd] =
                acc[i][j] + bias[dd];
        }
}

__global__ void __launch_bounds__(256) gcn_gemm2_kernel(
    const float* __restrict__ Ain, const float* __restrict__ w,
    const float* __restrict__ bias, float* __restrict__ out)
{
    const int st = blockIdx.x, b = blockIdx.y;
    __shared__ float As[64][17];
    __shared__ float Ws[64][17];
    const int tid = threadIdx.x, tx = tid & 15, ty = tid >> 4;
    const int rr = tid >> 2, k4 = (tid & 3) << 2;
    float acc[4][4];
#pragma unroll
    for (int i = 0; i < 4; i++)
#pragma unroll
        for (int j = 0; j < 4; j++) acc[i][j] = 0.f;

    for (int k0 = 0; k0 < 512; k0 += 16) {
        float4 a4 = *reinterpret_cast<const float4*>(
            Ain + (size_t)b * 32768 + (size_t)rr * 512 + k0 + k4);
        As[rr][k4 + 0] = a4.x; As[rr][k4 + 1] = a4.y;
        As[rr][k4 + 2] = a4.z; As[rr][k4 + 3] = a4.w;
        float4 w4 = *reinterpret_cast<const float4*>(
            w + (size_t)(st * 64 + rr) * 512 + k0 + k4);
        Ws[rr][k4 + 0] = w4.x; Ws[rr][k4 + 1] = w4.y;
        Ws[rr][k4 + 2] = w4.z; Ws[rr][k4 + 3] = w4.w;
        __syncthreads();
#pragma unroll
        for (int kk = 0; kk < 16; kk++) {
            float a[4], bb[4];
#pragma unroll
            for (int i = 0; i < 4; i++) a[i] = As[ty + 16 * i][kk];
#pragma unroll
            for (int j = 0; j < 4; j++) bb[j] = Ws[tx + 16 * j][kk];
#pragma unroll
            for (int i = 0; i < 4; i++)
#pragma unroll
                for (int j = 0; j < 4; j++)
                    acc[i][j] = fmaf(a[i], bb[j], acc[i][j]);
        }
        __syncthreads();
    }
#pragma unroll
    for (int i = 0; i < 4; i++)
#pragma unroll
        for (int j = 0; j < 4; j++) {
            int ss = st * 64 + tx + 16 * j;
            out[(size_t)b * 32768 + (size_t)(ty + 16 * i) * 512 + ss] =
                acc[i][j] + bias[ss];
        }
}

template <bool RELU, bool TRANSOUT>
__global__ void __launch_bounds__(256) an_mult_kernel(
    const float* __restrict__ An, const float* __restrict__ in,
    float* __restrict__ out)
{
    const int dt = blockIdx.x, b = blockIdx.y;
    __shared__ float As[64][65];
    __shared__ float Ins[64][64];
    const int tid = threadIdx.x, tx = tid & 15, ty = tid >> 4;

    for (int t = tid; t < 4096; t += 256)
        As[t >> 6][t & 63] = An[(size_t)b * 4096 + t];
#pragma unroll
    for (int hh = 0; hh < 4; hh++) {
        int idx4 = tid + hh * 256;
        int gg = idx4 >> 4, c4 = (idx4 & 15) << 2;
        float4 v = *reinterpret_cast<const float4*>(
            in + (size_t)b * 32768 + (size_t)gg * 512 + dt * 64 + c4);
        *reinterpret_cast<float4*>(&Ins[gg][c4]) = v;
    }
    __syncthreads();

    float acc[4][4];
#pragma unroll
    for (int i = 0; i < 4; i++)
#pragma unroll
        for (int j = 0; j < 4; j++) acc[i][j] = 0.f;

#pragma unroll 8
    for (int kk = 0; kk < 64; kk++) {
        float a[4], bb[4];
#pragma unroll
        for (int i = 0; i < 4; i++) a[i] = As[ty + 16 * i][kk];
#pragma unroll
        for (int j = 0; j < 4; j++) bb[j] = Ins[kk][tx + 16 * j];
#pragma unroll
        for (int i = 0; i < 4; i++)
#pragma unroll
            for (int j = 0; j < 4; j++)
                acc[i][j] = fmaf(a[i], bb[j], acc[i][j]);
    }

#pragma unroll
    for (int i = 0; i < 4; i++)
#pragma unroll
        for (int j = 0; j < 4; j++) {
            int ff = ty + 16 * i;
            int dd = dt * 64 + tx + 16 * j;
            float v = acc[i][j];
            if (RELU) v = fmaxf(v, 0.f);
            if (!TRANSOUT)
                out[(size_t)b * 32768 + (size_t)ff * 512 + dd] = v;
            else
                out[(size_t)b * 32768 + (size_t)dd * 64 + ff] = v;
        }
}

// ---------------------------------------------------------------------------
// Host orchestration
// ---------------------------------------------------------------------------
extern "C" void kernel_launch(void* const* d_in, const int* in_sizes, int n_in,
                              void* d_out, int out_size)
{
    const float* x      = (const float*)d_in[0];
    const float* W_in   = (const float*)d_in[1];
    const float* b_in   = (const float*)d_in[2];
    const float* qkv_w  = (const float*)d_in[3];
    const float* qkv_b  = (const float*)d_in[4];
    const float* out_w  = (const float*)d_in[5];
    const float* out_b  = (const float*)d_in[6];
    const float* ln1_g  = (const float*)d_in[7];
    const float* ln1_b  = (const float*)d_in[8];
    const float* ln2_g  = (const float*)d_in[9];
    const float* ln2_b  = (const float*)d_in[10];
    const float* ff1_w  = (const float*)d_in[11];
    const float* ff1_b  = (const float*)d_in[12];
    const float* ff2_w  = (const float*)d_in[13];
    const float* ff2_b  = (const float*)d_in[14];
    const float* memory = (const float*)d_in[15];
    const float* fc1_w  = (const float*)d_in[16];
    const float* fc1_b  = (const float*)d_in[17];
    const float* fc2_w  = (const float*)d_in[18];
    const float* fc2_b  = (const float*)d_in[19];
    const float* gc1_w  = (const float*)d_in[20];
    const float* gc1_b  = (const float*)d_in[21];
    const float* gc2_w  = (const float*)d_in[22];
    const float* gc2_b  = (const float*)d_in[23];

    float* out    = (float*)d_out;
    float* t_out  = out;                       // (32,512,64)
    float* gout_p = out + 1048576;             // (32,512,64)
    float* attn_p = out + 2097152;             // (32,512,1024)

    static float *p_pe = nullptr, *p_h, *p_tmp, *p_fn, *p_An, *p_gt1, *p_gh1;
    static __half *p_h16, *p_qkv, *p_o, *p_ff, *p_mlo, *p_memT, *p_wh;
    if (!p_pe) {
        cudaGetSymbolAddress((void**)&p_pe,    g_pe);
        cudaGetSymbolAddress((void**)&p_h,     g_h);
        cudaGetSymbolAddress((void**)&p_h16,   g_h16);
        cudaGetSymbolAddress((void**)&p_tmp,   g_tmp);
        cudaGetSymbolAddress((void**)&p_qkv,   g_qkv);
        cudaGetSymbolAddress((void**)&p_o,     g_o);
        cudaGetSymbolAddress((void**)&p_ff,    g_ff);
        cudaGetSymbolAddress((void**)&p_mlo,   g_mlo);
        cudaGetSymbolAddress((void**)&p_memT,  g_memT);
        cudaGetSymbolAddress((void**)&p_fn,    g_fn);
        cudaGetSymbolAddress((void**)&p_An,    g_An);
        cudaGetSymbolAddress((void**)&p_gt1,   g_gt1);
        cudaGetSymbolAddress((void**)&p_gh1,   g_gh1);
        cudaGetSymbolAddress((void**)&p_wh,    g_wh);
    }

    const int M = 16384;

    // ---- pre-convert weights to fp16 (graph-captured) ----
    auto conv = [&](const float* src, __half* dst, int n) {
        convert_w_kernel<<<(n / 4 + 255) / 256, 256>>>(src, dst, n / 4);
    };
    conv(qkv_w,  p_wh + WH_QKV, 3 * 1536 * 512);
    conv(out_w,  p_wh + WH_OUT, 3 * 512 * 512);
    conv(ff1_w,  p_wh + WH_FF1, 3 * 2048 * 512);
    conv(ff2_w,  p_wh + WH_FF2, 3 * 512 * 2048);
    conv(memory, p_wh + WH_MEM, 1024 * 512);
    conv(fc1_w,  p_wh + WH_FC1, 512 * 1024);
    conv(fc2_w,  p_wh + WH_FC2, 64 * 512);
    conv(W_in,   p_wh + WH_WIN, 512 * 64);
    make_lo_kernel<<<(1024 * 512 / 4 + 255) / 256, 256>>>(
        memory, p_wh + WH_MEM, p_mlo, 1024 * 512 / 4);
    transpose_mem_kernel<<<dim3(32, 16), dim3(32, 32)>>>(p_wh + WH_MEM, p_memT);

    pe_kernel<<<(512 * 512 + 255) / 256, 256>>>(p_pe);

    // h = x @ W_in^T + b_in + pe (dual fp32+fp16 out, fp16 B register-staged)
    gemm_tc<true, 2, false, false, false, true, false, true>
        <<<dim3(4, 128), 256>>>(
        x, nullptr, p_wh + WH_WIN, b_in, p_pe, nullptr, p_h, p_h16, M, 512, 64);

    for (int l = 0; l < 3; l++) {
        // qkv (pure fp16, cp.async)
        gemm_tc<true, 0, false, true, true, true, true, false>
            <<<dim3(12, 128), 256>>>(
            p_h16, nullptr, p_wh + WH_QKV + (size_t)l * 1536 * 512,
            qkv_b + l * 1536, nullptr, nullptr, p_qkv, nullptr, M, 1536, 512);
        // fused attention
        flash_attn_tc<<<dim3(8, 256), 128>>>(p_qkv, p_o);
        // out projection + residual (pure fp16 in, cp.async, fp32 out)
        gemm_tc<true, 3, false, true, false, true, true, false>
            <<<dim3(4, 128), 256>>>(
            p_o, nullptr, p_wh + WH_OUT + (size_t)l * 512 * 512,
            out_b + l * 512, nullptr, p_h, p_tmp, nullptr, M, 512, 512);
        ln_kernel<<<16384, 256>>>(p_tmp, ln1_g + l * 512, ln1_b + l * 512,
                                  p_h, p_h16);
        // feed-forward (pure fp16, cp.async)
        gemm_tc<true, 1, false, true, true, true, true, false>
            <<<dim3(16, 128), 256>>>(
            p_h16, nullptr, p_wh + WH_FF1 + (size_t)l * 2048 * 512,
            ff1_b + l * 2048, nullptr, nullptr, p_ff, nullptr, M, 2048, 512);
        gemm_tc<true, 3, false, true, false, true, true, false>
            <<<dim3(4, 128), 256>>>(
            p_ff, nullptr, p_wh + WH_FF2 + (size_t)l * 512 * 2048,
            ff2_b + l * 512, nullptr, p_h, p_tmp, nullptr, M, 512, 2048);
        ln_kernel<<<16384, 256>>>(p_tmp, ln2_g + l * 512, ln2_b + l * 512,
                                  p_h, p_h16);
    }

    // sims: 2-pass split GEMM (hi*hi + hi*lo), A = h16 only
    sims_split_tc<<<dim3(8, 128), 256>>>(
        p_h16, p_wh + WH_MEM, p_mlo, attn_p, M, 1024, 512);
    // softmax with dual fp32 + fp16 output (attn16 in g_ff scratch)
    softmax_dual_kernel<<<16384, 256>>>(attn_p, p_ff);
    // upd = attn16 @ memT^T (pure fp16, cp.async), fp16 out
    gemm_tc<true, 0, false, true, true, true, true, false>
        <<<dim3(4, 128), 256>>>(
        p_ff, nullptr, p_memT, nullptr, nullptr, nullptr,
        p_o, nullptr, M, 512, 1024);
    // fc1 over fp16 concat [h16 | upd16] (cp.async), fp16 out into qkv buffer
    gemm_tc<true, 1, true, true, true, true, true, false>
        <<<dim3(4, 128), 256>>>(
        p_h16, p_o, p_wh + WH_FC1, fc1_b, nullptr, nullptr,
        p_qkv, nullptr, M, 512, 1024);
    // fc2 (pure fp16 in, cp.async, fp32 out to t_out)
    gemm_tc<true, 0, false, true, false, true, true, false>
        <<<dim3(1, 128), 256>>>(
        p_qkv, nullptr, p_wh + WH_FC2, fc2_b, nullptr, nullptr,
        t_out, nullptr, M, 64, 512);

    // graph branch (exact fp32)
    feat_fn_kernel<<<32, 64>>>(x, p_fn);
    graph_adj_kernel<<<32, 64>>>(p_fn, p_An);
    gcn_gemm1_kernel<<<dim3(8, 32), 256>>>(x, gc1_w, gc1_b, p_gt1);
    an_mult_kernel<true, false><<<dim3(8, 32), 256>>>(p_An, p_gt1, p_gh1);
    gcn_gemm2_kernel<<<dim3(8, 32), 256>>>(p_gh1, gc2_w, gc2_b, p_gt1);
    an_mult_kernel<false, true><<<dim3(8, 32), 256>>>(p_An, p_gt1, gout_p);

    (void)in_sizes; (void)n_in; (void)out_size;
}

// round 17
// speedup vs baseline: 1.0858x; 1.0072x over previous
#include <cuda_runtime.h>
#include <cuda_fp16.h>
#include <math.h>
#include <stdint.h>

// ---------------------------------------------------------------------------
// Problem constants
//  B=32, S=512, F_IN=64, D=512, DFF=2048, MEM=1024, L=3, H=8, dh=64
//  rows = B*S = 16384
// ---------------------------------------------------------------------------

// ------------------------- static scratch buffers --------------------------
__device__ float  g_pe[512 * 512];             // 1 MB
__device__ float  g_h[16384 * 512];            // 32 MB (fp32 residual stream)
__device__ __half g_h16[16384 * 512];          // 16 MB (fp16 mirror of h)
__device__ float  g_tmp[16384 * 512];          // 32 MB
__device__ __half g_qkv[16384 * 1536];         // 48 MB (reused as fc1 out)
__device__ __half g_o[16384 * 512];            // 16 MB (reused as upd16)
__device__ __half g_ff[16384 * 2048];          // 64 MB (reused as attn16)
__device__ __half g_mlo[1024 * 512];           // 1 MB (fp16 low part of memory)
__device__ __half g_memT[512 * 1024];          // 1 MB (fp16 memory transposed)
__device__ float  g_fn[32 * 64];
__device__ float  g_An[32 * 64 * 64];
__device__ float  g_gt1[32 * 64 * 512];        // 4 MB
__device__ float  g_gh1[32 * 64 * 512];        // 4 MB
__device__ __half g_xt_hi[2048 * 512];         // 2 MB (x transposed, fp16 hi)
__device__ __half g_xt_lo[2048 * 512];         // 2 MB (x transposed, fp16 lo)
__device__ __half g_gh_hi[2048 * 512];         // 2 MB (gh1 fp16 hi)
__device__ __half g_gh_lo[2048 * 512];         // 2 MB (gh1 fp16 lo)
__device__ __half g_w1h[512 * 512];            // gc1_w fp16 hi
__device__ __half g_w1l[512 * 512];            // gc1_w fp16 lo
__device__ __half g_w2h[512 * 512];            // gc2_w fp16 hi
__device__ __half g_w2l[512 * 512];            // gc2_w fp16 lo
__device__ __half g_wh[10551296];              // 21 MB fp16 weights

// fp16 weight buffer offsets
#define WH_QKV   0                               // 3*1536*512 = 2359296
#define WH_OUT   2359296                         // 3*512*512  = 786432
#define WH_FF1   3145728                         // 3*2048*512 = 3145728
#define WH_FF2   6291456                         // 3*512*2048 = 3145728
#define WH_MEM   9437184                         // 1024*512   = 524288
#define WH_FC1   9961472                         // 512*1024   = 524288
#define WH_FC2   10485760                        // 64*512     = 32768
#define WH_WIN   10518528                        // 512*64     = 32768

// ---------------------------------------------------------------------------
// fp16 / async helpers
// ---------------------------------------------------------------------------
__device__ __forceinline__ uint32_t pack_half2(float a, float b) {
    __half2 h = __floats2half2_rn(a, b);
    return *reinterpret_cast<uint32_t*>(&h);
}

__device__ __forceinline__ void mma_f16(float c[4],
    uint32_t a0, uint32_t a1, uint32_t a2, uint32_t a3,
    uint32_t b0, uint32_t b1)
{
    asm volatile(
        "mma.sync.aligned.m16n8k16.row.col.f32.f16.f16.f32 "
        "{%0,%1,%2,%3}, {%4,%5,%6,%7}, {%8,%9}, {%0,%1,%2,%3};"
        : "+f"(c[0]), "+f"(c[1]), "+f"(c[2]), "+f"(c[3])
        : "r"(a0), "r"(a1), "r"(a2), "r"(a3), "r"(b0), "r"(b1));
}

__device__ __forceinline__ void cp_async16(void* smem_ptr, const void* gptr) {
    uint32_t a = (uint32_t)__cvta_generic_to_shared(smem_ptr);
    asm volatile("cp.async.cg.shared.global [%0], [%1], 16;" :: "r"(a), "l"(gptr));
}
#define CP_COMMIT() asm volatile("cp.async.commit_group;")
#define CP_WAIT0()  asm volatile("cp.async.wait_group 0;")

// ---------------------------------------------------------------------------
// Weight pre-conversion: fp32 -> fp16 (rn)
// ---------------------------------------------------------------------------
__global__ void convert_w_kernel(const float* __restrict__ src,
                                 __half* __restrict__ dst, int n4)
{
    int i = blockIdx.x * 256 + threadIdx.x;
    if (i >= n4) return;
    float4 v = *reinterpret_cast<const float4*>(src + i * 4);
    uint2 u;
    u.x = pack_half2(v.x, v.y);
    u.y = pack_half2(v.z, v.w);
    *reinterpret_cast<uint2*>(dst + i * 4) = u;
}

// lo = fp16(src - fp32(hi))  (hi already = fp16_rn(src))
__global__ void make_lo_kernel(const float* __restrict__ src,
                               const __half* __restrict__ hi,
                               __half* __restrict__ lo, int n4)
{
    int i = blockIdx.x * 256 + threadIdx.x;
    if (i >= n4) return;
    float4 v = *reinterpret_cast<const float4*>(src + i * 4);
    uint2 hu = *reinterpret_cast<const uint2*>(hi + i * 4);
    __half2 h0 = *reinterpret_cast<__half2*>(&hu.x);
    __half2 h1 = *reinterpret_cast<__half2*>(&hu.y);
    uint2 lu;
    lu.x = pack_half2(v.x - __low2float(h0), v.y - __high2float(h0));
    lu.y = pack_half2(v.z - __low2float(h1), v.w - __high2float(h1));
    *reinterpret_cast<uint2*>(lo + i * 4) = lu;
}

// memT[d][m] = wh_mem[m][d]  (fp16 -> fp16 transpose, 1024x512 -> 512x1024)
__global__ void transpose_mem_kernel(const __half* __restrict__ src,
                                     __half* __restrict__ dst)
{
    __shared__ __half s[32][33];
    const int m0 = blockIdx.x * 32, d0 = blockIdx.y * 32;
    const int tx = threadIdx.x, ty = threadIdx.y;
    s[ty][tx] = src[(size_t)(m0 + ty) * 512 + d0 + tx];
    __syncthreads();
    dst[(size_t)(d0 + ty) * 1024 + m0 + tx] = s[tx][ty];
}

// xt[(b*64+f)][s] = x[b][s][f], split into fp16 hi/lo
__global__ void transpose_x_split(const float* __restrict__ x,
                                  __half* __restrict__ hi,
                                  __half* __restrict__ lo)
{
    __shared__ float s[32][33];
    const int b = blockIdx.z, s0 = blockIdx.x * 32, f0 = blockIdx.y * 32;
    const int tx = threadIdx.x, ty = threadIdx.y;
    s[ty][tx] = x[(size_t)b * 32768 + (size_t)(s0 + ty) * 64 + f0 + tx];
    __syncthreads();
    float v = s[tx][ty];                    // row f0+ty, col s0+tx
    __half h = __float2half_rn(v);
    size_t o = (size_t)(b * 64 + f0 + ty) * 512 + s0 + tx;
    hi[o] = h;
    lo[o] = __float2half_rn(v - __half2float(h));
}

// ---------------------------------------------------------------------------
// Positional encoding (match numpy float64 -> float32)
// ---------------------------------------------------------------------------
__global__ void pe_kernel(float* __restrict__ pe) {
    int i = blockIdx.x * 256 + threadIdx.x;
    if (i >= 512 * 512) return;
    int s = i >> 9, d = i & 511;
    int t2 = d & ~1;
    double div = exp((double)t2 * (-9.210340371976184 / 512.0)); // ln(10000)
    double a = (double)s * div;
    pe[i] = (float)((d & 1) ? cos(a) : sin(a));
}

// ---------------------------------------------------------------------------
// Tensor-core GEMM (fp16 mma, fp32 accumulate).
//  C[M,N] = A[M,K] * op(B) + bias (+epilogue)
//   TRANSB : B is (N,K) row-major -> C = A @ B^T ; false: B (K,N)
//   CATAB  : A logical [M,1024] = concat(A[:,:512], A2[:,:512]) (fp16 srcs)
//   AHALF  : A is __half          OHALF : C written as __half
//   BHALF  : B is __half          CPA   : cp.async double-buffered mainloop
//   ODUAL  : write C fp32 AND C2 fp16
// Block tile 128x128, 256 threads (8 warps = 2m x 4n of 64x32 warp tiles).
// EPI: 0 bias, 1 bias+relu, 2 bias+pos-encoding, 3 bias+residual
// ---------------------------------------------------------------------------
template <bool TRANSB, int EPI, bool CATAB, bool AHALF, bool OHALF,
          bool BHALF, bool CPA, bool ODUAL>
__global__ void __launch_bounds__(256) gemm_tc(
    const void* __restrict__ Avoid, const void* __restrict__ A2void,
    const void* __restrict__ Bvoid,
    const float* __restrict__ bias, const float* __restrict__ pe,
    const float* __restrict__ resid,
    void* __restrict__ Cvoid, void* __restrict__ C2void,
    int M, int N, int K)
{
    constexpr int KT    = 32;              // fp16 elems per K-tile
    constexpr int STR2  = 20;              // half2 (uint) stride: 16 + 4
    constexpr int TILE2 = 128 * STR2;
    constexpr int NSEG  = CPA ? 2 : 1;

    __shared__ uint32_t As[NSEG * TILE2];
    __shared__ uint32_t Bs[NSEG * TILE2];

    const float*  Af  = (const float*)Avoid;
    const __half* Ah  = (const __half*)Avoid;
    const __half* A2h = (const __half*)A2void;
    const float*  Bf  = (const float*)Bvoid;
    const __half* Bh  = (const __half*)Bvoid;
    float*  Cf  = (float*)Cvoid;
    __half* Ch  = (__half*)Cvoid;
    __half* Ch2 = (__half*)C2void;

    const int tid  = threadIdx.x;
    const int lane = tid & 31, wid = tid >> 5;
    const int wm = (wid >> 2) * 64, wn = (wid & 3) * 32;
    const int g = lane >> 2, c = lane & 3;
    const int m0 = blockIdx.y * 128, n0 = blockIdx.x * 128;

    float acc[4][4][4];
#pragma unroll
    for (int i = 0; i < 4; i++)
#pragma unroll
        for (int j = 0; j < 4; j++)
#pragma unroll
            for (int t = 0; t < 4; t++) acc[i][j][t] = 0.f;

    // ---- MMA on one buffer ----
    auto mma_tile = [&](int buf) {
        const uint32_t* Asb = As + (CPA ? buf * TILE2 : 0);
        const uint32_t* Bsb = Bs + (CPA ? buf * TILE2 : 0);
#pragma unroll
        for (int ks = 0; ks < 2; ks++) {
            const int kb = ks * 8 + c;
            uint32_t af[4][4], bf[4][2];
#pragma unroll
            for (int mi = 0; mi < 4; mi++) {
                const int mr = wm + mi * 16 + g;
                af[mi][0] = Asb[mr * STR2 + kb];
                af[mi][1] = Asb[(mr + 8) * STR2 + kb];
                af[mi][2] = Asb[mr * STR2 + kb + 4];
                af[mi][3] = Asb[(mr + 8) * STR2 + kb + 4];
            }
#pragma unroll
            for (int ni = 0; ni < 4; ni++) {
                const int nr = wn + ni * 8 + g;
                bf[ni][0] = Bsb[nr * STR2 + kb];
                bf[ni][1] = Bsb[nr * STR2 + kb + 4];
            }
#pragma unroll
            for (int mi = 0; mi < 4; mi++)
#pragma unroll
                for (int ni = 0; ni < 4; ni++)
                    mma_f16(acc[mi][ni], af[mi][0], af[mi][1], af[mi][2], af[mi][3],
                            bf[ni][0], bf[ni][1]);
        }
    };

    if (CPA) {
        // ================= cp.async double-buffered mainloop =================
        auto issue_cp = [&](int k0, int buf) {
            uint32_t* Asb = As + buf * TILE2;
            uint32_t* Bsb = Bs + buf * TILE2;
#pragma unroll
            for (int i = 0; i < 2; i++) {
                int idx = tid + i * 256;
                int u4 = idx & 3, m = idx >> 2;
                const __half* Ap = Ah;
                int lda = K, kcol = k0 + u4 * 8;
                if (CATAB) {
                    lda = 512;
                    if (k0 >= 512) { Ap = A2h; kcol -= 512; }
                }
                cp_async16(&Asb[m * STR2 + u4 * 4],
                           Ap + (size_t)(m0 + m) * lda + kcol);
            }
#pragma unroll
            for (int i = 0; i < 2; i++) {
                int idx = tid + i * 256;
                int u4 = idx & 3, n = idx >> 2;
                if (n0 + n < N)
                    cp_async16(&Bsb[n * STR2 + u4 * 4],
                               Bh + (size_t)(n0 + n) * K + k0 + u4 * 8);
            }
        };

        issue_cp(0, 0);
        CP_COMMIT();
        int pb = 0;
        for (int k0 = 0; k0 < K; k0 += KT) {
            CP_WAIT0();
            __syncthreads();
            if (k0 + KT < K) {
                issue_cp(k0 + KT, pb ^ 1);
                CP_COMMIT();
            }
            mma_tile(pb);
            pb ^= 1;
        }
        __syncthreads();
    } else {
        // ============== register-staged single-buffer mainloop ==============
        float4 rA[4], rB[4];
        uint4  rAh[2], rBh[2];

        auto load_regs = [&](int k0) {
            if (AHALF) {
#pragma unroll
                for (int i = 0; i < 2; i++) {
                    int idx = tid + i * 256;
                    int u4 = idx & 3, m = idx >> 2;
                    rAh[i] = *reinterpret_cast<const uint4*>(
                        Ah + (size_t)(m0 + m) * K + k0 + u4 * 8);
                }
            } else {
#pragma unroll
                for (int i = 0; i < 4; i++) {
                    int idx = tid + i * 256;
                    int kg = idx & 7, m = idx >> 3;
                    rA[i] = *reinterpret_cast<const float4*>(
                        Af + (size_t)(m0 + m) * K + k0 + kg * 4);
                }
            }
            if (BHALF) {
                if (TRANSB) {
#pragma unroll
                    for (int i = 0; i < 2; i++) {
                        int idx = tid + i * 256;
                        int u4 = idx & 3, n = idx >> 2;
                        rBh[i] = make_uint4(0, 0, 0, 0);
                        if (n0 + n < N)
                            rBh[i] = *reinterpret_cast<const uint4*>(
                                Bh + (size_t)(n0 + n) * K + k0 + u4 * 8);
                    }
                } else {
#pragma unroll
                    for (int i = 0; i < 2; i++) {
                        int idx = tid + i * 256;
                        int ng = idx & 15, kk = idx >> 4;
                        rBh[i] = make_uint4(0, 0, 0, 0);
                        if (n0 + ng * 8 < N)
                            rBh[i] = *reinterpret_cast<const uint4*>(
                                Bh + (size_t)(k0 + kk) * N + n0 + ng * 8);
                    }
                }
            } else if (TRANSB) {
#pragma unroll
                for (int i = 0; i < 4; i++) {
                    int idx = tid + i * 256;
                    int kg = idx & 7, n = idx >> 3;
                    rB[i] = make_float4(0.f, 0.f, 0.f, 0.f);
                    if (n0 + n < N)
                        rB[i] = *reinterpret_cast<const float4*>(
                            Bf + (size_t)(n0 + n) * K + k0 + kg * 4);
                }
            } else {
#pragma unroll
                for (int i = 0; i < 4; i++) {
                    int idx = tid + i * 256;
                    int ng = idx & 31, kk = idx >> 5;
                    int n = ng * 4;
                    rB[i] = make_float4(0.f, 0.f, 0.f, 0.f);
                    if (n0 + n < N)
                        rB[i] = *reinterpret_cast<const float4*>(
                            Bf + (size_t)(k0 + kk) * N + n0 + n);
                }
            }
        };

        auto store_smem = [&]() {
            if (AHALF) {
#pragma unroll
                for (int i = 0; i < 2; i++) {
                    int idx = tid + i * 256;
                    int u4 = idx & 3, m = idx >> 2;
                    *reinterpret_cast<uint4*>(&As[m * STR2 + u4 * 4]) = rAh[i];
                }
            } else {
#pragma unroll
                for (int i = 0; i < 4; i++) {
                    int idx = tid + i * 256;
                    int kg = idx & 7, m = idx >> 3;
                    float4 v = rA[i];
                    uint2 hu;
                    hu.x = pack_half2(v.x, v.y);
                    hu.y = pack_half2(v.z, v.w);
                    *reinterpret_cast<uint2*>(&As[m * STR2 + kg * 2]) = hu;
                }
            }
            if (BHALF) {
                if (TRANSB) {
#pragma unroll
                    for (int i = 0; i < 2; i++) {
                        int idx = tid + i * 256;
                        int u4 = idx & 3, n = idx >> 2;
                        *reinterpret_cast<uint4*>(&Bs[n * STR2 + u4 * 4]) = rBh[i];
                    }
                } else {
                    __half* Bsh = reinterpret_cast<__half*>(Bs);
#pragma unroll
                    for (int i = 0; i < 2; i++) {
                        int idx = tid + i * 256;
                        int ng = idx & 15, kk = idx >> 4;
                        const __half* hv = reinterpret_cast<const __half*>(&rBh[i]);
#pragma unroll
                        for (int j = 0; j < 8; j++)
                            Bsh[(ng * 8 + j) * (STR2 * 2) + kk] = hv[j];
                    }
                }
            } else if (TRANSB) {
#pragma unroll
                for (int i = 0; i < 4; i++) {
                    int idx = tid + i * 256;
                    int kg = idx & 7, n = idx >> 3;
                    float4 v = rB[i];
                    uint2 hu;
                    hu.x = pack_half2(v.x, v.y);
                    hu.y = pack_half2(v.z, v.w);
                    *reinterpret_cast<uint2*>(&Bs[n * STR2 + kg * 2]) = hu;
                }
            } else {
                __half* Bsh = reinterpret_cast<__half*>(Bs);
#pragma unroll
                for (int i = 0; i < 4; i++) {
                    int idx = tid + i * 256;
                    int ng = idx & 31, kk = idx >> 5;
                    int n = ng * 4;
                    float4 v = rB[i];
                    float vv[4] = {v.x, v.y, v.z, v.w};
#pragma unroll
                    for (int j = 0; j < 4; j++)
                        Bsh[(n + j) * (STR2 * 2) + kk] = __float2half_rn(vv[j]);
                }
            }
        };

        load_regs(0);
        for (int k0 = 0; k0 < K; k0 += KT) {
            store_smem();
            __syncthreads();
            if (k0 + KT < K) load_regs(k0 + KT);
            mma_tile(0);
            __syncthreads();
        }
    }

    // ---- epilogue ----
#pragma unroll
    for (int mi = 0; mi < 4; mi++) {
#pragma unroll
        for (int ni = 0; ni < 4; ni++) {
            const int row = m0 + wm + mi * 16 + g;
            const int col = n0 + wn + ni * 8 + 2 * c;
#pragma unroll
            for (int hf = 0; hf < 2; hf++) {
                const int rr2 = row + hf * 8;
                if (col < N) {
                    float v0 = acc[mi][ni][hf * 2 + 0];
                    float v1 = acc[mi][ni][hf * 2 + 1];
                    if (bias) { v0 += __ldg(bias + col); v1 += __ldg(bias + col + 1); }
                    if (EPI == 1) { v0 = fmaxf(v0, 0.f); v1 = fmaxf(v1, 0.f); }
                    if (EPI == 2) {
                        v0 += pe[((rr2 & 511) << 9) + col];
                        v1 += pe[((rr2 & 511) << 9) + col + 1];
                    }
                    if (EPI == 3) {
                        v0 += resid[(size_t)rr2 * N + col];
                        v1 += resid[(size_t)rr2 * N + col + 1];
                    }
                    if (OHALF) {
                        *reinterpret_cast<uint32_t*>(Ch + (size_t)rr2 * N + col) =
                            pack_half2(v0, v1);
                    } else {
                        Cf[(size_t)rr2 * N + col]     = v0;
                        Cf[(size_t)rr2 * N + col + 1] = v1;
                        if (ODUAL)
                            *reinterpret_cast<uint32_t*>(Ch2 + (size_t)rr2 * N + col) =
                                pack_half2(v0, v1);
                    }
                }
            }
        }
    }
}

// ---------------------------------------------------------------------------
// Sims split GEMM (2-pass): C = Ahi@Bhi^T + Ahi@Blo^T (fp32 acc).
// ---------------------------------------------------------------------------
__global__ void __launch_bounds__(256) sims_split_tc(
    const __half* __restrict__ Ahi,
    const __half* __restrict__ Bhi, const __half* __restrict__ Blo,
    float* __restrict__ C, int M, int N, int K)
{
    constexpr int KT    = 32;
    constexpr int STR2  = 20;
    constexpr int TILE2 = 128 * STR2;

    __shared__ uint32_t As[TILE2];
    __shared__ uint32_t Bs[2 * TILE2];   // [hi | lo]

    const int tid  = threadIdx.x;
    const int lane = tid & 31, wid = tid >> 5;
    const int wm = (wid >> 2) * 64, wn = (wid & 3) * 32;
    const int g = lane >> 2, c = lane & 3;
    const int m0 = blockIdx.y * 128, n0 = blockIdx.x * 128;

    float acc[4][4][4];
#pragma unroll
    for (int i = 0; i < 4; i++)
#pragma unroll
        for (int j = 0; j < 4; j++)
#pragma unroll
            for (int t = 0; t < 4; t++) acc[i][j][t] = 0.f;

    uint4 rAh[2], rBh[2], rBl[2];

    auto load_regs = [&](int k0) {
#pragma unroll
        for (int i = 0; i < 2; i++) {
            int idx = tid + i * 256;
            int u4 = idx & 3, m = idx >> 2;
            size_t aoff = (size_t)(m0 + m) * K + k0 + u4 * 8;
            size_t boff = (size_t)(n0 + m) * K + k0 + u4 * 8;
            rAh[i] = *reinterpret_cast<const uint4*>(Ahi + aoff);
            rBh[i] = *reinterpret_cast<const uint4*>(Bhi + boff);
            rBl[i] = *reinterpret_cast<const uint4*>(Blo + boff);
        }
    };

    auto store_smem = [&]() {
#pragma unroll
        for (int i = 0; i < 2; i++) {
            int idx = tid + i * 256;
            int u4 = idx & 3, m = idx >> 2;
            *reinterpret_cast<uint4*>(&As[m * STR2 + u4 * 4]) = rAh[i];
            *reinterpret_cast<uint4*>(&Bs[m * STR2 + u4 * 4]) = rBh[i];
            *reinterpret_cast<uint4*>(&Bs[TILE2 + m * STR2 + u4 * 4]) = rBl[i];
        }
    };

    load_regs(0);
    for (int k0 = 0; k0 < K; k0 += KT) {
        store_smem();
        __syncthreads();
        if (k0 + KT < K) load_regs(k0 + KT);

#pragma unroll
        for (int ks = 0; ks < 2; ks++) {
            const int kb = ks * 8 + c;
            uint32_t af[4][4], bf[4][2], bfl[4][2];
#pragma unroll
            for (int mi = 0; mi < 4; mi++) {
                const int mr = wm + mi * 16 + g;
                af[mi][0] = As[mr * STR2 + kb];
                af[mi][1] = As[(mr + 8) * STR2 + kb];
                af[mi][2] = As[mr * STR2 + kb + 4];
                af[mi][3] = As[(mr + 8) * STR2 + kb + 4];
            }
#pragma unroll
            for (int ni = 0; ni < 4; ni++) {
                const int nr = wn + ni * 8 + g;
                bf[ni][0]  = Bs[nr * STR2 + kb];
                bf[ni][1]  = Bs[nr * STR2 + kb + 4];
                bfl[ni][0] = Bs[TILE2 + nr * STR2 + kb];
                bfl[ni][1] = Bs[TILE2 + nr * STR2 + kb + 4];
            }
#pragma unroll
            for (int mi = 0; mi < 4; mi++)
#pragma unroll
                for (int ni = 0; ni < 4; ni++) {
                    mma_f16(acc[mi][ni], af[mi][0], af[mi][1], af[mi][2], af[mi][3],
                            bf[ni][0], bf[ni][1]);
                    mma_f16(acc[mi][ni], af[mi][0], af[mi][1], af[mi][2], af[mi][3],
                            bfl[ni][0], bfl[ni][1]);
                }
        }
        __syncthreads();
    }

#pragma unroll
    for (int mi = 0; mi < 4; mi++)
#pragma unroll
        for (int ni = 0; ni < 4; ni++) {
            const int row = m0 + wm + mi * 16 + g;
            const int col = n0 + wn + ni * 8 + 2 * c;
#pragma unroll
            for (int hf = 0; hf < 2; hf++) {
                const int rr2 = row + hf * 8;
                C[(size_t)rr2 * N + col]     = acc[mi][ni][hf * 2 + 0];
                C[(size_t)rr2 * N + col + 1] = acc[mi][ni][hf * 2 + 1];
            }
        }
}

// ---------------------------------------------------------------------------
// 3-pass split GEMM (both operands split): C = AhBh^T + AhBl^T + AlBh^T + bias
// fp32 out. For GCN branch (M=2048, N=512, K=512). Error ~2^-24 (AlBl only).
// ---------------------------------------------------------------------------
__global__ void __launch_bounds__(256) split3_tc(
    const __half* __restrict__ Ahi, const __half* __restrict__ Alo,
    const __half* __restrict__ Bhi, const __half* __restrict__ Blo,
    const float* __restrict__ bias,
    float* __restrict__ C, int M, int N, int K)
{
    constexpr int KT    = 32;
    constexpr int STR2  = 20;
    constexpr int TILE2 = 128 * STR2;

    __shared__ uint32_t As[2 * TILE2];   // [hi | lo]
    __shared__ uint32_t Bs[2 * TILE2];

    const int tid  = threadIdx.x;
    const int lane = tid & 31, wid = tid >> 5;
    const int wm = (wid >> 2) * 64, wn = (wid & 3) * 32;
    const int g = lane >> 2, c = lane & 3;
    const int m0 = blockIdx.y * 128, n0 = blockIdx.x * 128;

    float acc[4][4][4];
#pragma unroll
    for (int i = 0; i < 4; i++)
#pragma unroll
        for (int j = 0; j < 4; j++)
#pragma unroll
            for (int t = 0; t < 4; t++) acc[i][j][t] = 0.f;

    uint4 rAh[2], rAl[2], rBh[2], rBl[2];

    auto load_regs = [&](int k0) {
#pragma unroll
        for (int i = 0; i < 2; i++) {
            int idx = tid + i * 256;
            int u4 = idx & 3, m = idx >> 2;
            size_t aoff = (size_t)(m0 + m) * K + k0 + u4 * 8;
            size_t boff = (size_t)(n0 + m) * K + k0 + u4 * 8;
            rAh[i] = *reinterpret_cast<const uint4*>(Ahi + aoff);
            rAl[i] = *reinterpret_cast<const uint4*>(Alo + aoff);
            rBh[i] = *reinterpret_cast<const uint4*>(Bhi + boff);
            rBl[i] = *reinterpret_cast<const uint4*>(Blo + boff);
        }
    };

    auto store_smem = [&]() {
#pragma unroll
        for (int i = 0; i < 2; i++) {
            int idx = tid + i * 256;
            int u4 = idx & 3, m = idx >> 2;
            *reinterpret_cast<uint4*>(&As[m * STR2 + u4 * 4]) = rAh[i];
            *reinterpret_cast<uint4*>(&As[TILE2 + m * STR2 + u4 * 4]) = rAl[i];
            *reinterpret_cast<uint4*>(&Bs[m * STR2 + u4 * 4]) = rBh[i];
            *reinterpret_cast<uint4*>(&Bs[TILE2 + m * STR2 + u4 * 4]) = rBl[i];
        }
    };

    load_regs(0);
    for (int k0 = 0; k0 < K; k0 += KT) {
        store_smem();
        __syncthreads();
        if (k0 + KT < K) load_regs(k0 + KT);

#pragma unroll
        for (int ks = 0; ks < 2; ks++) {
            const int kb = ks * 8 + c;
            uint32_t af[4][4], afl[4][4], bf[4][2], bfl[4][2];
#pragma unroll
            for (int mi = 0; mi < 4; mi++) {
                const int mr = wm + mi * 16 + g;
                af[mi][0]  = As[mr * STR2 + kb];
                af[mi][1]  = As[(mr + 8) * STR2 + kb];
                af[mi][2]  = As[mr * STR2 + kb + 4];
                af[mi][3]  = As[(mr + 8) * STR2 + kb + 4];
                afl[mi][0] = As[TILE2 + mr * STR2 + kb];
                afl[mi][1] = As[TILE2 + (mr + 8) * STR2 + kb];
                afl[mi][2] = As[TILE2 + mr * STR2 + kb + 4];
                afl[mi][3] = As[TILE2 + (mr + 8) * STR2 + kb + 4];
            }
#pragma unroll
            for (int ni = 0; ni < 4; ni++) {
                const int nr = wn + ni * 8 + g;
                bf[ni][0]  = Bs[nr * STR2 + kb];
                bf[ni][1]  = Bs[nr * STR2 + kb + 4];
                bfl[ni][0] = Bs[TILE2 + nr * STR2 + kb];
                bfl[ni][1] = Bs[TILE2 + nr * STR2 + kb + 4];
            }
#pragma unroll
            for (int mi = 0; mi < 4; mi++)
#pragma unroll
                for (int ni = 0; ni < 4; ni++) {
                    mma_f16(acc[mi][ni], af[mi][0], af[mi][1], af[mi][2], af[mi][3],
                            bf[ni][0], bf[ni][1]);
                    mma_f16(acc[mi][ni], af[mi][0], af[mi][1], af[mi][2], af[mi][3],
                            bfl[ni][0], bfl[ni][1]);
                    mma_f16(acc[mi][ni], afl[mi][0], afl[mi][1], afl[mi][2], afl[mi][3],
                            bf[ni][0], bf[ni][1]);
                }
        }
        __syncthreads();
    }

#pragma unroll
    for (int mi = 0; mi < 4; mi++)
#pragma unroll
        for (int ni = 0; ni < 4; ni++) {
            const int row = m0 + wm + mi * 16 + g;
            const int col = n0 + wn + ni * 8 + 2 * c;
#pragma unroll
            for (int hf = 0; hf < 2; hf++) {
                const int rr2 = row + hf * 8;
                C[(size_t)rr2 * N + col]     = acc[mi][ni][hf * 2 + 0] + __ldg(bias + col);
                C[(size_t)rr2 * N + col + 1] = acc[mi][ni][hf * 2 + 1] + __ldg(bias + col + 1);
            }
        }
}

// ---------------------------------------------------------------------------
// Fused flash attention (fp16 in/out): o = softmax(QK^T/8) @ V per (b,h).
// ---------------------------------------------------------------------------
__global__ void __launch_bounds__(128) flash_attn_tc(
    const __half* __restrict__ qkv, __half* __restrict__ o)
{
    constexpr int QSTR = 36;
    constexpr int VSTR = 38;
    __shared__ uint32_t Qs[64 * QSTR];
    __shared__ uint32_t Ks[64 * QSTR];
    __shared__ uint32_t Ps[64 * QSTR];
    __shared__ uint32_t Vs[64 * VSTR];

    const int qt = blockIdx.x, bh = blockIdx.y;
    const int b = bh >> 3, h = bh & 7;
    const int tid = threadIdx.x, lane = tid & 31, wid = tid >> 5;
    const int wm = wid * 16;
    const int g = lane >> 2, c = lane & 3;

#pragma unroll
    for (int i = 0; i < 4; i++) {
        int idx = tid + i * 128;
        int u4 = idx & 7, m = idx >> 3;
        uint4 u = *reinterpret_cast<const uint4*>(
            qkv + (size_t)(b * 512 + qt * 64 + m) * 1536 + h * 64 + u4 * 8);
        *reinterpret_cast<uint4*>(&Qs[m * QSTR + u4 * 4]) = u;
    }

    float m_r[2] = {-3.402823466e38f, -3.402823466e38f};
    float l_r[2] = {0.f, 0.f};
    float oacc[8][4];
#pragma unroll
    for (int nf = 0; nf < 8; nf++)
#pragma unroll
        for (int t = 0; t < 4; t++) oacc[nf][t] = 0.f;

    __half* Vsh = reinterpret_cast<__half*>(Vs);

    for (int kc = 0; kc < 8; kc++) {
#pragma unroll
        for (int i = 0; i < 4; i++) {
            int idx = tid + i * 128;
            int u4 = idx & 7, m = idx >> 3;
            const __half* base = qkv + (size_t)(b * 512 + kc * 64 + m) * 1536 + h * 64;
            uint4 ku = *reinterpret_cast<const uint4*>(base + 512 + u4 * 8);
            *reinterpret_cast<uint4*>(&Ks[m * QSTR + u4 * 4]) = ku;
            uint4 vu = *reinterpret_cast<const uint4*>(base + 1024 + u4 * 8);
            const __half2* vh = reinterpret_cast<const __half2*>(&vu);
#pragma unroll
            for (int j = 0; j < 4; j++) {
                __half2 p = vh[j];
                Vsh[(u4 * 8 + 2 * j + 0) * 76 + m] = __low2half(p);
                Vsh[(u4 * 8 + 2 * j + 1) * 76 + m] = __high2half(p);
            }
        }
        __syncthreads();

        float sacc[8][4];
#pragma unroll
        for (int nf = 0; nf < 8; nf++)
#pragma unroll
            for (int t = 0; t < 4; t++) sacc[nf][t] = 0.f;

#pragma unroll
        for (int ks = 0; ks < 4; ks++) {
            const int kb = ks * 8 + c;
            uint32_t a0 = Qs[(wm + g) * QSTR + kb];
            uint32_t a1 = Qs[(wm + g + 8) * QSTR + kb];
            uint32_t a2 = Qs[(wm + g) * QSTR + kb + 4];
            uint32_t a3 = Qs[(wm + g + 8) * QSTR + kb + 4];
#pragma unroll
            for (int nf = 0; nf < 8; nf++) {
                const int nr = nf * 8 + g;
                mma_f16(sacc[nf], a0, a1, a2, a3,
                        Ks[nr * QSTR + kb], Ks[nr * QSTR + kb + 4]);
            }
        }

        float mx0 = -3.402823466e38f, mx1 = -3.402823466e38f;
#pragma unroll
        for (int nf = 0; nf < 8; nf++) {
#pragma unroll
            for (int t = 0; t < 4; t++) sacc[nf][t] *= 0.125f;
            mx0 = fmaxf(mx0, fmaxf(sacc[nf][0], sacc[nf][1]));
            mx1 = fmaxf(mx1, fmaxf(sacc[nf][2], sacc[nf][3]));
        }
        mx0 = fmaxf(mx0, __shfl_xor_sync(0xffffffffu, mx0, 1));
        mx0 = fmaxf(mx0, __shfl_xor_sync(0xffffffffu, mx0, 2));
        mx1 = fmaxf(mx1, __shfl_xor_sync(0xffffffffu, mx1, 1));
        mx1 = fmaxf(mx1, __shfl_xor_sync(0xffffffffu, mx1, 2));

        const float mn0 = fmaxf(m_r[0], mx0);
        const float mn1 = fmaxf(m_r[1], mx1);
        const float f0 = expf(m_r[0] - mn0);
        const float f1 = expf(m_r[1] - mn1);

        float s0 = 0.f, s1 = 0.f;
#pragma unroll
        for (int nf = 0; nf < 8; nf++) {
            float p0 = expf(sacc[nf][0] - mn0);
            float p1 = expf(sacc[nf][1] - mn0);
            float p2 = expf(sacc[nf][2] - mn1);
            float p3 = expf(sacc[nf][3] - mn1);
            s0 += p0 + p1;
            s1 += p2 + p3;
            Ps[(wm + g) * QSTR + nf * 4 + c]     = pack_half2(p0, p1);
            Ps[(wm + g + 8) * QSTR + nf * 4 + c] = pack_half2(p2, p3);
            oacc[nf][0] *= f0; oacc[nf][1] *= f0;
            oacc[nf][2] *= f1; oacc[nf][3] *= f1;
        }
        s0 += __shfl_xor_sync(0xffffffffu, s0, 1);
        s0 += __shfl_xor_sync(0xffffffffu, s0, 2);
        s1 += __shfl_xor_sync(0xffffffffu, s1, 1);
        s1 += __shfl_xor_sync(0xffffffffu, s1, 2);
        l_r[0] = l_r[0] * f0 + s0;
        l_r[1] = l_r[1] * f1 + s1;
        m_r[0] = mn0; m_r[1] = mn1;
        __syncwarp();

#pragma unroll
        for (int ks = 0; ks < 4; ks++) {
            const int kb = ks * 8 + c;
            uint32_t a0 = Ps[(wm + g) * QSTR + kb];
            uint32_t a1 = Ps[(wm + g + 8) * QSTR + kb];
            uint32_t a2 = Ps[(wm + g) * QSTR + kb + 4];
            uint32_t a3 = Ps[(wm + g + 8) * QSTR + kb + 4];
#pragma unroll
            for (int nf = 0; nf < 8; nf++) {
                const int nr = nf * 8 + g;
                mma_f16(oacc[nf], a0, a1, a2, a3,
                        Vs[nr * VSTR + kb], Vs[nr * VSTR + kb + 4]);
            }
        }
        __syncthreads();
    }

    const float inv0 = 1.f / l_r[0];
    const float inv1 = 1.f / l_r[1];
#pragma unroll
    for (int nf = 0; nf < 8; nf++) {
        const int row = qt * 64 + wm + g;
        const int col = nf * 8 + 2 * c;
        __half* ob = o + (size_t)(b * 512 + row) * 512 + h * 64 + col;
        *reinterpret_cast<uint32_t*>(ob) =
            pack_half2(oacc[nf][0] * inv0, oacc[nf][1] * inv0);
        *reinterpret_cast<uint32_t*>(ob + 8 * 512) =
            pack_half2(oacc[nf][2] * inv1, oacc[nf][3] * inv1);
    }
}

// ---------------------------------------------------------------------------
// Row softmax (row length 1024) with dual fp32 + fp16 output
// ---------------------------------------------------------------------------
__global__ void __launch_bounds__(256) softmax_dual_kernel(
    float* __restrict__ data, __half* __restrict__ out16)
{
    float* row = data + (size_t)blockIdx.x * 1024;
    __half* hrow = out16 + (size_t)blockIdx.x * 1024;
    const int tid = threadIdx.x;
    float x[4];
    float mx = -3.402823466e38f;
#pragma unroll
    for (int c = 0; c < 4; c++) {
        x[c] = row[tid + 256 * c];
        mx = fmaxf(mx, x[c]);
    }
    __shared__ float sh[8];
#pragma unroll
    for (int o = 16; o; o >>= 1) mx = fmaxf(mx, __shfl_xor_sync(0xffffffffu, mx, o));
    if ((tid & 31) == 0) sh[tid >> 5] = mx;
    __syncthreads();
    mx = sh[0];
#pragma unroll
    for (int w = 1; w < 8; w++) mx = fmaxf(mx, sh[w]);

    float s = 0.f;
#pragma unroll
    for (int c = 0; c < 4; c++) { x[c] = expf(x[c] - mx); s += x[c]; }
    __syncthreads();
#pragma unroll
    for (int o = 16; o; o >>= 1) s += __shfl_xor_sync(0xffffffffu, s, o);
    if ((tid & 31) == 0) sh[tid >> 5] = s;
    __syncthreads();
    float tot = sh[0];
#pragma unroll
    for (int w = 1; w < 8; w++) tot += sh[w];
    float inv = 1.f / tot;
#pragma unroll
    for (int c = 0; c < 4; c++) {
        float r = x[c] * inv;
        row[tid + 256 * c] = r;
        hrow[tid + 256 * c] = __float2half_rn(r);
    }
}

// ---------------------------------------------------------------------------
// out = LayerNorm(X) * g + b ; dual fp32 + fp16 outputs
// ---------------------------------------------------------------------------
__global__ void __launch_bounds__(256) ln_kernel(
    const float* __restrict__ X,
    const float* __restrict__ gam, const float* __restrict__ bet,
    float* __restrict__ out, __half* __restrict__ out16)
{
    const size_t row = blockIdx.x;
    const float* xr = X + row * 512;
    const int tid = threadIdx.x;
    float t0 = xr[tid];
    float t1 = xr[tid + 256];

    __shared__ float sh[8];
    float s = t0 + t1;
#pragma unroll
    for (int o = 16; o; o >>= 1) s += __shfl_xor_sync(0xffffffffu, s, o);
    if ((tid & 31) == 0) sh[tid >> 5] = s;
    __syncthreads();
    float tot = sh[0];
#pragma unroll
    for (int w = 1; w < 8; w++) tot += sh[w];
    float mean = tot * (1.f / 512.f);
    float d0 = t0 - mean, d1 = t1 - mean;
    float q = d0 * d0 + d1 * d1;
    __syncthreads();
#pragma unroll
    for (int o = 16; o; o >>= 1) q += __shfl_xor_sync(0xffffffffu, q, o);
    if ((tid & 31) == 0) sh[tid >> 5] = q;
    __syncthreads();
    float vtot = sh[0];
#pragma unroll
    for (int w = 1; w < 8; w++) vtot += sh[w];
    float inv = rsqrtf(vtot * (1.f / 512.f) + 1e-5f);
    float r0 = d0 * inv * gam[tid] + bet[tid];
    float r1 = d1 * inv * gam[tid + 256] + bet[tid + 256];
    float* orow = out + row * 512;
    orow[tid] = r0;
    orow[tid + 256] = r1;
    __half* hrow = out16 + row * 512;
    hrow[tid] = __float2half_rn(r0);
    hrow[tid + 256] = __float2half_rn(r1);
}

// ---------------------------------------------------------------------------
// Graph branch helpers (exact fp32 where it matters)
// ---------------------------------------------------------------------------
__global__ void feat_fn_kernel(const float* __restrict__ x, float* __restrict__ fn)
{
    const int b = blockIdx.x, i = threadIdx.x;
    const float* xp = x + (size_t)b * 32768 + i;
    float s = 0.f;
    for (int t = 0; t < 512; t++) s += xp[(size_t)t * 64];
    float f = s * (1.f / 512.f);
    __shared__ float sh[64];
    sh[i] = f * f;
    __syncthreads();
    for (int o = 32; o; o >>= 1) {
        if (i < o) sh[i] += sh[i + o];
        __syncthreads();
    }
    float norm = sqrtf(sh[0]);
    fn[b * 64 + i] = f / fmaxf(norm, 1e-12f);
}

__global__ void graph_adj_kernel(const float* __restrict__ fn, float* __restrict__ An)
{
    const int b = blockIdx.x, i = threadIdx.x;
    __shared__ float f[64];
    __shared__ unsigned char A[64][64];
    f[i] = fn[b * 64 + i];
    for (int j = 0; j < 64; j++) A[i][j] = 0;
    __syncthreads();
    const float fi = f[i];
    float bv0 = -3.402823466e38f, bv1 = bv0, bv2 = bv0, bv3 = bv0;
    int i0 = 0, i1 = 0, i2 = 0, i3 = 0;
    for (int j = 0; j < 64; j++) {
        float v = fi * f[j];
        if (v > bv3) {
            if (v > bv0)      { bv3 = bv2; i3 = i2; bv2 = bv1; i2 = i1; bv1 = bv0; i1 = i0; bv0 = v; i0 = j; }
            else if (v > bv1) { bv3 = bv2; i3 = i2; bv2 = bv1; i2 = i1; bv1 = v; i1 = j; }
            else if (v > bv2) { bv3 = bv2; i3 = i2; bv2 = v; i2 = j; }
            else              { bv3 = v; i3 = j; }
        }
    }
    A[i][i1] = 1; A[i][i2] = 1; A[i][i3] = 1;
    __syncthreads();
    float deg = 0.f;
    for (int j = 0; j < 64; j++) {
        bool a = (j == i) || A[i][j] || A[j][i];
        deg += a ? 1.f : 0.f;
    }
    float inv = 1.f / deg;
    float* row = An + (size_t)b * 4096 + i * 64;
    for (int j = 0; j < 64; j++) {
        bool a = (j == i) || A[i][j] || A[j][i];
        row[j] = a ? inv : 0.f;
    }
}

// out = (relu?) An @ in ; optional transposed write; optional fp16 hi/lo out
template <bool RELU, bool TRANSOUT, bool SPLITOUT>
__global__ void __launch_bounds__(256) an_mult_kernel(
    const float* __restrict__ An, const float* __restrict__ in,
    float* __restrict__ out, __half* __restrict__ ohi, __half* __restrict__ olo)
{
    const int dt = blockIdx.x, b = blockIdx.y;
    __shared__ float As[64][65];
    __shared__ float Ins[64][64];
    const int tid = threadIdx.x, tx = tid & 15, ty = tid >> 4;

    for (int t = tid; t < 4096; t += 256)
        As[t >> 6][t & 63] = An[(size_t)b * 4096 + t];
#pragma unroll
    for (int hh = 0; hh < 4; hh++) {
        int idx4 = tid + hh * 256;
        int gg = idx4 >> 4, c4 = (idx4 & 15) << 2;
        float4 v = *reinterpret_cast<const float4*>(
            in + (size_t)b * 32768 + (size_t)gg * 512 + dt * 64 + c4);
        *reinterpret_cast<float4*>(&Ins[gg][c4]) = v;
    }
    __syncthreads();

    float acc[4][4];
#pragma unroll
    for (int i = 0; i < 4; i++)
#pragma unroll
        for (int j = 0; j < 4; j++) acc[i][j] = 0.f;

#pragma unroll 8
    for (int kk = 0; kk < 64; kk++) {
        float a[4], bb[4];
#pragma unroll
        for (int i = 0; i < 4; i++) a[i] = As[ty + 16 * i][kk];
#pragma unroll
        for (int j = 0; j < 4; j++) bb[j] = Ins[kk][tx + 16 * j];
#pragma unroll
        for (int i = 0; i < 4; i++)
#pragma unroll
            for (int j = 0; j < 4; j++)
                acc[i][j] = fmaf(a[i], bb[j], acc[i][j]);
    }

#pragma unroll
    for (int i = 0; i < 4; i++)
#pragma unroll
        for (int j = 0; j < 4; j++) {
            int ff = ty + 16 * i;
            int dd = dt * 64 + tx + 16 * j;
            float v = acc[i][j];
            if (RELU) v = fmaxf(v, 0.f);
            if (!TRANSOUT) {
                size_t o = (size_t)b * 32768 + (size_t)ff * 512 + dd;
                out[o] = v;
                if (SPLITOUT) {
                    __half h = __float2half_rn(v);
                    ohi[o] = h;
                    olo[o] = __float2half_rn(v - __half2float(h));
                }
            } else {
                out[(size_t)b * 32768 + (size_t)dd * 64 + ff] = v;
            }
        }
}

// ---------------------------------------------------------------------------
// Host orchestration
// ---------------------------------------------------------------------------
extern "C" void kernel_launch(void* const* d_in, const int* in_sizes, int n_in,
                              void* d_out, int out_size)
{
    const float* x      = (const float*)d_in[0];
    const float* W_in   = (const float*)d_in[1];
    const float* b_in   = (const float*)d_in[2];
    const float* qkv_w  = (const float*)d_in[3];
    const float* qkv_b  = (const float*)d_in[4];
    const float* out_w  = (const float*)d_in[5];
    const float* out_b  = (const float*)d_in[6];
    const float* ln1_g  = (const float*)d_in[7];
    const float* ln1_b  = (const float*)d_in[8];
    const float* ln2_g  = (const float*)d_in[9];
    const float* ln2_b  = (const float*)d_in[10];
    const float* ff1_w  = (const float*)d_in[11];
    const float* ff1_b  = (const float*)d_in[12];
    const float* ff2_w  = (const float*)d_in[13];
    const float* ff2_b  = (const float*)d_in[14];
    const float* memory = (const float*)d_in[15];
    const float* fc1_w  = (const float*)d_in[16];
    const float* fc1_b  = (const float*)d_in[17];
    const float* fc2_w  = (const float*)d_in[18];
    const float* fc2_b  = (const float*)d_in[19];
    const float* gc1_w  = (const float*)d_in[20];
    const float* gc1_b  = (const float*)d_in[21];
    const float* gc2_w  = (const float*)d_in[22];
    const float* gc2_b  = (const float*)d_in[23];

    float* out    = (float*)d_out;
    float* t_out  = out;                       // (32,512,64)
    float* gout_p = out + 1048576;             // (32,512,64)
    float* attn_p = out + 2097152;             // (32,512,1024)

    static float *p_pe = nullptr, *p_h, *p_tmp, *p_fn, *p_An, *p_gt1, *p_gh1;
    static __half *p_h16, *p_qkv, *p_o, *p_ff, *p_mlo, *p_memT, *p_wh;
    static __half *p_xth, *p_xtl, *p_ghh, *p_ghl, *p_w1h, *p_w1l, *p_w2h, *p_w2l;
    if (!p_pe) {
        cudaGetSymbolAddress((void**)&p_pe,    g_pe);
        cudaGetSymbolAddress((void**)&p_h,     g_h);
        cudaGetSymbolAddress((void**)&p_h16,   g_h16);
        cudaGetSymbolAddress((void**)&p_tmp,   g_tmp);
        cudaGetSymbolAddress((void**)&p_qkv,   g_qkv);
        cudaGetSymbolAddress((void**)&p_o,     g_o);
        cudaGetSymbolAddress((void**)&p_ff,    g_ff);
        cudaGetSymbolAddress((void**)&p_mlo,   g_mlo);
        cudaGetSymbolAddress((void**)&p_memT,  g_memT);
        cudaGetSymbolAddress((void**)&p_fn,    g_fn);
        cudaGetSymbolAddress((void**)&p_An,    g_An);
        cudaGetSymbolAddress((void**)&p_gt1,   g_gt1);
        cudaGetSymbolAddress((void**)&p_gh1,   g_gh1);
        cudaGetSymbolAddress((void**)&p_wh,    g_wh);
        cudaGetSymbolAddress((void**)&p_xth,   g_xt_hi);
        cudaGetSymbolAddress((void**)&p_xtl,   g_xt_lo);
        cudaGetSymbolAddress((void**)&p_ghh,   g_gh_hi);
        cudaGetSymbolAddress((void**)&p_ghl,   g_gh_lo);
        cudaGetSymbolAddress((void**)&p_w1h,   g_w1h);
        cudaGetSymbolAddress((void**)&p_w1l,   g_w1l);
        cudaGetSymbolAddress((void**)&p_w2h,   g_w2h);
        cudaGetSymbolAddress((void**)&p_w2l,   g_w2l);
    }

    const int M = 16384;

    // ---- pre-convert weights to fp16 (graph-captured) ----
    auto conv = [&](const float* src, __half* dst, int n) {
        convert_w_kernel<<<(n / 4 + 255) / 256, 256>>>(src, dst, n / 4);
    };
    conv(qkv_w,  p_wh + WH_QKV, 3 * 1536 * 512);
    conv(out_w,  p_wh + WH_OUT, 3 * 512 * 512);
    conv(ff1_w,  p_wh + WH_FF1, 3 * 2048 * 512);
    conv(ff2_w,  p_wh + WH_FF2, 3 * 512 * 2048);
    conv(memory, p_wh + WH_MEM, 1024 * 512);
    conv(fc1_w,  p_wh + WH_FC1, 512 * 1024);
    conv(fc2_w,  p_wh + WH_FC2, 64 * 512);
    conv(W_in,   p_wh + WH_WIN, 512 * 64);
    make_lo_kernel<<<(1024 * 512 / 4 + 255) / 256, 256>>>(
        memory, p_wh + WH_MEM, p_mlo, 1024 * 512 / 4);
    transpose_mem_kernel<<<dim3(32, 16), dim3(32, 32)>>>(p_wh + WH_MEM, p_memT);
    // GCN weight splits
    conv(gc1_w, p_w1h, 512 * 512);
    make_lo_kernel<<<(512 * 512 / 4 + 255) / 256, 256>>>(gc1_w, p_w1h, p_w1l,
                                                         512 * 512 / 4);
    conv(gc2_w, p_w2h, 512 * 512);
    make_lo_kernel<<<(512 * 512 / 4 + 255) / 256, 256>>>(gc2_w, p_w2h, p_w2l,
                                                         512 * 512 / 4);

    pe_kernel<<<(512 * 512 + 255) / 256, 256>>>(p_pe);

    // h = x @ W_in^T + b_in + pe (dual fp32+fp16 out, fp16 B register-staged)
    gemm_tc<true, 2, false, false, false, true, false, true>
        <<<dim3(4, 128), 256>>>(
        x, nullptr, p_wh + WH_WIN, b_in, p_pe, nullptr, p_h, p_h16, M, 512, 64);

    for (int l = 0; l < 3; l++) {
        // qkv (pure fp16, cp.async)
        gemm_tc<true, 0, false, true, true, true, true, false>
            <<<dim3(12, 128), 256>>>(
            p_h16, nullptr, p_wh + WH_QKV + (size_t)l * 1536 * 512,
            qkv_b + l * 1536, nullptr, nullptr, p_qkv, nullptr, M, 1536, 512);
        // fused attention
        flash_attn_tc<<<dim3(8, 256), 128>>>(p_qkv, p_o);
        // out projection + residual (pure fp16 in, cp.async, fp32 out)
        gemm_tc<true, 3, false, true, false, true, true, false>
            <<<dim3(4, 128), 256>>>(
            p_o, nullptr, p_wh + WH_OUT + (size_t)l * 512 * 512,
            out_b + l * 512, nullptr, p_h, p_tmp, nullptr, M, 512, 512);
        ln_kernel<<<16384, 256>>>(p_tmp, ln1_g + l * 512, ln1_b + l * 512,
                                  p_h, p_h16);
        // feed-forward (pure fp16, cp.async)
        gemm_tc<true, 1, false, true, true, true, true, false>
            <<<dim3(16, 128), 256>>>(
            p_h16, nullptr, p_wh + WH_FF1 + (size_t)l * 2048 * 512,
            ff1_b + l * 2048, nullptr, nullptr, p_ff, nullptr, M, 2048, 512);
        gemm_tc<true, 3, false, true, false, true, true, false>
            <<<dim3(4, 128), 256>>>(
            p_ff, nullptr, p_wh + WH_FF2 + (size_t)l * 512 * 2048,
            ff2_b + l * 512, nullptr, p_h, p_tmp, nullptr, M, 512, 2048);
        ln_kernel<<<16384, 256>>>(p_tmp, ln2_g + l * 512, ln2_b + l * 512,
                                  p_h, p_h16);
    }

    // sims: 2-pass split GEMM (hi*hi + hi*lo), A = h16 only
    sims_split_tc<<<dim3(8, 128), 256>>>(
        p_h16, p_wh + WH_MEM, p_mlo, attn_p, M, 1024, 512);
    // softmax with dual fp32 + fp16 output (attn16 in g_ff scratch)
    softmax_dual_kernel<<<16384, 256>>>(attn_p, p_ff);
    // upd = attn16 @ memT^T (pure fp16, cp.async), fp16 out
    gemm_tc<true, 0, false, true, true, true, true, false>
        <<<dim3(4, 128), 256>>>(
        p_ff, nullptr, p_memT, nullptr, nullptr, nullptr,
        p_o, nullptr, M, 512, 1024);
    // fc1 over fp16 concat [h16 | upd16] (cp.async), fp16 out into qkv buffer
    gemm_tc<true, 1, true, true, true, true, true, false>
        <<<dim3(4, 128), 256>>>(
        p_h16, p_o, p_wh + WH_FC1, fc1_b, nullptr, nullptr,
        p_qkv, nullptr, M, 512, 1024);
    // fc2 (pure fp16 in, cp.async, fp32 out to t_out)
    gemm_tc<true, 0, false, true, false, true, true, false>
        <<<dim3(1, 128), 256>>>(
        p_qkv, nullptr, p_wh + WH_FC2, fc2_b, nullptr, nullptr,
        t_out, nullptr, M, 64, 512);

    // ---- graph branch: tensor-core 3-pass split GEMMs (error ~2^-24) ----
    feat_fn_kernel<<<32, 64>>>(x, p_fn);
    graph_adj_kernel<<<32, 64>>>(p_fn, p_An);
    transpose_x_split<<<dim3(16, 2, 32), dim3(32, 32)>>>(x, p_xth, p_xtl);
    // t1 = xt @ gc1_w^T + b1   (2048 x 512 x 512)
    split3_tc<<<dim3(4, 16), 256>>>(p_xth, p_xtl, p_w1h, p_w1l, gc1_b,
                                    p_gt1, 2048, 512, 512);
    // gh1 = relu(An @ t1), with fp16 hi/lo split outputs
    an_mult_kernel<true, false, true><<<dim3(8, 32), 256>>>(
        p_An, p_gt1, p_gh1, p_ghh, p_ghl);
    // t2 = gh1 @ gc2_w^T + b2  (2048 x 512 x 512)
    split3_tc<<<dim3(4, 16), 256>>>(p_ghh, p_ghl, p_w2h, p_w2l, gc2_b,
                                    p_gt1, 2048, 512, 512);
    // g_out = An @ t2 (transposed write)
    an_mult_kernel<false, true, false><<<dim3(8, 32), 256>>>(
        p_An, p_gt1, gout_p, nullptr, nullptr);

    (void)in_sizes; (void)n_in; (void)out_size;
}